// round 1
// baseline (speedup 1.0000x reference)
#include <cuda_runtime.h>
#include <cuda_bf16.h>
#include <math.h>

// Problem constants
#define SEQ 2048
#define HID 4096
#define NQH 32
#define NKV 8
#define HD  128
#define GROUPS (NQH / NKV)   // 4

// ---------------- scratch (no cudaMalloc allowed) ----------------
__device__ float g_q[SEQ * NQH * HD];   // 32 MB
__device__ float g_k[SEQ * NKV * HD];   // 8 MB
__device__ float g_v[SEQ * NKV * HD];   // 8 MB
__device__ float g_o[SEQ * NQH * HD];   // 32 MB

// ---------------- SGEMM: C[M,N] = A[M,K] @ B[K,N], all row-major, dims % 128 == 0, K % 8 == 0
__global__ __launch_bounds__(256)
void sgemm128(const float* __restrict__ A, const float* __restrict__ B,
              float* __restrict__ C, int M, int N, int K) {
    const int BM = 128, BN = 128, BK = 8, TM = 8, TN = 8;
    __shared__ __align__(16) float As[BK * BM];
    __shared__ __align__(16) float Bs[BK * BN];

    const int tid  = threadIdx.x;
    const int cRow = blockIdx.y;
    const int cCol = blockIdx.x;
    const int threadRow = tid / 16;
    const int threadCol = tid % 16;

    A += (size_t)cRow * BM * K;
    B += cCol * BN;
    C += (size_t)cRow * BM * N + cCol * BN;

    const int innerRowA = tid / 2;      // 0..127
    const int innerColA = tid % 2;      // float4 index within BK=8
    const int innerRowB = tid / 32;     // 0..7
    const int innerColB = tid % 32;     // float4 index within BN=128

    float acc[TM][TN];
    #pragma unroll
    for (int i = 0; i < TM; i++)
        #pragma unroll
        for (int j = 0; j < TN; j++) acc[i][j] = 0.0f;

    for (int k0 = 0; k0 < K; k0 += BK) {
        // load A tile (transposed into As[k][m])
        float4 a4 = *(const float4*)(A + (size_t)innerRowA * K + innerColA * 4);
        As[(innerColA * 4 + 0) * BM + innerRowA] = a4.x;
        As[(innerColA * 4 + 1) * BM + innerRowA] = a4.y;
        As[(innerColA * 4 + 2) * BM + innerRowA] = a4.z;
        As[(innerColA * 4 + 3) * BM + innerRowA] = a4.w;
        // load B tile
        *(float4*)(Bs + innerRowB * BN + innerColB * 4) =
            *(const float4*)(B + (size_t)innerRowB * N + innerColB * 4);
        __syncthreads();

        A += BK;
        B += (size_t)BK * N;

        #pragma unroll
        for (int k = 0; k < BK; k++) {
            float4 m0 = *(const float4*)(As + k * BM + threadRow * TM);
            float4 m1 = *(const float4*)(As + k * BM + threadRow * TM + 4);
            float4 n0 = *(const float4*)(Bs + k * BN + threadCol * TN);
            float4 n1 = *(const float4*)(Bs + k * BN + threadCol * TN + 4);
            float rm[8] = {m0.x, m0.y, m0.z, m0.w, m1.x, m1.y, m1.z, m1.w};
            float rn[8] = {n0.x, n0.y, n0.z, n0.w, n1.x, n1.y, n1.z, n1.w};
            #pragma unroll
            for (int i = 0; i < TM; i++)
                #pragma unroll
                for (int j = 0; j < TN; j++)
                    acc[i][j] = fmaf(rm[i], rn[j], acc[i][j]);
        }
        __syncthreads();
    }

    #pragma unroll
    for (int i = 0; i < TM; i++) {
        float4 o0 = make_float4(acc[i][0], acc[i][1], acc[i][2], acc[i][3]);
        float4 o1 = make_float4(acc[i][4], acc[i][5], acc[i][6], acc[i][7]);
        *(float4*)(C + (size_t)(threadRow * TM + i) * N + threadCol * TN)     = o0;
        *(float4*)(C + (size_t)(threadRow * TM + i) * N + threadCol * TN + 4) = o1;
    }
}

// ---------------- RMSNorm (per 128-wide head row) + RoPE ----------------
// buf layout: [SEQ][n_heads*HD]; grid(SEQ, n_heads), block(128)
__global__ __launch_bounds__(128)
void rmsnorm_rope(float* __restrict__ buf, const float* __restrict__ w,
                  const float* __restrict__ cosT, const float* __restrict__ sinT,
                  const int* __restrict__ pos_ids, int n_heads) {
    const int s = blockIdx.x;
    const int h = blockIdx.y;
    const int d = threadIdx.x;

    float* row = buf + (size_t)s * n_heads * HD + h * HD;
    float v = row[d];

    float ss = v * v;
    #pragma unroll
    for (int off = 16; off > 0; off >>= 1)
        ss += __shfl_xor_sync(0xffffffffu, ss, off);
    __shared__ float wsum[4];
    if ((d & 31) == 0) wsum[d >> 5] = ss;
    __syncthreads();
    float total = wsum[0] + wsum[1] + wsum[2] + wsum[3];
    float inv = rsqrtf(total * (1.0f / HD) + 1e-6f);

    float xn = v * inv * w[d];
    __shared__ float xs[HD];
    xs[d] = xn;
    __syncthreads();

    const int p = pos_ids[s];
    float c  = cosT[(size_t)p * HD + d];
    float sn = sinT[(size_t)p * HD + d];
    float rot = (d < HD / 2) ? -xs[d + HD / 2] : xs[d - HD / 2];
    row[d] = xn * c + rot * sn;
}

// ---------------- Flash attention (causal, GQA 4:1) ----------------
// Q: [SEQ][NQH*HD], K/V: [SEQ][NKV*HD], O: [SEQ][NQH*HD]
// grid(SEQ/64, NQH), block(256). dyn smem: Q/K/V tiles + P tile.
#define BQ 64
#define BKV 64
#define TSTR 132          // padded float stride for 128-wide tiles
#define PSTR 68           // padded stride for 64-wide P tile
#define ATTN_SMEM ((3 * BQ * TSTR + BQ * PSTR) * (int)sizeof(float))

__global__ __launch_bounds__(256)
void flash_attn(const float* __restrict__ Q, const float* __restrict__ Kb,
                const float* __restrict__ Vb, float* __restrict__ O) {
    extern __shared__ __align__(16) float sm[];
    float* Qs = sm;                     // BQ  x TSTR
    float* Ks = Qs + BQ * TSTR;         // BKV x TSTR
    float* Vs = Ks + BKV * TSTR;        // BKV x TSTR
    float* Ps = Vs + BKV * TSTR;        // BQ  x PSTR

    const int tid = threadIdx.x;
    const int ty = tid >> 4;            // 0..15 -> 4 query rows
    const int tx = tid & 15;            // 0..15 -> 4 score cols / 8 out cols
    const int qb = blockIdx.x;
    const int h  = blockIdx.y;
    const int kvh = h >> 2;             // GQA: repeat(k, 4) -> kv = h/4
    const int qbase = qb * BQ;
    const int r0 = ty * 4;
    const int c0 = tx * 4;
    const int d0 = tx * 8;
    const float scale = 0.08838834764831845f;  // 128^-0.5

    // load Q tile, pre-scaled
    for (int t = tid; t < BQ * (HD / 4); t += 256) {
        int row = t >> 5, c4 = t & 31;
        float4 v = *(const float4*)(Q + (size_t)(qbase + row) * (NQH * HD) + h * HD + c4 * 4);
        v.x *= scale; v.y *= scale; v.z *= scale; v.w *= scale;
        *(float4*)(Qs + row * TSTR + c4 * 4) = v;
    }

    float oacc[4][8];
    #pragma unroll
    for (int i = 0; i < 4; i++)
        #pragma unroll
        for (int j = 0; j < 8; j++) oacc[i][j] = 0.0f;
    float m_i[4] = {-INFINITY, -INFINITY, -INFINITY, -INFINITY};
    float l_i[4] = {0.0f, 0.0f, 0.0f, 0.0f};

    for (int kb = 0; kb <= qb; kb++) {
        __syncthreads();  // prev iter done with Ks/Vs/Ps (also covers Q load on iter 0)
        const int kbase = kb * BKV;
        for (int t = tid; t < BKV * (HD / 4); t += 256) {
            int row = t >> 5, c4 = t & 31;
            size_t g = (size_t)(kbase + row) * (NKV * HD) + kvh * HD + c4 * 4;
            *(float4*)(Ks + row * TSTR + c4 * 4) = *(const float4*)(Kb + g);
            *(float4*)(Vs + row * TSTR + c4 * 4) = *(const float4*)(Vb + g);
        }
        __syncthreads();

        // scores: 4x4 per thread
        float s[4][4];
        #pragma unroll
        for (int i = 0; i < 4; i++)
            #pragma unroll
            for (int j = 0; j < 4; j++) s[i][j] = 0.0f;

        #pragma unroll 4
        for (int kk = 0; kk < HD; kk += 4) {
            float4 qv[4], kv[4];
            #pragma unroll
            for (int i = 0; i < 4; i++) qv[i] = *(const float4*)(Qs + (r0 + i) * TSTR + kk);
            #pragma unroll
            for (int j = 0; j < 4; j++) kv[j] = *(const float4*)(Ks + (c0 + j) * TSTR + kk);
            #pragma unroll
            for (int i = 0; i < 4; i++)
                #pragma unroll
                for (int j = 0; j < 4; j++) {
                    s[i][j] = fmaf(qv[i].x, kv[j].x, s[i][j]);
                    s[i][j] = fmaf(qv[i].y, kv[j].y, s[i][j]);
                    s[i][j] = fmaf(qv[i].z, kv[j].z, s[i][j]);
                    s[i][j] = fmaf(qv[i].w, kv[j].w, s[i][j]);
                }
        }

        const bool diag = (kb == qb);
        #pragma unroll
        for (int i = 0; i < 4; i++) {
            if (diag) {
                #pragma unroll
                for (int j = 0; j < 4; j++)
                    if (c0 + j > r0 + i) s[i][j] = -1e30f;
            }
            float mloc = fmaxf(fmaxf(s[i][0], s[i][1]), fmaxf(s[i][2], s[i][3]));
            #pragma unroll
            for (int off = 1; off < 16; off <<= 1)
                mloc = fmaxf(mloc, __shfl_xor_sync(0xffffffffu, mloc, off, 16));
            float mnew = fmaxf(m_i[i], mloc);
            float sc = expf(m_i[i] - mnew);
            m_i[i] = mnew;
            float pj[4], psum = 0.0f;
            #pragma unroll
            for (int j = 0; j < 4; j++) { pj[j] = expf(s[i][j] - mnew); psum += pj[j]; }
            #pragma unroll
            for (int off = 1; off < 16; off <<= 1)
                psum += __shfl_xor_sync(0xffffffffu, psum, off, 16);
            l_i[i] = l_i[i] * sc + psum;
            #pragma unroll
            for (int j = 0; j < 4; j++) Ps[(r0 + i) * PSTR + c0 + j] = pj[j];
            #pragma unroll
            for (int jj = 0; jj < 8; jj++) oacc[i][jj] *= sc;
        }
        __syncthreads();

        // PV: 4 rows x 8 cols per thread
        #pragma unroll 8
        for (int c = 0; c < BKV; c++) {
            float4 v0 = *(const float4*)(Vs + c * TSTR + d0);
            float4 v1 = *(const float4*)(Vs + c * TSTR + d0 + 4);
            #pragma unroll
            for (int i = 0; i < 4; i++) {
                float p = Ps[(r0 + i) * PSTR + c];
                oacc[i][0] = fmaf(p, v0.x, oacc[i][0]);
                oacc[i][1] = fmaf(p, v0.y, oacc[i][1]);
                oacc[i][2] = fmaf(p, v0.z, oacc[i][2]);
                oacc[i][3] = fmaf(p, v0.w, oacc[i][3]);
                oacc[i][4] = fmaf(p, v1.x, oacc[i][4]);
                oacc[i][5] = fmaf(p, v1.y, oacc[i][5]);
                oacc[i][6] = fmaf(p, v1.z, oacc[i][6]);
                oacc[i][7] = fmaf(p, v1.w, oacc[i][7]);
            }
        }
    }

    #pragma unroll
    for (int i = 0; i < 4; i++) {
        float inv = 1.0f / l_i[i];
        float4 o0 = make_float4(oacc[i][0] * inv, oacc[i][1] * inv, oacc[i][2] * inv, oacc[i][3] * inv);
        float4 o1 = make_float4(oacc[i][4] * inv, oacc[i][5] * inv, oacc[i][6] * inv, oacc[i][7] * inv);
        size_t g = (size_t)(qbase + r0 + i) * (NQH * HD) + h * HD + d0;
        *(float4*)(O + g)     = o0;
        *(float4*)(O + g + 4) = o1;
    }
}

// ---------------- launch ----------------
extern "C" void kernel_launch(void* const* d_in, const int* in_sizes, int n_in,
                              void* d_out, int out_size) {
    const float* x    = (const float*)d_in[0];
    const int*   pos  = (const int*)  d_in[1];
    const float* cosT = (const float*)d_in[2];
    const float* sinT = (const float*)d_in[3];
    // d_in[4] = attn_mask (causal -1e9) — replicated exactly by causal skip
    const float* Wq   = (const float*)d_in[5];
    const float* Wk   = (const float*)d_in[6];
    const float* Wv   = (const float*)d_in[7];
    const float* Wo   = (const float*)d_in[8];
    const float* qw   = (const float*)d_in[9];
    const float* kw   = (const float*)d_in[10];
    float* out = (float*)d_out;

    float *qp, *kp, *vp, *op;
    cudaGetSymbolAddress((void**)&qp, g_q);
    cudaGetSymbolAddress((void**)&kp, g_k);
    cudaGetSymbolAddress((void**)&vp, g_v);
    cudaGetSymbolAddress((void**)&op, g_o);

    cudaFuncSetAttribute(flash_attn, cudaFuncAttributeMaxDynamicSharedMemorySize, ATTN_SMEM);

    // QKV projections
    sgemm128<<<dim3(NQH * HD / 128, SEQ / 128), 256>>>(x, Wq, qp, SEQ, NQH * HD, HID);
    sgemm128<<<dim3(NKV * HD / 128, SEQ / 128), 256>>>(x, Wk, kp, SEQ, NKV * HD, HID);
    sgemm128<<<dim3(NKV * HD / 128, SEQ / 128), 256>>>(x, Wv, vp, SEQ, NKV * HD, HID);

    // per-head RMSNorm + RoPE (q and k only)
    rmsnorm_rope<<<dim3(SEQ, NQH), 128>>>(qp, qw, cosT, sinT, pos, NQH);
    rmsnorm_rope<<<dim3(SEQ, NKV), 128>>>(kp, kw, cosT, sinT, pos, NKV);

    // causal flash attention
    flash_attn<<<dim3(SEQ / BQ, NQH), 256, ATTN_SMEM>>>(qp, kp, vp, op);

    // output projection
    sgemm128<<<dim3(HID / 128, SEQ / 128), 256>>>(op, Wo, out, SEQ, HID, HID);
}

// round 2
// speedup vs baseline: 3.2892x; 3.2892x over previous
#include <cuda_runtime.h>
#include <cuda_bf16.h>
#include <math.h>
#include <stdint.h>

// Problem constants
#define SEQ 2048
#define HID 4096
#define NQH 32
#define NKV 8
#define HD  128

// ---------------- scratch (no cudaMalloc allowed) ----------------
__device__ float g_q[SEQ * NQH * HD];
__device__ float g_k[SEQ * NKV * HD];
__device__ float g_v[SEQ * NKV * HD];
__device__ float g_o[SEQ * NQH * HD];

// ---------------- helpers ----------------
__device__ __forceinline__ uint32_t tf32_rna_u(float x) {
    uint32_t u;
    asm("cvt.rna.tf32.f32 %0, %1;" : "=r"(u) : "f"(x));
    return u;
}
__device__ __forceinline__ float tf32_rna(float x) {
    return __uint_as_float(tf32_rna_u(x));
}

// D += A(16x8) * B(8x8), tf32 inputs, fp32 accum
__device__ __forceinline__ void mma_tf32(float (&d)[4], const uint32_t (&a)[4], const uint32_t (&b)[2]) {
    asm volatile(
        "mma.sync.aligned.m16n8k8.row.col.f32.tf32.tf32.f32 "
        "{%0,%1,%2,%3}, {%4,%5,%6,%7}, {%8,%9}, {%0,%1,%2,%3};\n"
        : "+f"(d[0]), "+f"(d[1]), "+f"(d[2]), "+f"(d[3])
        : "r"(a[0]), "r"(a[1]), "r"(a[2]), "r"(a[3]), "r"(b[0]), "r"(b[1]));
}

// ---------------- TF32 GEMM: C[M,N] = A[M,K] @ B[K,N], row-major ----------------
// BM=128 BN=128 BK=16, 256 threads = 8 warps (2x4), warp tile 64x32
#define GSTR_A 20
#define GSTR_B 136
__global__ __launch_bounds__(256)
void sgemm_tf32(const float* __restrict__ A, const float* __restrict__ B,
                float* __restrict__ C, int M, int N, int K) {
    __shared__ __align__(16) float As[128 * GSTR_A];  // [m][k]
    __shared__ __align__(16) float Bs[16 * GSTR_B];   // [k][n]

    const int tid  = threadIdx.x;
    const int warp = tid >> 5;
    const int lane = tid & 31;
    const int g    = lane >> 2;
    const int t4   = lane & 3;
    const int wm   = warp >> 2;   // 0..1
    const int wn   = warp & 3;    // 0..3
    const int bm   = blockIdx.y * 128;
    const int bn   = blockIdx.x * 128;

    float acc[4][4][4];
    #pragma unroll
    for (int mi = 0; mi < 4; mi++)
        #pragma unroll
        for (int ni = 0; ni < 4; ni++)
            #pragma unroll
            for (int r = 0; r < 4; r++) acc[mi][ni][r] = 0.0f;

    for (int k0 = 0; k0 < K; k0 += 16) {
        // A tile: 128x16 = 512 float4
        #pragma unroll
        for (int ld = 0; ld < 2; ld++) {
            int f = tid + ld * 256;
            int row = f >> 2, c4 = f & 3;
            float4 v = *(const float4*)(A + (size_t)(bm + row) * K + k0 + c4 * 4);
            v.x = tf32_rna(v.x); v.y = tf32_rna(v.y);
            v.z = tf32_rna(v.z); v.w = tf32_rna(v.w);
            float* p = As + row * GSTR_A + c4 * 4;
            *(float2*)(p)     = make_float2(v.x, v.y);
            *(float2*)(p + 2) = make_float2(v.z, v.w);
        }
        // B tile: 16x128 = 512 float4
        #pragma unroll
        for (int ld = 0; ld < 2; ld++) {
            int f = tid + ld * 256;
            int row = f >> 5, c4 = f & 31;
            float4 v = *(const float4*)(B + (size_t)(k0 + row) * N + bn + c4 * 4);
            v.x = tf32_rna(v.x); v.y = tf32_rna(v.y);
            v.z = tf32_rna(v.z); v.w = tf32_rna(v.w);
            *(float4*)(Bs + row * GSTR_B + c4 * 4) = v;
        }
        __syncthreads();

        #pragma unroll
        for (int ks = 0; ks < 2; ks++) {
            const int kk = ks * 8;
            uint32_t af[4][4];
            #pragma unroll
            for (int mi = 0; mi < 4; mi++) {
                int r = wm * 64 + mi * 16;
                af[mi][0] = __float_as_uint(As[(r + g) * GSTR_A + kk + t4]);
                af[mi][1] = __float_as_uint(As[(r + g + 8) * GSTR_A + kk + t4]);
                af[mi][2] = __float_as_uint(As[(r + g) * GSTR_A + kk + t4 + 4]);
                af[mi][3] = __float_as_uint(As[(r + g + 8) * GSTR_A + kk + t4 + 4]);
            }
            uint32_t bf[4][2];
            #pragma unroll
            for (int ni = 0; ni < 4; ni++) {
                int c = wn * 32 + ni * 8 + g;
                bf[ni][0] = __float_as_uint(Bs[(kk + t4) * GSTR_B + c]);
                bf[ni][1] = __float_as_uint(Bs[(kk + t4 + 4) * GSTR_B + c]);
            }
            #pragma unroll
            for (int mi = 0; mi < 4; mi++)
                #pragma unroll
                for (int ni = 0; ni < 4; ni++)
                    mma_tf32(acc[mi][ni], af[mi], bf[ni]);
        }
        __syncthreads();
    }

    #pragma unroll
    for (int mi = 0; mi < 4; mi++) {
        #pragma unroll
        for (int ni = 0; ni < 4; ni++) {
            int r1 = bm + wm * 64 + mi * 16 + g;
            int c  = bn + wn * 32 + ni * 8 + t4 * 2;
            *(float2*)(C + (size_t)r1 * N + c)       = make_float2(acc[mi][ni][0], acc[mi][ni][1]);
            *(float2*)(C + (size_t)(r1 + 8) * N + c) = make_float2(acc[mi][ni][2], acc[mi][ni][3]);
        }
    }
}

// ---------------- RMSNorm + RoPE ----------------
__global__ __launch_bounds__(128)
void rmsnorm_rope(float* __restrict__ buf, const float* __restrict__ w,
                  const float* __restrict__ cosT, const float* __restrict__ sinT,
                  const int* __restrict__ pos_ids, int n_heads) {
    const int s = blockIdx.x;
    const int h = blockIdx.y;
    const int d = threadIdx.x;

    float* row = buf + (size_t)s * n_heads * HD + h * HD;
    float v = row[d];

    float ss = v * v;
    #pragma unroll
    for (int off = 16; off > 0; off >>= 1)
        ss += __shfl_xor_sync(0xffffffffu, ss, off);
    __shared__ float wsum[4];
    if ((d & 31) == 0) wsum[d >> 5] = ss;
    __syncthreads();
    float total = wsum[0] + wsum[1] + wsum[2] + wsum[3];
    float inv = rsqrtf(total * (1.0f / HD) + 1e-6f);

    float xn = v * inv * w[d];
    __shared__ float xs[HD];
    xs[d] = xn;
    __syncthreads();

    const int p = pos_ids[s];
    float c  = cosT[(size_t)p * HD + d];
    float sn = sinT[(size_t)p * HD + d];
    float rot = (d < HD / 2) ? -xs[d + HD / 2] : xs[d - HD / 2];
    row[d] = xn * c + rot * sn;
}

// ---------------- Flash attention with tf32 MMA (causal, GQA 4:1) ----------------
#define AQ 128     // q rows per block
#define AK 64      // kv rows per tile
#define QSTR 132
#define KSTR 132
#define VSTR 136
#define PSTR 68
#define ATTN_SMEM ((AQ*QSTR + AK*KSTR + AK*VSTR + AQ*PSTR) * (int)sizeof(float))

__global__ __launch_bounds__(256, 1)
void flash_attn_mma(const float* __restrict__ Q, const float* __restrict__ Kb,
                    const float* __restrict__ Vb, float* __restrict__ O) {
    extern __shared__ __align__(16) float sm[];
    float* Qs = sm;                     // AQ x QSTR
    float* Ks = Qs + AQ * QSTR;         // AK x KSTR
    float* Vs = Ks + AK * KSTR;         // AK x VSTR
    float* Ps = Vs + AK * VSTR;         // AQ x PSTR

    const int tid  = threadIdx.x;
    const int warp = tid >> 5;
    const int lane = tid & 31;
    const int g    = lane >> 2;
    const int t4   = lane & 3;
    const int wrow = warp * 16;

    const int qb   = blockIdx.x;
    const int h    = blockIdx.y;
    const int kvh  = h >> 2;
    const int qbase = qb * AQ;
    const float scale = 0.08838834764831845f;  // 128^-0.5

    // load Q tile (scaled, tf32-rounded)
    for (int f = tid; f < AQ * 32; f += 256) {
        int row = f >> 5, c4 = f & 31;
        float4 v = *(const float4*)(Q + (size_t)(qbase + row) * (NQH * HD) + h * HD + c4 * 4);
        v.x = tf32_rna(v.x * scale); v.y = tf32_rna(v.y * scale);
        v.z = tf32_rna(v.z * scale); v.w = tf32_rna(v.w * scale);
        *(float4*)(Qs + row * QSTR + c4 * 4) = v;
    }

    float o[16][4];
    #pragma unroll
    for (int ni = 0; ni < 16; ni++)
        #pragma unroll
        for (int r = 0; r < 4; r++) o[ni][r] = 0.0f;
    float m1 = -INFINITY, m2 = -INFINITY, l1 = 0.0f, l2 = 0.0f;

    const int nkb = 2 * qb + 2;
    for (int kb = 0; kb < nkb; kb++) {
        __syncthreads();
        const int kbase = kb * AK;
        for (int f = tid; f < AK * 32; f += 256) {
            int row = f >> 5, c4 = f & 31;
            size_t gidx = (size_t)(kbase + row) * (NKV * HD) + kvh * HD + c4 * 4;
            float4 kv = *(const float4*)(Kb + gidx);
            kv.x = tf32_rna(kv.x); kv.y = tf32_rna(kv.y);
            kv.z = tf32_rna(kv.z); kv.w = tf32_rna(kv.w);
            *(float4*)(Ks + row * KSTR + c4 * 4) = kv;
            float4 vv = *(const float4*)(Vb + gidx);
            vv.x = tf32_rna(vv.x); vv.y = tf32_rna(vv.y);
            vv.z = tf32_rna(vv.z); vv.w = tf32_rna(vv.w);
            *(float4*)(Vs + row * VSTR + c4 * 4) = vv;
        }
        __syncthreads();

        // S = Q K^T : per warp 16 rows x 64 cols
        float s[8][4];
        #pragma unroll
        for (int ni = 0; ni < 8; ni++)
            #pragma unroll
            for (int r = 0; r < 4; r++) s[ni][r] = 0.0f;

        #pragma unroll
        for (int k0 = 0; k0 < HD; k0 += 8) {
            uint32_t af[4];
            af[0] = __float_as_uint(Qs[(wrow + g) * QSTR + k0 + t4]);
            af[1] = __float_as_uint(Qs[(wrow + g + 8) * QSTR + k0 + t4]);
            af[2] = __float_as_uint(Qs[(wrow + g) * QSTR + k0 + t4 + 4]);
            af[3] = __float_as_uint(Qs[(wrow + g + 8) * QSTR + k0 + t4 + 4]);
            #pragma unroll
            for (int ni = 0; ni < 8; ni++) {
                uint32_t bf[2];
                bf[0] = __float_as_uint(Ks[(ni * 8 + g) * KSTR + k0 + t4]);
                bf[1] = __float_as_uint(Ks[(ni * 8 + g) * KSTR + k0 + t4 + 4]);
                mma_tf32(s[ni], af, bf);
            }
        }

        // causal mask (only near diagonal)
        if (kb >= 2 * qb) {
            const int r1 = qbase + wrow + g;
            const int r2 = r1 + 8;
            #pragma unroll
            for (int ni = 0; ni < 8; ni++) {
                int c0 = kbase + ni * 8 + t4 * 2;
                if (c0     > r1) s[ni][0] = -1e30f;
                if (c0 + 1 > r1) s[ni][1] = -1e30f;
                if (c0     > r2) s[ni][2] = -1e30f;
                if (c0 + 1 > r2) s[ni][3] = -1e30f;
            }
        }

        // online softmax (fp32)
        float mx1 = -INFINITY, mx2 = -INFINITY;
        #pragma unroll
        for (int ni = 0; ni < 8; ni++) {
            mx1 = fmaxf(mx1, fmaxf(s[ni][0], s[ni][1]));
            mx2 = fmaxf(mx2, fmaxf(s[ni][2], s[ni][3]));
        }
        mx1 = fmaxf(mx1, __shfl_xor_sync(0xffffffffu, mx1, 1));
        mx1 = fmaxf(mx1, __shfl_xor_sync(0xffffffffu, mx1, 2));
        mx2 = fmaxf(mx2, __shfl_xor_sync(0xffffffffu, mx2, 1));
        mx2 = fmaxf(mx2, __shfl_xor_sync(0xffffffffu, mx2, 2));

        float mn1 = fmaxf(m1, mx1), mn2 = fmaxf(m2, mx2);
        float sc1 = __expf(m1 - mn1), sc2 = __expf(m2 - mn2);
        m1 = mn1; m2 = mn2;

        float ps1 = 0.0f, ps2 = 0.0f;
        #pragma unroll
        for (int ni = 0; ni < 8; ni++) {
            float p0 = __expf(s[ni][0] - mn1);
            float p1 = __expf(s[ni][1] - mn1);
            float p2 = __expf(s[ni][2] - mn2);
            float p3 = __expf(s[ni][3] - mn2);
            ps1 += p0 + p1; ps2 += p2 + p3;
            float* pr1 = Ps + (wrow + g) * PSTR + ni * 8 + t4 * 2;
            float* pr2 = Ps + (wrow + g + 8) * PSTR + ni * 8 + t4 * 2;
            pr1[0] = tf32_rna(p0); pr1[1] = tf32_rna(p1);
            pr2[0] = tf32_rna(p2); pr2[1] = tf32_rna(p3);
        }
        ps1 += __shfl_xor_sync(0xffffffffu, ps1, 1);
        ps1 += __shfl_xor_sync(0xffffffffu, ps1, 2);
        ps2 += __shfl_xor_sync(0xffffffffu, ps2, 1);
        ps2 += __shfl_xor_sync(0xffffffffu, ps2, 2);
        l1 = l1 * sc1 + ps1;
        l2 = l2 * sc2 + ps2;

        #pragma unroll
        for (int ni = 0; ni < 16; ni++) {
            o[ni][0] *= sc1; o[ni][1] *= sc1;
            o[ni][2] *= sc2; o[ni][3] *= sc2;
        }
        __syncwarp();

        // O += P V : per warp 16 rows x 128 cols
        #pragma unroll
        for (int k0 = 0; k0 < AK; k0 += 8) {
            uint32_t af[4];
            af[0] = __float_as_uint(Ps[(wrow + g) * PSTR + k0 + t4]);
            af[1] = __float_as_uint(Ps[(wrow + g + 8) * PSTR + k0 + t4]);
            af[2] = __float_as_uint(Ps[(wrow + g) * PSTR + k0 + t4 + 4]);
            af[3] = __float_as_uint(Ps[(wrow + g + 8) * PSTR + k0 + t4 + 4]);
            #pragma unroll
            for (int ni = 0; ni < 16; ni++) {
                uint32_t bf[2];
                bf[0] = __float_as_uint(Vs[(k0 + t4) * VSTR + ni * 8 + g]);
                bf[1] = __float_as_uint(Vs[(k0 + t4 + 4) * VSTR + ni * 8 + g]);
                mma_tf32(o[ni], af, bf);
            }
        }
    }

    // epilogue
    const float inv1 = 1.0f / l1;
    const float inv2 = 1.0f / l2;
    const int r1 = qbase + wrow + g;
    #pragma unroll
    for (int ni = 0; ni < 16; ni++) {
        int c = ni * 8 + t4 * 2;
        *(float2*)(O + (size_t)r1 * (NQH * HD) + h * HD + c) =
            make_float2(o[ni][0] * inv1, o[ni][1] * inv1);
        *(float2*)(O + (size_t)(r1 + 8) * (NQH * HD) + h * HD + c) =
            make_float2(o[ni][2] * inv2, o[ni][3] * inv2);
    }
}

// ---------------- launch ----------------
extern "C" void kernel_launch(void* const* d_in, const int* in_sizes, int n_in,
                              void* d_out, int out_size) {
    const float* x    = (const float*)d_in[0];
    const int*   pos  = (const int*)  d_in[1];
    const float* cosT = (const float*)d_in[2];
    const float* sinT = (const float*)d_in[3];
    // d_in[4] = attn_mask — replicated exactly by causal skip
    const float* Wq   = (const float*)d_in[5];
    const float* Wk   = (const float*)d_in[6];
    const float* Wv   = (const float*)d_in[7];
    const float* Wo   = (const float*)d_in[8];
    const float* qw   = (const float*)d_in[9];
    const float* kw   = (const float*)d_in[10];
    float* out = (float*)d_out;

    float *qp, *kp, *vp, *op;
    cudaGetSymbolAddress((void**)&qp, g_q);
    cudaGetSymbolAddress((void**)&kp, g_k);
    cudaGetSymbolAddress((void**)&vp, g_v);
    cudaGetSymbolAddress((void**)&op, g_o);

    cudaFuncSetAttribute(flash_attn_mma, cudaFuncAttributeMaxDynamicSharedMemorySize, ATTN_SMEM);

    // QKV projections (tf32 tensor-core)
    sgemm_tf32<<<dim3(NQH * HD / 128, SEQ / 128), 256>>>(x, Wq, qp, SEQ, NQH * HD, HID);
    sgemm_tf32<<<dim3(NKV * HD / 128, SEQ / 128), 256>>>(x, Wk, kp, SEQ, NKV * HD, HID);
    sgemm_tf32<<<dim3(NKV * HD / 128, SEQ / 128), 256>>>(x, Wv, vp, SEQ, NKV * HD, HID);

    // per-head RMSNorm + RoPE
    rmsnorm_rope<<<dim3(SEQ, NQH), 128>>>(qp, qw, cosT, sinT, pos, NQH);
    rmsnorm_rope<<<dim3(SEQ, NKV), 128>>>(kp, kw, cosT, sinT, pos, NKV);

    // causal flash attention (tf32 mma)
    flash_attn_mma<<<dim3(SEQ / AQ, NQH), 256, ATTN_SMEM>>>(qp, kp, vp, op);

    // output projection
    sgemm_tf32<<<dim3(HID / 128, SEQ / 128), 256>>>(op, Wo, out, SEQ, HID, HID);
}

// round 3
// speedup vs baseline: 3.8446x; 1.1689x over previous
#include <cuda_runtime.h>
#include <cuda_bf16.h>
#include <math.h>
#include <stdint.h>

// Problem constants
#define SEQ 2048
#define HID 4096
#define NQH 32
#define NKV 8
#define HD  128

// ---------------- scratch (no cudaMalloc allowed) ----------------
__device__ float g_q[SEQ * NQH * HD];
__device__ float g_k[SEQ * NKV * HD];
__device__ float g_v[SEQ * NKV * HD];
__device__ float g_o[SEQ * NQH * HD];

// ---------------- helpers ----------------
__device__ __forceinline__ uint32_t tf32_rna_u(float x) {
    uint32_t u;
    asm("cvt.rna.tf32.f32 %0, %1;" : "=r"(u) : "f"(x));
    return u;
}
__device__ __forceinline__ float tf32_rna(float x) {
    return __uint_as_float(tf32_rna_u(x));
}

// D += A(16x8) * B(8x8), tf32 inputs, fp32 accum
__device__ __forceinline__ void mma_tf32(float (&d)[4], const uint32_t (&a)[4], const uint32_t (&b)[2]) {
    asm volatile(
        "mma.sync.aligned.m16n8k8.row.col.f32.tf32.tf32.f32 "
        "{%0,%1,%2,%3}, {%4,%5,%6,%7}, {%8,%9}, {%0,%1,%2,%3};\n"
        : "+f"(d[0]), "+f"(d[1]), "+f"(d[2]), "+f"(d[3])
        : "r"(a[0]), "r"(a[1]), "r"(a[2]), "r"(a[3]), "r"(b[0]), "r"(b[1]));
}

// ---------------- TF32 GEMM body: C[bm:bm+128, bn:bn+128] = A[M,K] @ B[K,N] ----------------
// 256 threads = 8 warps (2x4), warp tile 64x32, BK=16, reg-staged double buffer.
#define GSTR_A 20
#define GSTR_B 136

__device__ __forceinline__
void gemm_body(const float* __restrict__ A, const float* __restrict__ B,
               float* __restrict__ C, int N, int K, int bm, int bn) {
    __shared__ __align__(16) float As[2][128 * GSTR_A];  // [m][k]
    __shared__ __align__(16) float Bs[2][16 * GSTR_B];   // [k][n]

    const int tid  = threadIdx.x;
    const int warp = tid >> 5;
    const int lane = tid & 31;
    const int g    = lane >> 2;
    const int t4   = lane & 3;
    const int wm   = warp >> 2;   // 0..1
    const int wn   = warp & 3;    // 0..3

    // A tile: 128x16 floats = 512 float4 -> 2 per thread
    const int rA0 = tid >> 2,          cA0 = tid & 3;
    const int rA1 = (tid + 256) >> 2,  cA1 = (tid + 256) & 3;
    // B tile: 16x128 floats = 512 float4 -> 2 per thread
    const int rB0 = tid >> 5,          cB0 = tid & 31;
    const int rB1 = (tid + 256) >> 5,  cB1 = (tid + 256) & 31;

    const float* Arow0 = A + (size_t)(bm + rA0) * K + cA0 * 4;
    const float* Arow1 = A + (size_t)(bm + rA1) * K + cA1 * 4;
    const float* Brow0 = B + (size_t)rB0 * N + bn + cB0 * 4;
    const float* Brow1 = B + (size_t)rB1 * N + bn + cB1 * 4;

    float acc[4][4][4];
    #pragma unroll
    for (int mi = 0; mi < 4; mi++)
        #pragma unroll
        for (int ni = 0; ni < 4; ni++)
            #pragma unroll
            for (int r = 0; r < 4; r++) acc[mi][ni][r] = 0.0f;

    float4 a_st0, a_st1, b_st0, b_st1;

    // ---- prologue: load + store tile 0
    a_st0 = *(const float4*)(Arow0);
    a_st1 = *(const float4*)(Arow1);
    b_st0 = *(const float4*)(Brow0);
    b_st1 = *(const float4*)(Brow1);
    {
        float4 v;
        v = a_st0; v.x=tf32_rna(v.x); v.y=tf32_rna(v.y); v.z=tf32_rna(v.z); v.w=tf32_rna(v.w);
        *(float4*)(&As[0][rA0 * GSTR_A + cA0 * 4]) = v;
        v = a_st1; v.x=tf32_rna(v.x); v.y=tf32_rna(v.y); v.z=tf32_rna(v.z); v.w=tf32_rna(v.w);
        *(float4*)(&As[0][rA1 * GSTR_A + cA1 * 4]) = v;
        v = b_st0; v.x=tf32_rna(v.x); v.y=tf32_rna(v.y); v.z=tf32_rna(v.z); v.w=tf32_rna(v.w);
        *(float4*)(&Bs[0][rB0 * GSTR_B + cB0 * 4]) = v;
        v = b_st1; v.x=tf32_rna(v.x); v.y=tf32_rna(v.y); v.z=tf32_rna(v.z); v.w=tf32_rna(v.w);
        *(float4*)(&Bs[0][rB1 * GSTR_B + cB1 * 4]) = v;
    }
    __syncthreads();

    const int iters = K >> 4;
    int cur = 0;
    for (int i = 0; i < iters; i++) {
        const bool more = (i + 1 < iters);
        if (more) {
            const int k1 = (i + 1) << 4;
            a_st0 = *(const float4*)(Arow0 + k1);
            a_st1 = *(const float4*)(Arow1 + k1);
            b_st0 = *(const float4*)(Brow0 + (size_t)k1 * N);
            b_st1 = *(const float4*)(Brow1 + (size_t)k1 * N);
        }

        // compute current tile
        const float* Ac = As[cur];
        const float* Bc = Bs[cur];
        #pragma unroll
        for (int ks = 0; ks < 2; ks++) {
            const int kk = ks * 8;
            uint32_t af[4][4];
            #pragma unroll
            for (int mi = 0; mi < 4; mi++) {
                int r = wm * 64 + mi * 16;
                af[mi][0] = __float_as_uint(Ac[(r + g) * GSTR_A + kk + t4]);
                af[mi][1] = __float_as_uint(Ac[(r + g + 8) * GSTR_A + kk + t4]);
                af[mi][2] = __float_as_uint(Ac[(r + g) * GSTR_A + kk + t4 + 4]);
                af[mi][3] = __float_as_uint(Ac[(r + g + 8) * GSTR_A + kk + t4 + 4]);
            }
            uint32_t bf[4][2];
            #pragma unroll
            for (int ni = 0; ni < 4; ni++) {
                int c = wn * 32 + ni * 8 + g;
                bf[ni][0] = __float_as_uint(Bc[(kk + t4) * GSTR_B + c]);
                bf[ni][1] = __float_as_uint(Bc[(kk + t4 + 4) * GSTR_B + c]);
            }
            #pragma unroll
            for (int mi = 0; mi < 4; mi++)
                #pragma unroll
                for (int ni = 0; ni < 4; ni++)
                    mma_tf32(acc[mi][ni], af[mi], bf[ni]);
        }

        if (more) {
            const int nxt = cur ^ 1;
            float4 v;
            v = a_st0; v.x=tf32_rna(v.x); v.y=tf32_rna(v.y); v.z=tf32_rna(v.z); v.w=tf32_rna(v.w);
            *(float4*)(&As[nxt][rA0 * GSTR_A + cA0 * 4]) = v;
            v = a_st1; v.x=tf32_rna(v.x); v.y=tf32_rna(v.y); v.z=tf32_rna(v.z); v.w=tf32_rna(v.w);
            *(float4*)(&As[nxt][rA1 * GSTR_A + cA1 * 4]) = v;
            v = b_st0; v.x=tf32_rna(v.x); v.y=tf32_rna(v.y); v.z=tf32_rna(v.z); v.w=tf32_rna(v.w);
            *(float4*)(&Bs[nxt][rB0 * GSTR_B + cB0 * 4]) = v;
            v = b_st1; v.x=tf32_rna(v.x); v.y=tf32_rna(v.y); v.z=tf32_rna(v.z); v.w=tf32_rna(v.w);
            *(float4*)(&Bs[nxt][rB1 * GSTR_B + cB1 * 4]) = v;
        }
        __syncthreads();
        cur ^= 1;
    }

    // epilogue
    #pragma unroll
    for (int mi = 0; mi < 4; mi++) {
        #pragma unroll
        for (int ni = 0; ni < 4; ni++) {
            int r1 = bm + wm * 64 + mi * 16 + g;
            int c  = bn + wn * 32 + ni * 8 + t4 * 2;
            *(float2*)(C + (size_t)r1 * N + c)       = make_float2(acc[mi][ni][0], acc[mi][ni][1]);
            *(float2*)(C + (size_t)(r1 + 8) * N + c) = make_float2(acc[mi][ni][2], acc[mi][ni][3]);
        }
    }
}

__global__ __launch_bounds__(256)
void sgemm_tf32(const float* __restrict__ A, const float* __restrict__ B,
                float* __restrict__ C, int N, int K) {
    gemm_body(A, B, C, N, K, blockIdx.y * 128, blockIdx.x * 128);
}

// fused K-proj + V-proj: gridDim.x = 16 (first 8 -> K, last 8 -> V), N=1024
__global__ __launch_bounds__(256)
void sgemm_tf32_kv(const float* __restrict__ A,
                   const float* __restrict__ Bk, const float* __restrict__ Bv,
                   float* __restrict__ Ck, float* __restrict__ Cv, int N, int K) {
    const int bx = blockIdx.x;
    if (bx < 8) gemm_body(A, Bk, Ck, N, K, blockIdx.y * 128, bx * 128);
    else        gemm_body(A, Bv, Cv, N, K, blockIdx.y * 128, (bx - 8) * 128);
}

// ---------------- RMSNorm + RoPE ----------------
__global__ __launch_bounds__(128)
void rmsnorm_rope(float* __restrict__ buf, const float* __restrict__ w,
                  const float* __restrict__ cosT, const float* __restrict__ sinT,
                  const int* __restrict__ pos_ids, int n_heads) {
    const int s = blockIdx.x;
    const int h = blockIdx.y;
    const int d = threadIdx.x;

    float* row = buf + (size_t)s * n_heads * HD + h * HD;
    float v = row[d];

    float ss = v * v;
    #pragma unroll
    for (int off = 16; off > 0; off >>= 1)
        ss += __shfl_xor_sync(0xffffffffu, ss, off);
    __shared__ float wsum[4];
    if ((d & 31) == 0) wsum[d >> 5] = ss;
    __syncthreads();
    float total = wsum[0] + wsum[1] + wsum[2] + wsum[3];
    float inv = rsqrtf(total * (1.0f / HD) + 1e-6f);

    float xn = v * inv * w[d];
    __shared__ float xs[HD];
    xs[d] = xn;
    __syncthreads();

    const int p = pos_ids[s];
    float c  = cosT[(size_t)p * HD + d];
    float sn = sinT[(size_t)p * HD + d];
    float rot = (d < HD / 2) ? -xs[d + HD / 2] : xs[d - HD / 2];
    row[d] = xn * c + rot * sn;
}

// ---------------- Flash attention with tf32 MMA (causal, GQA 4:1) ----------------
#define AQ 128     // q rows per block
#define AK 64      // kv rows per tile
#define QSTR 132
#define KSTR 132
#define VSTR 136
#define PSTR 68
#define ATTN_SMEM ((AQ*QSTR + AK*KSTR + AK*VSTR + AQ*PSTR) * (int)sizeof(float))

__global__ __launch_bounds__(256, 1)
void flash_attn_mma(const float* __restrict__ Q, const float* __restrict__ Kb,
                    const float* __restrict__ Vb, float* __restrict__ O) {
    extern __shared__ __align__(16) float sm[];
    float* Qs = sm;                     // AQ x QSTR
    float* Ks = Qs + AQ * QSTR;         // AK x KSTR
    float* Vs = Ks + AK * KSTR;         // AK x VSTR
    float* Ps = Vs + AK * VSTR;         // AQ x PSTR

    const int tid  = threadIdx.x;
    const int warp = tid >> 5;
    const int lane = tid & 31;
    const int g    = lane >> 2;
    const int t4   = lane & 3;
    const int wrow = warp * 16;

    const int qb   = blockIdx.x;
    const int h    = blockIdx.y;
    const int kvh  = h >> 2;
    const int qbase = qb * AQ;
    const float scale = 0.08838834764831845f;  // 128^-0.5

    // load Q tile (scaled, tf32-rounded)
    for (int f = tid; f < AQ * 32; f += 256) {
        int row = f >> 5, c4 = f & 31;
        float4 v = *(const float4*)(Q + (size_t)(qbase + row) * (NQH * HD) + h * HD + c4 * 4);
        v.x = tf32_rna(v.x * scale); v.y = tf32_rna(v.y * scale);
        v.z = tf32_rna(v.z * scale); v.w = tf32_rna(v.w * scale);
        *(float4*)(Qs + row * QSTR + c4 * 4) = v;
    }

    float o[16][4];
    #pragma unroll
    for (int ni = 0; ni < 16; ni++)
        #pragma unroll
        for (int r = 0; r < 4; r++) o[ni][r] = 0.0f;
    float m1 = -INFINITY, m2 = -INFINITY, l1 = 0.0f, l2 = 0.0f;

    const int nkb = 2 * qb + 2;
    for (int kb = 0; kb < nkb; kb++) {
        __syncthreads();
        const int kbase = kb * AK;
        for (int f = tid; f < AK * 32; f += 256) {
            int row = f >> 5, c4 = f & 31;
            size_t gidx = (size_t)(kbase + row) * (NKV * HD) + kvh * HD + c4 * 4;
            float4 kv = *(const float4*)(Kb + gidx);
            kv.x = tf32_rna(kv.x); kv.y = tf32_rna(kv.y);
            kv.z = tf32_rna(kv.z); kv.w = tf32_rna(kv.w);
            *(float4*)(Ks + row * KSTR + c4 * 4) = kv;
            float4 vv = *(const float4*)(Vb + gidx);
            vv.x = tf32_rna(vv.x); vv.y = tf32_rna(vv.y);
            vv.z = tf32_rna(vv.z); vv.w = tf32_rna(vv.w);
            *(float4*)(Vs + row * VSTR + c4 * 4) = vv;
        }
        __syncthreads();

        // S = Q K^T : per warp 16 rows x 64 cols
        float s[8][4];
        #pragma unroll
        for (int ni = 0; ni < 8; ni++)
            #pragma unroll
            for (int r = 0; r < 4; r++) s[ni][r] = 0.0f;

        #pragma unroll
        for (int k0 = 0; k0 < HD; k0 += 8) {
            uint32_t af[4];
            af[0] = __float_as_uint(Qs[(wrow + g) * QSTR + k0 + t4]);
            af[1] = __float_as_uint(Qs[(wrow + g + 8) * QSTR + k0 + t4]);
            af[2] = __float_as_uint(Qs[(wrow + g) * QSTR + k0 + t4 + 4]);
            af[3] = __float_as_uint(Qs[(wrow + g + 8) * QSTR + k0 + t4 + 4]);
            #pragma unroll
            for (int ni = 0; ni < 8; ni++) {
                uint32_t bf[2];
                bf[0] = __float_as_uint(Ks[(ni * 8 + g) * KSTR + k0 + t4]);
                bf[1] = __float_as_uint(Ks[(ni * 8 + g) * KSTR + k0 + t4 + 4]);
                mma_tf32(s[ni], af, bf);
            }
        }

        // causal mask (only near diagonal)
        if (kb >= 2 * qb) {
            const int r1 = qbase + wrow + g;
            const int r2 = r1 + 8;
            #pragma unroll
            for (int ni = 0; ni < 8; ni++) {
                int c0 = kbase + ni * 8 + t4 * 2;
                if (c0     > r1) s[ni][0] = -1e30f;
                if (c0 + 1 > r1) s[ni][1] = -1e30f;
                if (c0     > r2) s[ni][2] = -1e30f;
                if (c0 + 1 > r2) s[ni][3] = -1e30f;
            }
        }

        // online softmax (fp32)
        float mx1 = -INFINITY, mx2 = -INFINITY;
        #pragma unroll
        for (int ni = 0; ni < 8; ni++) {
            mx1 = fmaxf(mx1, fmaxf(s[ni][0], s[ni][1]));
            mx2 = fmaxf(mx2, fmaxf(s[ni][2], s[ni][3]));
        }
        mx1 = fmaxf(mx1, __shfl_xor_sync(0xffffffffu, mx1, 1));
        mx1 = fmaxf(mx1, __shfl_xor_sync(0xffffffffu, mx1, 2));
        mx2 = fmaxf(mx2, __shfl_xor_sync(0xffffffffu, mx2, 1));
        mx2 = fmaxf(mx2, __shfl_xor_sync(0xffffffffu, mx2, 2));

        float mn1 = fmaxf(m1, mx1), mn2 = fmaxf(m2, mx2);
        float sc1 = __expf(m1 - mn1), sc2 = __expf(m2 - mn2);
        m1 = mn1; m2 = mn2;

        float ps1 = 0.0f, ps2 = 0.0f;
        #pragma unroll
        for (int ni = 0; ni < 8; ni++) {
            float p0 = __expf(s[ni][0] - mn1);
            float p1 = __expf(s[ni][1] - mn1);
            float p2 = __expf(s[ni][2] - mn2);
            float p3 = __expf(s[ni][3] - mn2);
            ps1 += p0 + p1; ps2 += p2 + p3;
            float* pr1 = Ps + (wrow + g) * PSTR + ni * 8 + t4 * 2;
            float* pr2 = Ps + (wrow + g + 8) * PSTR + ni * 8 + t4 * 2;
            pr1[0] = tf32_rna(p0); pr1[1] = tf32_rna(p1);
            pr2[0] = tf32_rna(p2); pr2[1] = tf32_rna(p3);
        }
        ps1 += __shfl_xor_sync(0xffffffffu, ps1, 1);
        ps1 += __shfl_xor_sync(0xffffffffu, ps1, 2);
        ps2 += __shfl_xor_sync(0xffffffffu, ps2, 1);
        ps2 += __shfl_xor_sync(0xffffffffu, ps2, 2);
        l1 = l1 * sc1 + ps1;
        l2 = l2 * sc2 + ps2;

        #pragma unroll
        for (int ni = 0; ni < 16; ni++) {
            o[ni][0] *= sc1; o[ni][1] *= sc1;
            o[ni][2] *= sc2; o[ni][3] *= sc2;
        }
        __syncwarp();

        // O += P V : per warp 16 rows x 128 cols
        #pragma unroll
        for (int k0 = 0; k0 < AK; k0 += 8) {
            uint32_t af[4];
            af[0] = __float_as_uint(Ps[(wrow + g) * PSTR + k0 + t4]);
            af[1] = __float_as_uint(Ps[(wrow + g + 8) * PSTR + k0 + t4]);
            af[2] = __float_as_uint(Ps[(wrow + g) * PSTR + k0 + t4 + 4]);
            af[3] = __float_as_uint(Ps[(wrow + g + 8) * PSTR + k0 + t4 + 4]);
            #pragma unroll
            for (int ni = 0; ni < 16; ni++) {
                uint32_t bf[2];
                bf[0] = __float_as_uint(Vs[(k0 + t4) * VSTR + ni * 8 + g]);
                bf[1] = __float_as_uint(Vs[(k0 + t4 + 4) * VSTR + ni * 8 + g]);
                mma_tf32(o[ni], af, bf);
            }
        }
    }

    // epilogue
    const float inv1 = 1.0f / l1;
    const float inv2 = 1.0f / l2;
    const int r1 = qbase + wrow + g;
    #pragma unroll
    for (int ni = 0; ni < 16; ni++) {
        int c = ni * 8 + t4 * 2;
        *(float2*)(O + (size_t)r1 * (NQH * HD) + h * HD + c) =
            make_float2(o[ni][0] * inv1, o[ni][1] * inv1);
        *(float2*)(O + (size_t)(r1 + 8) * (NQH * HD) + h * HD + c) =
            make_float2(o[ni][2] * inv2, o[ni][3] * inv2);
    }
}

// ---------------- launch ----------------
extern "C" void kernel_launch(void* const* d_in, const int* in_sizes, int n_in,
                              void* d_out, int out_size) {
    const float* x    = (const float*)d_in[0];
    const int*   pos  = (const int*)  d_in[1];
    const float* cosT = (const float*)d_in[2];
    const float* sinT = (const float*)d_in[3];
    // d_in[4] = attn_mask — replicated exactly by causal skip
    const float* Wq   = (const float*)d_in[5];
    const float* Wk   = (const float*)d_in[6];
    const float* Wv   = (const float*)d_in[7];
    const float* Wo   = (const float*)d_in[8];
    const float* qw   = (const float*)d_in[9];
    const float* kw   = (const float*)d_in[10];
    float* out = (float*)d_out;

    float *qp, *kp, *vp, *op;
    cudaGetSymbolAddress((void**)&qp, g_q);
    cudaGetSymbolAddress((void**)&kp, g_k);
    cudaGetSymbolAddress((void**)&vp, g_v);
    cudaGetSymbolAddress((void**)&op, g_o);

    cudaFuncSetAttribute(flash_attn_mma, cudaFuncAttributeMaxDynamicSharedMemorySize, ATTN_SMEM);

    // Q projection
    sgemm_tf32<<<dim3(NQH * HD / 128, SEQ / 128), 256>>>(x, Wq, qp, NQH * HD, HID);
    // fused K+V projections (one full-chip wave)
    sgemm_tf32_kv<<<dim3(16, SEQ / 128), 256>>>(x, Wk, Wv, kp, vp, NKV * HD, HID);

    // per-head RMSNorm + RoPE
    rmsnorm_rope<<<dim3(SEQ, NQH), 128>>>(qp, qw, cosT, sinT, pos, NQH);
    rmsnorm_rope<<<dim3(SEQ, NKV), 128>>>(kp, kw, cosT, sinT, pos, NKV);

    // causal flash attention (tf32 mma)
    flash_attn_mma<<<dim3(SEQ / AQ, NQH), 256, ATTN_SMEM>>>(qp, kp, vp, op);

    // output projection
    sgemm_tf32<<<dim3(HID / 128, SEQ / 128), 256>>>(op, Wo, out, HID, HID);
}

// round 6
// speedup vs baseline: 6.3047x; 1.6399x over previous
#include <cuda_runtime.h>
#include <cuda_fp16.h>
#include <math.h>
#include <stdint.h>

#define SEQ 2048
#define HID 4096
#define NQH 32
#define NKV 8
#define HD  128

// ---------------- scratch (no cudaMalloc allowed) ----------------
__device__ float  g_q[SEQ * NQH * HD];
__device__ float  g_k[SEQ * NKV * HD];
__device__ float  g_v[SEQ * NKV * HD];
__device__ __half g_xh[SEQ * HID];
__device__ __half g_qh[SEQ * NQH * HD];
__device__ __half g_kh[SEQ * NKV * HD];
__device__ __half g_vh[SEQ * NKV * HD];
__device__ __half g_oh[SEQ * NQH * HD];
__device__ __half g_WqT[(NQH * HD) * HID];
__device__ __half g_WkT[(NKV * HD) * HID];
__device__ __half g_WvT[(NKV * HD) * HID];
__device__ __half g_WoT[HID * (NQH * HD)];

// ---------------- asm helpers (all baseline PTX: sm_80-class) ----------------
__device__ __forceinline__ uint32_t smem_u32(const void* p) {
    uint32_t a;
    asm("{ .reg .u64 t; cvta.to.shared.u64 t, %1; cvt.u32.u64 %0, t; }" : "=r"(a) : "l"(p));
    return a;
}
#define CP_A16(dst, src) asm volatile("cp.async.cg.shared.global [%0], [%1], 16;" :: "r"(dst), "l"(src))
#define CP_COMMIT() asm volatile("cp.async.commit_group;")
#define CP_WAIT(n)  asm volatile("cp.async.wait_group %0;" :: "n"(n))

__device__ __forceinline__ void ldsm_x4(uint32_t* r, uint32_t a) {
    asm volatile("ldmatrix.sync.aligned.m8n8.x4.shared.b16 {%0,%1,%2,%3}, [%4];"
                 : "=r"(r[0]), "=r"(r[1]), "=r"(r[2]), "=r"(r[3]) : "r"(a));
}
__device__ __forceinline__ void ldsm_x2(uint32_t* r, uint32_t a) {
    asm volatile("ldmatrix.sync.aligned.m8n8.x2.shared.b16 {%0,%1}, [%2];"
                 : "=r"(r[0]), "=r"(r[1]) : "r"(a));
}
__device__ __forceinline__ void ldsm_x2_t(uint32_t* r, uint32_t a) {
    asm volatile("ldmatrix.sync.aligned.m8n8.x2.trans.shared.b16 {%0,%1}, [%2];"
                 : "=r"(r[0]), "=r"(r[1]) : "r"(a));
}
__device__ __forceinline__ void mma16816(float (&d)[4], const uint32_t (&a)[4], const uint32_t (&b)[2]) {
    asm volatile(
        "mma.sync.aligned.m16n8k16.row.col.f32.f16.f16.f32 "
        "{%0,%1,%2,%3}, {%4,%5,%6,%7}, {%8,%9}, {%0,%1,%2,%3};"
        : "+f"(d[0]), "+f"(d[1]), "+f"(d[2]), "+f"(d[3])
        : "r"(a[0]), "r"(a[1]), "r"(a[2]), "r"(a[3]), "r"(b[0]), "r"(b[1]));
}
__device__ __forceinline__ uint32_t pack_h2(float lo, float hi) {
    __half2 h = __floats2half2_rn(lo, hi);
    return *(uint32_t*)&h;
}

// ---------------- pre-pass kernels ----------------
__global__ __launch_bounds__(256)
void cvt_f2h(const float* __restrict__ in, __half* __restrict__ out, int n) {
    int i = (blockIdx.x * 256 + threadIdx.x) * 4;
    if (i < n) {
        float4 v = *(const float4*)(in + i);
        uint32_t lo = pack_h2(v.x, v.y);
        uint32_t hi = pack_h2(v.z, v.w);
        *(uint2*)(out + i) = make_uint2(lo, hi);
    }
}

// out[c*R + r] = half(in[r*C + c]); R,C multiples of 32
__global__ __launch_bounds__(256)
void transpose_cvt_h(const float* __restrict__ in, __half* __restrict__ out, int R, int C) {
    __shared__ float tile[32][33];
    const int tx = threadIdx.x, ty = threadIdx.y;
    const int c0 = blockIdx.x * 32;
    const int r0 = blockIdx.y * 32;
    #pragma unroll
    for (int j = ty; j < 32; j += 8)
        tile[j][tx] = in[(size_t)(r0 + j) * C + c0 + tx];
    __syncthreads();
    #pragma unroll
    for (int j = ty; j < 32; j += 8)
        out[(size_t)(c0 + j) * R + r0 + tx] = __float2half(tile[tx][j]);
}

// ---------------- fp16 GEMM: C[M,N](f32) = A[M,K](h) @ Bt[N,K](h)^T ----------------
// 128x128 tile, BK=32, 256 threads = 8 warps (2x4), warp tile 64x32, cp.async 2-stage.
#define HG_STR 40                       // halves per smem row (32 + 8 pad); 80B, 16B-aligned rows
#define HG_ST  (128 * HG_STR)           // halves per stage

__device__ __forceinline__
void hgemm_body(const __half* __restrict__ A, const __half* __restrict__ Bt,
                float* __restrict__ C, int Ncols, int K, int bm, int bn) {
    __shared__ __align__(16) __half As[2][HG_ST];
    __shared__ __align__(16) __half Bs[2][HG_ST];

    const int tid  = threadIdx.x;
    const int warp = tid >> 5;
    const int lane = tid & 31;
    const int g    = lane >> 2;
    const int t4   = lane & 3;
    const int wm   = warp >> 2;
    const int wn   = warp & 3;

    // load map: tile = 128 rows x 4 chunks(16B) = 512 chunks; 2 per thread
    const int ch0 = tid, ch1 = tid + 256;
    const int rA0 = ch0 >> 2, kA0 = (ch0 & 3) * 8;
    const int rA1 = ch1 >> 2, kA1 = (ch1 & 3) * 8;

    const __half* Asrc0 = A + (size_t)(bm + rA0) * K + kA0;
    const __half* Asrc1 = A + (size_t)(bm + rA1) * K + kA1;
    const __half* Bsrc0 = Bt + (size_t)(bn + rA0) * K + kA0;
    const __half* Bsrc1 = Bt + (size_t)(bn + rA1) * K + kA1;

    const uint32_t asb = smem_u32(As);
    const uint32_t bsb = smem_u32(Bs);
    const uint32_t dA0 = asb + (rA0 * HG_STR + kA0) * 2;
    const uint32_t dA1 = asb + (rA1 * HG_STR + kA1) * 2;
    const uint32_t dB0 = bsb + (rA0 * HG_STR + kA0) * 2;
    const uint32_t dB1 = bsb + (rA1 * HG_STR + kA1) * 2;
    const uint32_t STB = HG_ST * 2;   // stage bytes

    // ldmatrix lane addressing
    const int arow = (lane & 7) + ((lane >> 3) & 1) * 8;
    const int acol = (lane >> 4) * 8;
    const uint32_t aBase = asb + ((wm * 64 + arow) * HG_STR + acol) * 2;
    const int l15  = lane & 15;
    const uint32_t bBase = bsb + ((wn * 32 + (l15 & 7)) * HG_STR + (l15 >> 3) * 8) * 2;

    float acc[4][4][4];
    #pragma unroll
    for (int mi = 0; mi < 4; mi++)
        #pragma unroll
        for (int ni = 0; ni < 4; ni++)
            #pragma unroll
            for (int r = 0; r < 4; r++) acc[mi][ni][r] = 0.0f;

    const int iters = K >> 5;

    // prologue
    CP_A16(dA0, Asrc0); CP_A16(dA1, Asrc1);
    CP_A16(dB0, Bsrc0); CP_A16(dB1, Bsrc1);
    CP_COMMIT();

    for (int i = 0; i < iters; i++) {
        if (i + 1 < iters) {
            const int st = (i + 1) & 1;
            const int ko = (i + 1) << 5;
            CP_A16(dA0 + st * STB, Asrc0 + ko); CP_A16(dA1 + st * STB, Asrc1 + ko);
            CP_A16(dB0 + st * STB, Bsrc0 + ko); CP_A16(dB1 + st * STB, Bsrc1 + ko);
            CP_COMMIT();
            CP_WAIT(1);
        } else {
            CP_WAIT(0);
        }
        __syncthreads();

        const uint32_t so = (i & 1) * STB;
        #pragma unroll
        for (int kb = 0; kb < 2; kb++) {
            uint32_t af[4][4];
            #pragma unroll
            for (int mi = 0; mi < 4; mi++)
                ldsm_x4(af[mi], aBase + so + mi * (16 * HG_STR * 2) + kb * 32);
            uint32_t bf[4][2];
            #pragma unroll
            for (int ni = 0; ni < 4; ni++)
                ldsm_x2(bf[ni], bBase + so + ni * (8 * HG_STR * 2) + kb * 32);
            #pragma unroll
            for (int mi = 0; mi < 4; mi++)
                #pragma unroll
                for (int ni = 0; ni < 4; ni++)
                    mma16816(acc[mi][ni], af[mi], bf[ni]);
        }
        __syncthreads();
    }

    #pragma unroll
    for (int mi = 0; mi < 4; mi++) {
        #pragma unroll
        for (int ni = 0; ni < 4; ni++) {
            int r1 = bm + wm * 64 + mi * 16 + g;
            int c  = bn + wn * 32 + ni * 8 + t4 * 2;
            *(float2*)(C + (size_t)r1 * Ncols + c)       = make_float2(acc[mi][ni][0], acc[mi][ni][1]);
            *(float2*)(C + (size_t)(r1 + 8) * Ncols + c) = make_float2(acc[mi][ni][2], acc[mi][ni][3]);
        }
    }
}

__global__ __launch_bounds__(256, 1)
void hgemm(const __half* __restrict__ A, const __half* __restrict__ Bt,
           float* __restrict__ C, int Ncols, int K) {
    hgemm_body(A, Bt, C, Ncols, K, blockIdx.y * 128, blockIdx.x * 128);
}

// fused K+V projections: gridDim.x = 16 (first 8 -> K, last 8 -> V)
__global__ __launch_bounds__(256, 1)
void hgemm_kv(const __half* __restrict__ A,
              const __half* __restrict__ BtK, const __half* __restrict__ BtV,
              float* __restrict__ Ck, float* __restrict__ Cv, int Ncols, int K) {
    const int bx = blockIdx.x;
    if (bx < 8) hgemm_body(A, BtK, Ck, Ncols, K, blockIdx.y * 128, bx * 128);
    else        hgemm_body(A, BtV, Cv, Ncols, K, blockIdx.y * 128, (bx - 8) * 128);
}

// ---------------- RMSNorm + RoPE (fp32 in, fp16 out, optional output scale) ----------------
__global__ __launch_bounds__(128)
void rmsnorm_rope_h(const float* __restrict__ buf, __half* __restrict__ outh,
                    const float* __restrict__ w,
                    const float* __restrict__ cosT, const float* __restrict__ sinT,
                    const int* __restrict__ pos_ids, int n_heads, float oscale) {
    const int s = blockIdx.x;
    const int h = blockIdx.y;
    const int d = threadIdx.x;

    const float* row = buf + (size_t)s * n_heads * HD + h * HD;
    float v = row[d];

    float ss = v * v;
    #pragma unroll
    for (int off = 16; off > 0; off >>= 1)
        ss += __shfl_xor_sync(0xffffffffu, ss, off);
    __shared__ float wsum[4];
    if ((d & 31) == 0) wsum[d >> 5] = ss;
    __syncthreads();
    float total = wsum[0] + wsum[1] + wsum[2] + wsum[3];
    float inv = rsqrtf(total * (1.0f / HD) + 1e-6f);

    float xn = v * inv * w[d];
    __shared__ float xs[HD];
    xs[d] = xn;
    __syncthreads();

    const int p = pos_ids[s];
    float c  = cosT[(size_t)p * HD + d];
    float sn = sinT[(size_t)p * HD + d];
    float rot = (d < HD / 2) ? -xs[d + HD / 2] : xs[d - HD / 2];
    outh[(size_t)s * n_heads * HD + h * HD + d] = __float2half((xn * c + rot * sn) * oscale);
}

// ---------------- fp16 flash attention (causal, GQA 4:1) ----------------
// Q block 128, KV tile 64 (double-buffered via cp.async), 256 threads = 8 warps x 16 rows.
#define FSTR 136                        // halves per row (128 + 8 pad); 272B rows, 16B aligned
#define FQ_HALVES (128 * FSTR)
#define FK_HALVES (64 * FSTR)
#define ATTN_SMEM ((FQ_HALVES + 4 * FK_HALVES) * 2)

__global__ __launch_bounds__(256, 1)
void flash_h(const __half* __restrict__ Qh, const __half* __restrict__ Kh,
             const __half* __restrict__ Vh, __half* __restrict__ Oh) {
    extern __shared__ __align__(16) __half fsm[];
    __half* Qs = fsm;                          // 128 x FSTR
    __half* Ks = fsm + FQ_HALVES;              // 2 stages x 64 x FSTR
    __half* Vs = Ks + 2 * FK_HALVES;           // 2 stages x 64 x FSTR

    const int tid  = threadIdx.x;
    const int warp = tid >> 5;
    const int lane = tid & 31;
    const int g    = lane >> 2;
    const int t4   = lane & 3;
    const int l15  = lane & 15;
    const int wrow = warp * 16;

    const int qb    = blockIdx.x;
    const int h     = blockIdx.y;
    const int kvh   = h >> 2;
    const int qbase = qb * 128;

    const uint32_t qsb = smem_u32(Qs);
    const uint32_t ksb = smem_u32(Ks);
    const uint32_t vsb = smem_u32(Vs);
    const uint32_t KSTB = FK_HALVES * 2;

    // ---- issue Q (8 chunks/thread) + KV tile 0, one commit group
    {
        #pragma unroll
        for (int j = 0; j < 8; j++) {
            int c = tid + j * 256;
            int row = c >> 4, c8 = c & 15;
            CP_A16(qsb + (row * FSTR + c8 * 8) * 2,
                   Qh + (size_t)(qbase + row) * (NQH * HD) + h * HD + c8 * 8);
        }
        #pragma unroll
        for (int j = 0; j < 4; j++) {
            int c = tid + j * 256;
            int row = c >> 4, c8 = c & 15;
            size_t gi = (size_t)row * (NKV * HD) + kvh * HD + c8 * 8;
            CP_A16(ksb + (row * FSTR + c8 * 8) * 2, Kh + gi);
            CP_A16(vsb + (row * FSTR + c8 * 8) * 2, Vh + gi);
        }
        CP_COMMIT();
    }

    float o[16][4];
    #pragma unroll
    for (int ni = 0; ni < 16; ni++)
        #pragma unroll
        for (int r = 0; r < 4; r++) o[ni][r] = 0.0f;
    float m1 = -INFINITY, m2 = -INFINITY, l1 = 0.0f, l2 = 0.0f;

    // ldmatrix lane bases
    const int arow = (lane & 7) + ((lane >> 3) & 1) * 8;
    const int acol = (lane >> 4) * 8;
    const uint32_t qBase = qsb + ((wrow + arow) * FSTR + acol) * 2;
    const uint32_t kBase = ksb + (((l15 & 7)) * FSTR + (l15 >> 3) * 8) * 2;
    const uint32_t vBase = vsb + (((l15 & 7) + (l15 >> 3) * 8) * FSTR) * 2;

    const int nkb = 2 * qb + 2;
    for (int kb = 0; kb < nkb; kb++) {
        if (kb + 1 < nkb) {
            const int st = (kb + 1) & 1;
            const int kbase1 = (kb + 1) * 64;
            #pragma unroll
            for (int j = 0; j < 4; j++) {
                int c = tid + j * 256;
                int row = c >> 4, c8 = c & 15;
                size_t gi = (size_t)(kbase1 + row) * (NKV * HD) + kvh * HD + c8 * 8;
                CP_A16(ksb + st * KSTB + (row * FSTR + c8 * 8) * 2, Kh + gi);
                CP_A16(vsb + st * KSTB + (row * FSTR + c8 * 8) * 2, Vh + gi);
            }
            CP_COMMIT();
            CP_WAIT(1);
        } else {
            CP_WAIT(0);
        }
        __syncthreads();

        const uint32_t so = (kb & 1) * KSTB;
        const int kbase = kb * 64;

        // ---- S = Q K^T : 16 rows x 64 cols per warp
        float s[8][4];
        #pragma unroll
        for (int ni = 0; ni < 8; ni++)
            #pragma unroll
            for (int r = 0; r < 4; r++) s[ni][r] = 0.0f;

        #pragma unroll
        for (int k0 = 0; k0 < HD; k0 += 16) {
            uint32_t aq[4];
            ldsm_x4(aq, qBase + k0 * 2);
            #pragma unroll
            for (int ni = 0; ni < 8; ni++) {
                uint32_t bk[2];
                ldsm_x2(bk, kBase + so + ni * (8 * FSTR * 2) + k0 * 2);
                mma16816(s[ni], aq, bk);
            }
        }

        // ---- causal mask
        if (kbase + 63 > qbase + wrow) {
            const int r1 = qbase + wrow + g;
            const int r2 = r1 + 8;
            #pragma unroll
            for (int ni = 0; ni < 8; ni++) {
                int c0 = kbase + ni * 8 + t4 * 2;
                if (c0     > r1) s[ni][0] = -1e30f;
                if (c0 + 1 > r1) s[ni][1] = -1e30f;
                if (c0     > r2) s[ni][2] = -1e30f;
                if (c0 + 1 > r2) s[ni][3] = -1e30f;
            }
        }

        // ---- online softmax (fp32); s becomes P in place
        float mx1 = -INFINITY, mx2 = -INFINITY;
        #pragma unroll
        for (int ni = 0; ni < 8; ni++) {
            mx1 = fmaxf(mx1, fmaxf(s[ni][0], s[ni][1]));
            mx2 = fmaxf(mx2, fmaxf(s[ni][2], s[ni][3]));
        }
        mx1 = fmaxf(mx1, __shfl_xor_sync(0xffffffffu, mx1, 1));
        mx1 = fmaxf(mx1, __shfl_xor_sync(0xffffffffu, mx1, 2));
        mx2 = fmaxf(mx2, __shfl_xor_sync(0xffffffffu, mx2, 1));
        mx2 = fmaxf(mx2, __shfl_xor_sync(0xffffffffu, mx2, 2));

        float mn1 = fmaxf(m1, mx1), mn2 = fmaxf(m2, mx2);
        float sc1 = __expf(m1 - mn1), sc2 = __expf(m2 - mn2);
        m1 = mn1; m2 = mn2;

        float ps1 = 0.0f, ps2 = 0.0f;
        #pragma unroll
        for (int ni = 0; ni < 8; ni++) {
            s[ni][0] = __expf(s[ni][0] - mn1);
            s[ni][1] = __expf(s[ni][1] - mn1);
            s[ni][2] = __expf(s[ni][2] - mn2);
            s[ni][3] = __expf(s[ni][3] - mn2);
            ps1 += s[ni][0] + s[ni][1];
            ps2 += s[ni][2] + s[ni][3];
        }
        ps1 += __shfl_xor_sync(0xffffffffu, ps1, 1);
        ps1 += __shfl_xor_sync(0xffffffffu, ps1, 2);
        ps2 += __shfl_xor_sync(0xffffffffu, ps2, 1);
        ps2 += __shfl_xor_sync(0xffffffffu, ps2, 2);
        l1 = l1 * sc1 + ps1;
        l2 = l2 * sc2 + ps2;

        #pragma unroll
        for (int ni = 0; ni < 16; ni++) {
            o[ni][0] *= sc1; o[ni][1] *= sc1;
            o[ni][2] *= sc2; o[ni][3] *= sc2;
        }

        // ---- O += P V : P packed from registers, V via ldmatrix.trans
        #pragma unroll
        for (int j = 0; j < 4; j++) {
            uint32_t ap[4];
            ap[0] = pack_h2(s[2 * j][0],     s[2 * j][1]);
            ap[1] = pack_h2(s[2 * j][2],     s[2 * j][3]);
            ap[2] = pack_h2(s[2 * j + 1][0], s[2 * j + 1][1]);
            ap[3] = pack_h2(s[2 * j + 1][2], s[2 * j + 1][3]);
            #pragma unroll
            for (int ni = 0; ni < 16; ni++) {
                uint32_t bv[2];
                ldsm_x2_t(bv, vBase + so + j * (16 * FSTR * 2) + ni * 16);
                mma16816(o[ni], ap, bv);
            }
        }
        __syncthreads();
    }

    // ---- epilogue: write fp16 O (feeds O-projection)
    const float inv1 = 1.0f / l1;
    const float inv2 = 1.0f / l2;
    const int r1 = qbase + wrow + g;
    #pragma unroll
    for (int ni = 0; ni < 16; ni++) {
        int c = ni * 8 + t4 * 2;
        *(uint32_t*)(Oh + (size_t)r1 * (NQH * HD) + h * HD + c) =
            pack_h2(o[ni][0] * inv1, o[ni][1] * inv1);
        *(uint32_t*)(Oh + (size_t)(r1 + 8) * (NQH * HD) + h * HD + c) =
            pack_h2(o[ni][2] * inv2, o[ni][3] * inv2);
    }
}

// ---------------- launch ----------------
extern "C" void kernel_launch(void* const* d_in, const int* in_sizes, int n_in,
                              void* d_out, int out_size) {
    const float* x    = (const float*)d_in[0];
    const int*   pos  = (const int*)  d_in[1];
    const float* cosT = (const float*)d_in[2];
    const float* sinT = (const float*)d_in[3];
    // d_in[4] = attn_mask — replicated exactly by causal skip
    const float* Wq   = (const float*)d_in[5];
    const float* Wk   = (const float*)d_in[6];
    const float* Wv   = (const float*)d_in[7];
    const float* Wo   = (const float*)d_in[8];
    const float* qw   = (const float*)d_in[9];
    const float* kw   = (const float*)d_in[10];
    float* out = (float*)d_out;

    float *qp, *kp, *vp;
    __half *xh, *qh, *kh, *vh, *oh, *wqT, *wkT, *wvT, *woT;
    cudaGetSymbolAddress((void**)&qp, g_q);
    cudaGetSymbolAddress((void**)&kp, g_k);
    cudaGetSymbolAddress((void**)&vp, g_v);
    cudaGetSymbolAddress((void**)&xh, g_xh);
    cudaGetSymbolAddress((void**)&qh, g_qh);
    cudaGetSymbolAddress((void**)&kh, g_kh);
    cudaGetSymbolAddress((void**)&vh, g_vh);
    cudaGetSymbolAddress((void**)&oh, g_oh);
    cudaGetSymbolAddress((void**)&wqT, g_WqT);
    cudaGetSymbolAddress((void**)&wkT, g_WkT);
    cudaGetSymbolAddress((void**)&wvT, g_WvT);
    cudaGetSymbolAddress((void**)&woT, g_WoT);

    cudaFuncSetAttribute(flash_h, cudaFuncAttributeMaxDynamicSharedMemorySize, ATTN_SMEM);

    // pre-pass: fp16 conversions + weight transposes
    cvt_f2h<<<SEQ * HID / 4 / 256, 256>>>(x, xh, SEQ * HID);
    transpose_cvt_h<<<dim3((NQH * HD) / 32, HID / 32), dim3(32, 8)>>>(Wq, wqT, HID, NQH * HD);
    transpose_cvt_h<<<dim3((NKV * HD) / 32, HID / 32), dim3(32, 8)>>>(Wk, wkT, HID, NKV * HD);
    transpose_cvt_h<<<dim3((NKV * HD) / 32, HID / 32), dim3(32, 8)>>>(Wv, wvT, HID, NKV * HD);
    transpose_cvt_h<<<dim3(HID / 32, (NQH * HD) / 32), dim3(32, 8)>>>(Wo, woT, NQH * HD, HID);

    // projections (fp16 HMMA)
    hgemm<<<dim3(NQH * HD / 128, SEQ / 128), 256>>>(xh, wqT, qp, NQH * HD, HID);
    hgemm_kv<<<dim3(16, SEQ / 128), 256>>>(xh, wkT, wvT, kp, vp, NKV * HD, HID);

    // RMSNorm + RoPE -> fp16 (q pre-scaled by 128^-0.5); V -> fp16
    rmsnorm_rope_h<<<dim3(SEQ, NQH), 128>>>(qp, qh, qw, cosT, sinT, pos, NQH, 0.08838834764831845f);
    rmsnorm_rope_h<<<dim3(SEQ, NKV), 128>>>(kp, kh, kw, cosT, sinT, pos, NKV, 1.0f);
    cvt_f2h<<<SEQ * NKV * HD / 4 / 256, 256>>>(vp, vh, SEQ * NKV * HD);

    // causal flash attention (fp16 mma, register-resident P)
    flash_h<<<dim3(SEQ / 128, NQH), 256, ATTN_SMEM>>>(qh, kh, vh, oh);

    // output projection
    hgemm<<<dim3(HID / 128, SEQ / 128), 256>>>(oh, woT, out, HID, HID);
}

// round 7
// speedup vs baseline: 7.3478x; 1.1654x over previous
#include <cuda_runtime.h>
#include <cuda_fp16.h>
#include <math.h>
#include <stdint.h>

#define SEQ 2048
#define HID 4096
#define NQH 32
#define NKV 8
#define HD  128

// ---------------- scratch (no cudaMalloc allowed) ----------------
__device__ float  g_q[SEQ * NQH * HD];
__device__ float  g_k[SEQ * NKV * HD];
__device__ float  g_v[SEQ * NKV * HD];
__device__ __half g_xh[SEQ * HID];
__device__ __half g_qh[SEQ * NQH * HD];
__device__ __half g_kh[SEQ * NKV * HD];
__device__ __half g_vh[SEQ * NKV * HD];
__device__ __half g_oh[SEQ * NQH * HD];
__device__ __half g_WqT[(NQH * HD) * HID];
__device__ __half g_WkT[(NKV * HD) * HID];
__device__ __half g_WvT[(NKV * HD) * HID];
__device__ __half g_WoT[HID * (NQH * HD)];

// ---------------- asm helpers ----------------
__device__ __forceinline__ uint32_t smem_u32(const void* p) {
    uint32_t a;
    asm("{ .reg .u64 t; cvta.to.shared.u64 t, %1; cvt.u32.u64 %0, t; }" : "=r"(a) : "l"(p));
    return a;
}
#define CP_A16(dst, src) asm volatile("cp.async.cg.shared.global [%0], [%1], 16;" :: "r"(dst), "l"(src))
#define CP_COMMIT() asm volatile("cp.async.commit_group;")
#define CP_WAIT(n)  asm volatile("cp.async.wait_group %0;" :: "n"(n))

__device__ __forceinline__ void ldsm_x4(uint32_t* r, uint32_t a) {
    asm volatile("ldmatrix.sync.aligned.m8n8.x4.shared.b16 {%0,%1,%2,%3}, [%4];"
                 : "=r"(r[0]), "=r"(r[1]), "=r"(r[2]), "=r"(r[3]) : "r"(a));
}
__device__ __forceinline__ void ldsm_x4_t(uint32_t* r, uint32_t a) {
    asm volatile("ldmatrix.sync.aligned.m8n8.x4.trans.shared.b16 {%0,%1,%2,%3}, [%4];"
                 : "=r"(r[0]), "=r"(r[1]), "=r"(r[2]), "=r"(r[3]) : "r"(a));
}
__device__ __forceinline__ void mma16816(float (&d)[4], const uint32_t (&a)[4], uint32_t b0, uint32_t b1) {
    asm volatile(
        "mma.sync.aligned.m16n8k16.row.col.f32.f16.f16.f32 "
        "{%0,%1,%2,%3}, {%4,%5,%6,%7}, {%8,%9}, {%0,%1,%2,%3};"
        : "+f"(d[0]), "+f"(d[1]), "+f"(d[2]), "+f"(d[3])
        : "r"(a[0]), "r"(a[1]), "r"(a[2]), "r"(a[3]), "r"(b0), "r"(b1));
}
__device__ __forceinline__ uint32_t pack_h2(float lo, float hi) {
    __half2 h = __floats2half2_rn(lo, hi);
    return *(uint32_t*)&h;
}

// ---------------- pre-pass kernels ----------------
__global__ __launch_bounds__(256)
void cvt_f2h(const float* __restrict__ in, __half* __restrict__ out, int n) {
    int i = (blockIdx.x * 256 + threadIdx.x) * 4;
    if (i < n) {
        float4 v = *(const float4*)(in + i);
        *(uint2*)(out + i) = make_uint2(pack_h2(v.x, v.y), pack_h2(v.z, v.w));
    }
}

__global__ __launch_bounds__(256)
void transpose_cvt_h(const float* __restrict__ in, __half* __restrict__ out, int R, int C) {
    __shared__ float tile[32][33];
    const int tx = threadIdx.x, ty = threadIdx.y;
    const int c0 = blockIdx.x * 32;
    const int r0 = blockIdx.y * 32;
    #pragma unroll
    for (int j = ty; j < 32; j += 8)
        tile[j][tx] = in[(size_t)(r0 + j) * C + c0 + tx];
    __syncthreads();
    #pragma unroll
    for (int j = ty; j < 32; j += 8)
        out[(size_t)(c0 + j) * R + r0 + tx] = __float2half(tile[tx][j]);
}

// ---------------- fp16 GEMM: C[M,N](f32) = A[M,K](h) @ Bt[N,K](h)^T ----------------
// CTA tile 128(M) x 256(N), BK=32, 8 warps (2x4), warp tile 64x64, cp.async 2-stage, dyn smem.
#define HG_STR 40                                // halves per smem row (32 + 8 pad)
#define HG_A_ST (128 * HG_STR * 2)               // A stage bytes  (10240)
#define HG_B_ST (256 * HG_STR * 2)               // B stage bytes  (20480)
#define HG_SMEM (2 * HG_A_ST + 2 * HG_B_ST)      // 61440

__device__ __forceinline__
void hgemm_body(const __half* __restrict__ A, const __half* __restrict__ Bt,
                float* __restrict__ C, int Ncols, int K, int bm, int bn) {
    extern __shared__ __align__(16) __half hsm[];
    const uint32_t asb = smem_u32(hsm);                  // A: 2 stages
    const uint32_t bsb = asb + 2 * HG_A_ST;              // B: 2 stages

    const int tid  = threadIdx.x;
    const int warp = tid >> 5;
    const int lane = tid & 31;
    const int g    = lane >> 2;
    const int t4   = lane & 3;
    const int wm   = warp >> 2;   // 0..1
    const int wn   = warp & 3;    // 0..3

    // load map: chunk = 16B = 8 halves; rows have 4 chunks (BK=32)
    // A: 512 chunks -> 2/thread ; B: 1024 chunks -> 4/thread
    const __half* Asrc[2];
    uint32_t Adst[2];
    #pragma unroll
    for (int j = 0; j < 2; j++) {
        int ch = tid + j * 256;
        int row = ch >> 2, kc = (ch & 3) * 8;
        Asrc[j] = A + (size_t)(bm + row) * K + kc;
        Adst[j] = asb + (row * HG_STR + kc) * 2;
    }
    const __half* Bsrc[4];
    uint32_t Bdst[4];
    #pragma unroll
    for (int j = 0; j < 4; j++) {
        int ch = tid + j * 256;
        int row = ch >> 2, kc = (ch & 3) * 8;
        Bsrc[j] = Bt + (size_t)(bn + row) * K + kc;
        Bdst[j] = bsb + (row * HG_STR + kc) * 2;
    }

    // ldmatrix lane bases
    // A (m16k16): row = m + (lane&7) + ((lane>>3)&1)*8 ; col = (lane>>4)*8
    const uint32_t aBase = asb + ((wm * 64 + (lane & 7) + ((lane >> 3) & 1) * 8) * HG_STR
                                  + (lane >> 4) * 8) * 2;
    // B (two n8k16 tiles): row = n + (lane&7) + (lane>>4)*8 ; col = ((lane>>3)&1)*8
    const uint32_t bBase = bsb + ((wn * 64 + (lane & 7) + (lane >> 4) * 8) * HG_STR
                                  + ((lane >> 3) & 1) * 8) * 2;

    float acc[4][8][4];
    #pragma unroll
    for (int mi = 0; mi < 4; mi++)
        #pragma unroll
        for (int ni = 0; ni < 8; ni++)
            #pragma unroll
            for (int r = 0; r < 4; r++) acc[mi][ni][r] = 0.0f;

    const int iters = K >> 5;

    // prologue: stage 0
    #pragma unroll
    for (int j = 0; j < 2; j++) CP_A16(Adst[j], Asrc[j]);
    #pragma unroll
    for (int j = 0; j < 4; j++) CP_A16(Bdst[j], Bsrc[j]);
    CP_COMMIT();

    for (int i = 0; i < iters; i++) {
        if (i + 1 < iters) {
            const uint32_t ao = ((i + 1) & 1) * HG_A_ST;
            const uint32_t bo = ((i + 1) & 1) * HG_B_ST;
            const int ko = (i + 1) << 5;
            #pragma unroll
            for (int j = 0; j < 2; j++) CP_A16(Adst[j] + ao, Asrc[j] + ko);
            #pragma unroll
            for (int j = 0; j < 4; j++) CP_A16(Bdst[j] + bo, Bsrc[j] + ko);
            CP_COMMIT();
            CP_WAIT(1);
        } else {
            CP_WAIT(0);
        }
        __syncthreads();

        const uint32_t ao = (i & 1) * HG_A_ST;
        const uint32_t bo = (i & 1) * HG_B_ST;
        #pragma unroll
        for (int kb = 0; kb < 2; kb++) {
            uint32_t af[4][4];
            #pragma unroll
            for (int mi = 0; mi < 4; mi++)
                ldsm_x4(af[mi], aBase + ao + mi * (16 * HG_STR * 2) + kb * 32);
            uint32_t bf[4][4];
            #pragma unroll
            for (int nj = 0; nj < 4; nj++)
                ldsm_x4(bf[nj], bBase + bo + nj * (16 * HG_STR * 2) + kb * 32);
            #pragma unroll
            for (int mi = 0; mi < 4; mi++)
                #pragma unroll
                for (int nj = 0; nj < 4; nj++) {
                    mma16816(acc[mi][2 * nj],     af[mi], bf[nj][0], bf[nj][1]);
                    mma16816(acc[mi][2 * nj + 1], af[mi], bf[nj][2], bf[nj][3]);
                }
        }
        __syncthreads();
    }

    #pragma unroll
    for (int mi = 0; mi < 4; mi++) {
        #pragma unroll
        for (int ni = 0; ni < 8; ni++) {
            int r1 = bm + wm * 64 + mi * 16 + g;
            int c  = bn + wn * 64 + ni * 8 + t4 * 2;
            *(float2*)(C + (size_t)r1 * Ncols + c)       = make_float2(acc[mi][ni][0], acc[mi][ni][1]);
            *(float2*)(C + (size_t)(r1 + 8) * Ncols + c) = make_float2(acc[mi][ni][2], acc[mi][ni][3]);
        }
    }
}

// fused QKV: gridDim.x = 24 (0-15: Q, 16-19: K, 20-23: V)
__global__ __launch_bounds__(256, 1)
void hgemm_qkv(const __half* __restrict__ A,
               const __half* __restrict__ BtQ, const __half* __restrict__ BtK,
               const __half* __restrict__ BtV,
               float* __restrict__ Cq, float* __restrict__ Ck, float* __restrict__ Cv) {
    const int bx = blockIdx.x;
    const int bm = blockIdx.y * 128;
    if (bx < 16)      hgemm_body(A, BtQ, Cq, NQH * HD, HID, bm, bx * 256);
    else if (bx < 20) hgemm_body(A, BtK, Ck, NKV * HD, HID, bm, (bx - 16) * 256);
    else              hgemm_body(A, BtV, Cv, NKV * HD, HID, bm, (bx - 20) * 256);
}

__global__ __launch_bounds__(256, 1)
void hgemm_o(const __half* __restrict__ A, const __half* __restrict__ Bt,
             float* __restrict__ C) {
    hgemm_body(A, Bt, C, HID, NQH * HD, blockIdx.y * 128, blockIdx.x * 256);
}

// ---------------- RMSNorm + RoPE (fp32 in, fp16 out) ----------------
__global__ __launch_bounds__(128)
void rmsnorm_rope_h(const float* __restrict__ buf, __half* __restrict__ outh,
                    const float* __restrict__ w,
                    const float* __restrict__ cosT, const float* __restrict__ sinT,
                    const int* __restrict__ pos_ids, int n_heads, float oscale) {
    const int s = blockIdx.x;
    const int h = blockIdx.y;
    const int d = threadIdx.x;

    const float* row = buf + (size_t)s * n_heads * HD + h * HD;
    float v = row[d];

    float ss = v * v;
    #pragma unroll
    for (int off = 16; off > 0; off >>= 1)
        ss += __shfl_xor_sync(0xffffffffu, ss, off);
    __shared__ float wsum[4];
    if ((d & 31) == 0) wsum[d >> 5] = ss;
    __syncthreads();
    float total = wsum[0] + wsum[1] + wsum[2] + wsum[3];
    float inv = rsqrtf(total * (1.0f / HD) + 1e-6f);

    float xn = v * inv * w[d];
    __shared__ float xs[HD];
    xs[d] = xn;
    __syncthreads();

    const int p = pos_ids[s];
    float c  = cosT[(size_t)p * HD + d];
    float sn = sinT[(size_t)p * HD + d];
    float rot = (d < HD / 2) ? -xs[d + HD / 2] : xs[d - HD / 2];
    outh[(size_t)s * n_heads * HD + h * HD + d] = __float2half((xn * c + rot * sn) * oscale);
}

// ---------------- fp16 flash attention (causal, GQA 4:1) ----------------
#define FSTR 136
#define FQ_HALVES (128 * FSTR)
#define FK_HALVES (64 * FSTR)
#define ATTN_SMEM ((FQ_HALVES + 4 * FK_HALVES) * 2)

__global__ __launch_bounds__(256, 1)
void flash_h(const __half* __restrict__ Qh, const __half* __restrict__ Kh,
             const __half* __restrict__ Vh, __half* __restrict__ Oh) {
    extern __shared__ __align__(16) __half fsm[];
    __half* Qs = fsm;
    __half* Ks = fsm + FQ_HALVES;
    __half* Vs = Ks + 2 * FK_HALVES;

    const int tid  = threadIdx.x;
    const int warp = tid >> 5;
    const int lane = tid & 31;
    const int g    = lane >> 2;
    const int t4   = lane & 3;
    const int wrow = warp * 16;

    const int qb    = blockIdx.x;
    const int h     = blockIdx.y;
    const int kvh   = h >> 2;
    const int qbase = qb * 128;

    const uint32_t qsb = smem_u32(Qs);
    const uint32_t ksb = smem_u32(Ks);
    const uint32_t vsb = smem_u32(Vs);
    const uint32_t KSTB = FK_HALVES * 2;

    // Q + KV tile 0
    {
        #pragma unroll
        for (int j = 0; j < 8; j++) {
            int c = tid + j * 256;
            int row = c >> 4, c8 = c & 15;
            CP_A16(qsb + (row * FSTR + c8 * 8) * 2,
                   Qh + (size_t)(qbase + row) * (NQH * HD) + h * HD + c8 * 8);
        }
        #pragma unroll
        for (int j = 0; j < 4; j++) {
            int c = tid + j * 256;
            int row = c >> 4, c8 = c & 15;
            size_t gi = (size_t)row * (NKV * HD) + kvh * HD + c8 * 8;
            CP_A16(ksb + (row * FSTR + c8 * 8) * 2, Kh + gi);
            CP_A16(vsb + (row * FSTR + c8 * 8) * 2, Vh + gi);
        }
        CP_COMMIT();
    }

    float o[16][4];
    #pragma unroll
    for (int ni = 0; ni < 16; ni++)
        #pragma unroll
        for (int r = 0; r < 4; r++) o[ni][r] = 0.0f;
    float m1 = -INFINITY, m2 = -INFINITY, l1 = 0.0f, l2 = 0.0f;

    // lane bases
    const uint32_t qBase = qsb + ((wrow + (lane & 7) + ((lane >> 3) & 1) * 8) * FSTR
                                   + (lane >> 4) * 8) * 2;
    // K: two n8k16 per ldsm_x4: row = n + (lane&7) + (lane>>4)*8 ; col = ((lane>>3)&1)*8
    const uint32_t kBase = ksb + (((lane & 7) + (lane >> 4) * 8) * FSTR
                                   + ((lane >> 3) & 1) * 8) * 2;
    // V trans x4: row k = (lane&7) + ((lane>>3)&1)*8 ; col n = (lane>>4)*8
    const uint32_t vBase = vsb + (((lane & 7) + ((lane >> 3) & 1) * 8) * FSTR
                                   + (lane >> 4) * 8) * 2;

    const int nkb = 2 * qb + 2;
    for (int kb = 0; kb < nkb; kb++) {
        if (kb + 1 < nkb) {
            const int st = (kb + 1) & 1;
            const int kbase1 = (kb + 1) * 64;
            #pragma unroll
            for (int j = 0; j < 4; j++) {
                int c = tid + j * 256;
                int row = c >> 4, c8 = c & 15;
                size_t gi = (size_t)(kbase1 + row) * (NKV * HD) + kvh * HD + c8 * 8;
                CP_A16(ksb + st * KSTB + (row * FSTR + c8 * 8) * 2, Kh + gi);
                CP_A16(vsb + st * KSTB + (row * FSTR + c8 * 8) * 2, Vh + gi);
            }
            CP_COMMIT();
            CP_WAIT(1);
        } else {
            CP_WAIT(0);
        }
        __syncthreads();

        const uint32_t so = (kb & 1) * KSTB;
        const int kbase = kb * 64;

        // ---- S = Q K^T : 16 rows x 64 cols per warp
        float s[8][4];
        #pragma unroll
        for (int ni = 0; ni < 8; ni++)
            #pragma unroll
            for (int r = 0; r < 4; r++) s[ni][r] = 0.0f;

        #pragma unroll
        for (int k0 = 0; k0 < HD; k0 += 16) {
            uint32_t aq[4];
            ldsm_x4(aq, qBase + k0 * 2);
            #pragma unroll
            for (int nj = 0; nj < 4; nj++) {
                uint32_t bk[4];
                ldsm_x4(bk, kBase + so + nj * (16 * FSTR * 2) + k0 * 2);
                mma16816(s[2 * nj],     aq, bk[0], bk[1]);
                mma16816(s[2 * nj + 1], aq, bk[2], bk[3]);
            }
        }

        // ---- causal mask
        if (kbase + 63 > qbase + wrow) {
            const int r1 = qbase + wrow + g;
            const int r2 = r1 + 8;
            #pragma unroll
            for (int ni = 0; ni < 8; ni++) {
                int c0 = kbase + ni * 8 + t4 * 2;
                if (c0     > r1) s[ni][0] = -1e30f;
                if (c0 + 1 > r1) s[ni][1] = -1e30f;
                if (c0     > r2) s[ni][2] = -1e30f;
                if (c0 + 1 > r2) s[ni][3] = -1e30f;
            }
        }

        // ---- online softmax (fp32); s becomes P in place
        float mx1 = -INFINITY, mx2 = -INFINITY;
        #pragma unroll
        for (int ni = 0; ni < 8; ni++) {
            mx1 = fmaxf(mx1, fmaxf(s[ni][0], s[ni][1]));
            mx2 = fmaxf(mx2, fmaxf(s[ni][2], s[ni][3]));
        }
        mx1 = fmaxf(mx1, __shfl_xor_sync(0xffffffffu, mx1, 1));
        mx1 = fmaxf(mx1, __shfl_xor_sync(0xffffffffu, mx1, 2));
        mx2 = fmaxf(mx2, __shfl_xor_sync(0xffffffffu, mx2, 1));
        mx2 = fmaxf(mx2, __shfl_xor_sync(0xffffffffu, mx2, 2));

        float mn1 = fmaxf(m1, mx1), mn2 = fmaxf(m2, mx2);
        float sc1 = __expf(m1 - mn1), sc2 = __expf(m2 - mn2);
        m1 = mn1; m2 = mn2;

        float ps1 = 0.0f, ps2 = 0.0f;
        #pragma unroll
        for (int ni = 0; ni < 8; ni++) {
            s[ni][0] = __expf(s[ni][0] - mn1);
            s[ni][1] = __expf(s[ni][1] - mn1);
            s[ni][2] = __expf(s[ni][2] - mn2);
            s[ni][3] = __expf(s[ni][3] - mn2);
            ps1 += s[ni][0] + s[ni][1];
            ps2 += s[ni][2] + s[ni][3];
        }
        ps1 += __shfl_xor_sync(0xffffffffu, ps1, 1);
        ps1 += __shfl_xor_sync(0xffffffffu, ps1, 2);
        ps2 += __shfl_xor_sync(0xffffffffu, ps2, 1);
        ps2 += __shfl_xor_sync(0xffffffffu, ps2, 2);
        l1 = l1 * sc1 + ps1;
        l2 = l2 * sc2 + ps2;

        #pragma unroll
        for (int ni = 0; ni < 16; ni++) {
            o[ni][0] *= sc1; o[ni][1] *= sc1;
            o[ni][2] *= sc2; o[ni][3] *= sc2;
        }

        // ---- O += P V : P from registers, V via ldsm_x4.trans (two n8 per load)
        #pragma unroll
        for (int j = 0; j < 4; j++) {
            uint32_t ap[4];
            ap[0] = pack_h2(s[2 * j][0],     s[2 * j][1]);
            ap[1] = pack_h2(s[2 * j][2],     s[2 * j][3]);
            ap[2] = pack_h2(s[2 * j + 1][0], s[2 * j + 1][1]);
            ap[3] = pack_h2(s[2 * j + 1][2], s[2 * j + 1][3]);
            #pragma unroll
            for (int nj = 0; nj < 8; nj++) {
                uint32_t bv[4];
                ldsm_x4_t(bv, vBase + so + j * (16 * FSTR * 2) + nj * 32);
                mma16816(o[2 * nj],     ap, bv[0], bv[1]);
                mma16816(o[2 * nj + 1], ap, bv[2], bv[3]);
            }
        }
        __syncthreads();
    }

    // ---- epilogue
    const float inv1 = 1.0f / l1;
    const float inv2 = 1.0f / l2;
    const int r1 = qbase + wrow + g;
    #pragma unroll
    for (int ni = 0; ni < 16; ni++) {
        int c = ni * 8 + t4 * 2;
        *(uint32_t*)(Oh + (size_t)r1 * (NQH * HD) + h * HD + c) =
            pack_h2(o[ni][0] * inv1, o[ni][1] * inv1);
        *(uint32_t*)(Oh + (size_t)(r1 + 8) * (NQH * HD) + h * HD + c) =
            pack_h2(o[ni][2] * inv2, o[ni][3] * inv2);
    }
}

// ---------------- launch ----------------
extern "C" void kernel_launch(void* const* d_in, const int* in_sizes, int n_in,
                              void* d_out, int out_size) {
    const float* x    = (const float*)d_in[0];
    const int*   pos  = (const int*)  d_in[1];
    const float* cosT = (const float*)d_in[2];
    const float* sinT = (const float*)d_in[3];
    // d_in[4] = attn_mask — replicated exactly by causal skip
    const float* Wq   = (const float*)d_in[5];
    const float* Wk   = (const float*)d_in[6];
    const float* Wv   = (const float*)d_in[7];
    const float* Wo   = (const float*)d_in[8];
    const float* qw   = (const float*)d_in[9];
    const float* kw   = (const float*)d_in[10];
    float* out = (float*)d_out;

    float *qp, *kp, *vp;
    __half *xh, *qh, *kh, *vh, *oh, *wqT, *wkT, *wvT, *woT;
    cudaGetSymbolAddress((void**)&qp, g_q);
    cudaGetSymbolAddress((void**)&kp, g_k);
    cudaGetSymbolAddress((void**)&vp, g_v);
    cudaGetSymbolAddress((void**)&xh, g_xh);
    cudaGetSymbolAddress((void**)&qh, g_qh);
    cudaGetSymbolAddress((void**)&kh, g_kh);
    cudaGetSymbolAddress((void**)&vh, g_vh);
    cudaGetSymbolAddress((void**)&oh, g_oh);
    cudaGetSymbolAddress((void**)&wqT, g_WqT);
    cudaGetSymbolAddress((void**)&wkT, g_WkT);
    cudaGetSymbolAddress((void**)&wvT, g_WvT);
    cudaGetSymbolAddress((void**)&woT, g_WoT);

    cudaFuncSetAttribute(flash_h,   cudaFuncAttributeMaxDynamicSharedMemorySize, ATTN_SMEM);
    cudaFuncSetAttribute(hgemm_qkv, cudaFuncAttributeMaxDynamicSharedMemorySize, HG_SMEM);
    cudaFuncSetAttribute(hgemm_o,   cudaFuncAttributeMaxDynamicSharedMemorySize, HG_SMEM);

    // pre-pass: fp16 conversions + weight transposes
    cvt_f2h<<<SEQ * HID / 4 / 256, 256>>>(x, xh, SEQ * HID);
    transpose_cvt_h<<<dim3((NQH * HD) / 32, HID / 32), dim3(32, 8)>>>(Wq, wqT, HID, NQH * HD);
    transpose_cvt_h<<<dim3((NKV * HD) / 32, HID / 32), dim3(32, 8)>>>(Wk, wkT, HID, NKV * HD);
    transpose_cvt_h<<<dim3((NKV * HD) / 32, HID / 32), dim3(32, 8)>>>(Wv, wvT, HID, NKV * HD);
    transpose_cvt_h<<<dim3(HID / 32, (NQH * HD) / 32), dim3(32, 8)>>>(Wo, woT, NQH * HD, HID);

    // fused QKV projection (fp16 HMMA, 128x256 tiles)
    hgemm_qkv<<<dim3(24, SEQ / 128), 256, HG_SMEM>>>(xh, wqT, wkT, wvT, qp, kp, vp);

    // RMSNorm + RoPE -> fp16 (q pre-scaled by 128^-0.5); V -> fp16
    rmsnorm_rope_h<<<dim3(SEQ, NQH), 128>>>(qp, qh, qw, cosT, sinT, pos, NQH, 0.08838834764831845f);
    rmsnorm_rope_h<<<dim3(SEQ, NKV), 128>>>(kp, kh, kw, cosT, sinT, pos, NKV, 1.0f);
    cvt_f2h<<<SEQ * NKV * HD / 4 / 256, 256>>>(vp, vh, SEQ * NKV * HD);

    // causal flash attention (fp16 mma, register-resident P)
    flash_h<<<dim3(SEQ / 128, NQH), 256, ATTN_SMEM>>>(qh, kh, vh, oh);

    // output projection
    hgemm_o<<<dim3(HID / 256, SEQ / 128), 256, HG_SMEM>>>(oh, woT, out);
}

// round 8
// speedup vs baseline: 8.1681x; 1.1116x over previous
#include <cuda_runtime.h>
#include <cuda_fp16.h>
#include <math.h>
#include <stdint.h>

#define SEQ 2048
#define HID 4096
#define NQH 32
#define NKV 8
#define HD  128

// ---------------- scratch (no cudaMalloc allowed) ----------------
__device__ float  g_q[SEQ * NQH * HD];
__device__ float  g_k[SEQ * NKV * HD];
__device__ __half g_xh[SEQ * HID];
__device__ __half g_qh[SEQ * NQH * HD];
__device__ __half g_kh[SEQ * NKV * HD];
__device__ __half g_vh[SEQ * NKV * HD];
__device__ __half g_oh[SEQ * NQH * HD];
__device__ __half g_Wqh[HID * (NQH * HD)];   // row-major [K, N] fp16
__device__ __half g_Wkh[HID * (NKV * HD)];
__device__ __half g_Wvh[HID * (NKV * HD)];
__device__ __half g_Woh[(NQH * HD) * HID];

// ---------------- asm helpers ----------------
__device__ __forceinline__ uint32_t smem_u32(const void* p) {
    uint32_t a;
    asm("{ .reg .u64 t; cvta.to.shared.u64 t, %1; cvt.u32.u64 %0, t; }" : "=r"(a) : "l"(p));
    return a;
}
#define CP_A16(dst, src) asm volatile("cp.async.cg.shared.global [%0], [%1], 16;" :: "r"(dst), "l"(src))
#define CP_COMMIT() asm volatile("cp.async.commit_group;")
#define CP_WAIT(n)  asm volatile("cp.async.wait_group %0;" :: "n"(n))

__device__ __forceinline__ void ldsm_x4(uint32_t* r, uint32_t a) {
    asm volatile("ldmatrix.sync.aligned.m8n8.x4.shared.b16 {%0,%1,%2,%3}, [%4];"
                 : "=r"(r[0]), "=r"(r[1]), "=r"(r[2]), "=r"(r[3]) : "r"(a));
}
__device__ __forceinline__ void ldsm_x4_t(uint32_t* r, uint32_t a) {
    asm volatile("ldmatrix.sync.aligned.m8n8.x4.trans.shared.b16 {%0,%1,%2,%3}, [%4];"
                 : "=r"(r[0]), "=r"(r[1]), "=r"(r[2]), "=r"(r[3]) : "r"(a));
}
__device__ __forceinline__ void mma16816(float (&d)[4], const uint32_t (&a)[4], uint32_t b0, uint32_t b1) {
    asm volatile(
        "mma.sync.aligned.m16n8k16.row.col.f32.f16.f16.f32 "
        "{%0,%1,%2,%3}, {%4,%5,%6,%7}, {%8,%9}, {%0,%1,%2,%3};"
        : "+f"(d[0]), "+f"(d[1]), "+f"(d[2]), "+f"(d[3])
        : "r"(a[0]), "r"(a[1]), "r"(a[2]), "r"(a[3]), "r"(b0), "r"(b1));
}
__device__ __forceinline__ uint32_t pack_h2(float lo, float hi) {
    __half2 h = __floats2half2_rn(lo, hi);
    return *(uint32_t*)&h;
}

// ---------------- pre-pass: fp32 -> fp16 streaming cvt ----------------
__global__ __launch_bounds__(256)
void cvt_f2h(const float* __restrict__ in, __half* __restrict__ out, int n) {
    int i = (blockIdx.x * 256 + threadIdx.x) * 4;
    if (i < n) {
        float4 v = *(const float4*)(in + i);
        *(uint2*)(out + i) = make_uint2(pack_h2(v.x, v.y), pack_h2(v.z, v.w));
    }
}

// ---------------- fp16 GEMM: C[M,N] = A[M,K](h,K-major) @ W[K,N](h,row-major) ----------------
// CTA tile 128(M) x 256(N), BK=32, 8 warps (2x4), warp tile 64x64, cp.async 2-stage, dyn smem.
#define HA_STR 40                               // halves per A smem row (32 + 8 pad)
#define HB_STR 264                              // halves per B smem row (256 + 8 pad)
#define HA_ST  (128 * HA_STR * 2)               // 10240 B
#define HB_ST  (32 * HB_STR * 2)                // 16896 B
#define HG_SMEM (2 * HA_ST + 2 * HB_ST)         // 54272 B

template <typename OT>
__device__ __forceinline__
void hgemm_rm(const __half* __restrict__ A, const __half* __restrict__ W,
              OT* __restrict__ C, int Ncols, int K, int bm, int bn) {
    extern __shared__ __align__(16) __half hsm[];
    const uint32_t asb = smem_u32(hsm);                  // A: 2 stages
    const uint32_t bsb = asb + 2 * HA_ST;                // B: 2 stages

    const int tid  = threadIdx.x;
    const int warp = tid >> 5;
    const int lane = tid & 31;
    const int g    = lane >> 2;
    const int t4   = lane & 3;
    const int wm   = warp >> 2;   // 0..1
    const int wn   = warp & 3;    // 0..3

    // A: 128x32 halves = 512 16B-chunks -> 2/thread
    const __half* Asrc[2];
    uint32_t Adst[2];
    #pragma unroll
    for (int j = 0; j < 2; j++) {
        int ch = tid + j * 256;
        int row = ch >> 2, kc = (ch & 3) * 8;
        Asrc[j] = A + (size_t)(bm + row) * K + kc;
        Adst[j] = asb + (row * HA_STR + kc) * 2;
    }
    // B: 32x256 halves = 1024 16B-chunks -> wait, 32*256/8 = 1024 -> 4/thread? no: 1024/256 = 4.
    const __half* Bsrc[4];
    uint32_t Bdst[4];
    #pragma unroll
    for (int j = 0; j < 4; j++) {
        int ch = tid + j * 256;
        int row = ch >> 5, c8 = ch & 31;       // 32 chunks per 256-col row
        Bsrc[j] = W + (size_t)row * Ncols + bn + c8 * 8;
        Bdst[j] = bsb + (row * HB_STR + c8 * 8) * 2;
    }

    // A fragment base (m16k16 non-trans)
    const uint32_t aBase = asb + ((wm * 64 + (lane & 7) + ((lane >> 3) & 1) * 8) * HA_STR
                                  + (lane >> 4) * 8) * 2;
    // B fragment base (k16n16 trans): row k = (lane&7)+((lane>>3)&1)*8 ; col n = (lane>>4)*8
    const uint32_t bBase = bsb + (((lane & 7) + ((lane >> 3) & 1) * 8) * HB_STR
                                  + wn * 64 + (lane >> 4) * 8) * 2;

    float acc[4][8][4];
    #pragma unroll
    for (int mi = 0; mi < 4; mi++)
        #pragma unroll
        for (int ni = 0; ni < 8; ni++)
            #pragma unroll
            for (int r = 0; r < 4; r++) acc[mi][ni][r] = 0.0f;

    const int iters = K >> 5;
    const size_t bAdv = (size_t)32 * Ncols;    // B advance per K-chunk

    // prologue: stage 0
    #pragma unroll
    for (int j = 0; j < 2; j++) CP_A16(Adst[j], Asrc[j]);
    #pragma unroll
    for (int j = 0; j < 4; j++) CP_A16(Bdst[j], Bsrc[j]);
    CP_COMMIT();

    for (int i = 0; i < iters; i++) {
        if (i + 1 < iters) {
            const uint32_t ao = ((i + 1) & 1) * HA_ST;
            const uint32_t bo = ((i + 1) & 1) * HB_ST;
            const int ko = (i + 1) << 5;
            #pragma unroll
            for (int j = 0; j < 2; j++) CP_A16(Adst[j] + ao, Asrc[j] + ko);
            #pragma unroll
            for (int j = 0; j < 4; j++) CP_A16(Bdst[j] + bo, Bsrc[j] + (size_t)(i + 1) * bAdv);
            CP_COMMIT();
            CP_WAIT(1);
        } else {
            CP_WAIT(0);
        }
        __syncthreads();

        const uint32_t ao = (i & 1) * HA_ST;
        const uint32_t bo = (i & 1) * HB_ST;
        #pragma unroll
        for (int kb = 0; kb < 2; kb++) {
            uint32_t af[4][4];
            #pragma unroll
            for (int mi = 0; mi < 4; mi++)
                ldsm_x4(af[mi], aBase + ao + mi * (16 * HA_STR * 2) + kb * 32);
            uint32_t bf[4][4];
            #pragma unroll
            for (int nj = 0; nj < 4; nj++)
                ldsm_x4_t(bf[nj], bBase + bo + kb * (16 * HB_STR * 2) + nj * 32);
            #pragma unroll
            for (int mi = 0; mi < 4; mi++)
                #pragma unroll
                for (int nj = 0; nj < 4; nj++) {
                    mma16816(acc[mi][2 * nj],     af[mi], bf[nj][0], bf[nj][1]);
                    mma16816(acc[mi][2 * nj + 1], af[mi], bf[nj][2], bf[nj][3]);
                }
        }
        __syncthreads();
    }

    #pragma unroll
    for (int mi = 0; mi < 4; mi++) {
        #pragma unroll
        for (int ni = 0; ni < 8; ni++) {
            int r1 = bm + wm * 64 + mi * 16 + g;
            int c  = bn + wn * 64 + ni * 8 + t4 * 2;
            if (sizeof(OT) == 2) {
                __half* Ch = (__half*)C;
                *(uint32_t*)(Ch + (size_t)r1 * Ncols + c)       = pack_h2(acc[mi][ni][0], acc[mi][ni][1]);
                *(uint32_t*)(Ch + (size_t)(r1 + 8) * Ncols + c) = pack_h2(acc[mi][ni][2], acc[mi][ni][3]);
            } else {
                float* Cf = (float*)C;
                *(float2*)(Cf + (size_t)r1 * Ncols + c)       = make_float2(acc[mi][ni][0], acc[mi][ni][1]);
                *(float2*)(Cf + (size_t)(r1 + 8) * Ncols + c) = make_float2(acc[mi][ni][2], acc[mi][ni][3]);
            }
        }
    }
}

// fused QKV: gridDim.x = 24 (0-15: Q->f32, 16-19: K->f32, 20-23: V->f16)
__global__ __launch_bounds__(256, 1)
void hgemm_qkv(const __half* __restrict__ A,
               const __half* __restrict__ Wq, const __half* __restrict__ Wk,
               const __half* __restrict__ Wv,
               float* __restrict__ Cq, float* __restrict__ Ck, __half* __restrict__ Cv) {
    const int bx = blockIdx.x;
    const int bm = blockIdx.y * 128;
    if (bx < 16)      hgemm_rm<float >(A, Wq, Cq, NQH * HD, HID, bm, bx * 256);
    else if (bx < 20) hgemm_rm<float >(A, Wk, Ck, NKV * HD, HID, bm, (bx - 16) * 256);
    else              hgemm_rm<__half>(A, Wv, Cv, NKV * HD, HID, bm, (bx - 20) * 256);
}

__global__ __launch_bounds__(256, 1)
void hgemm_o(const __half* __restrict__ A, const __half* __restrict__ W,
             float* __restrict__ C) {
    hgemm_rm<float>(A, W, C, HID, NQH * HD, blockIdx.y * 128, blockIdx.x * 256);
}

// ---------------- RMSNorm + RoPE (fp32 in, fp16 out) ----------------
__global__ __launch_bounds__(128)
void rmsnorm_rope_h(const float* __restrict__ buf, __half* __restrict__ outh,
                    const float* __restrict__ w,
                    const float* __restrict__ cosT, const float* __restrict__ sinT,
                    const int* __restrict__ pos_ids, int n_heads, float oscale) {
    const int s = blockIdx.x;
    const int h = blockIdx.y;
    const int d = threadIdx.x;

    const float* row = buf + (size_t)s * n_heads * HD + h * HD;
    float v = row[d];

    float ss = v * v;
    #pragma unroll
    for (int off = 16; off > 0; off >>= 1)
        ss += __shfl_xor_sync(0xffffffffu, ss, off);
    __shared__ float wsum[4];
    if ((d & 31) == 0) wsum[d >> 5] = ss;
    __syncthreads();
    float total = wsum[0] + wsum[1] + wsum[2] + wsum[3];
    float inv = rsqrtf(total * (1.0f / HD) + 1e-6f);

    float xn = v * inv * w[d];
    __shared__ float xs[HD];
    xs[d] = xn;
    __syncthreads();

    const int p = pos_ids[s];
    float c  = cosT[(size_t)p * HD + d];
    float sn = sinT[(size_t)p * HD + d];
    float rot = (d < HD / 2) ? -xs[d + HD / 2] : xs[d - HD / 2];
    outh[(size_t)s * n_heads * HD + h * HD + d] = __float2half((xn * c + rot * sn) * oscale);
}

// ---------------- fp16 flash attention (causal, GQA 4:1) ----------------
#define FSTR 136
#define FQ_HALVES (128 * FSTR)
#define FK_HALVES (64 * FSTR)
#define ATTN_SMEM ((FQ_HALVES + 4 * FK_HALVES) * 2)

__global__ __launch_bounds__(256, 1)
void flash_h(const __half* __restrict__ Qh, const __half* __restrict__ Kh,
             const __half* __restrict__ Vh, __half* __restrict__ Oh) {
    extern __shared__ __align__(16) __half fsm[];
    __half* Qs = fsm;
    __half* Ks = fsm + FQ_HALVES;
    __half* Vs = Ks + 2 * FK_HALVES;

    const int tid  = threadIdx.x;
    const int warp = tid >> 5;
    const int lane = tid & 31;
    const int g    = lane >> 2;
    const int t4   = lane & 3;
    const int wrow = warp * 16;

    const int qb    = blockIdx.x;
    const int h     = blockIdx.y;
    const int kvh   = h >> 2;
    const int qbase = qb * 128;

    const uint32_t qsb = smem_u32(Qs);
    const uint32_t ksb = smem_u32(Ks);
    const uint32_t vsb = smem_u32(Vs);
    const uint32_t KSTB = FK_HALVES * 2;

    // Q + KV tile 0
    {
        #pragma unroll
        for (int j = 0; j < 8; j++) {
            int c = tid + j * 256;
            int row = c >> 4, c8 = c & 15;
            CP_A16(qsb + (row * FSTR + c8 * 8) * 2,
                   Qh + (size_t)(qbase + row) * (NQH * HD) + h * HD + c8 * 8);
        }
        #pragma unroll
        for (int j = 0; j < 4; j++) {
            int c = tid + j * 256;
            int row = c >> 4, c8 = c & 15;
            size_t gi = (size_t)row * (NKV * HD) + kvh * HD + c8 * 8;
            CP_A16(ksb + (row * FSTR + c8 * 8) * 2, Kh + gi);
            CP_A16(vsb + (row * FSTR + c8 * 8) * 2, Vh + gi);
        }
        CP_COMMIT();
    }

    float o[16][4];
    #pragma unroll
    for (int ni = 0; ni < 16; ni++)
        #pragma unroll
        for (int r = 0; r < 4; r++) o[ni][r] = 0.0f;
    float m1 = -INFINITY, m2 = -INFINITY, l1 = 0.0f, l2 = 0.0f;

    const uint32_t qBase = qsb + ((wrow + (lane & 7) + ((lane >> 3) & 1) * 8) * FSTR
                                   + (lane >> 4) * 8) * 2;
    const uint32_t kBase = ksb + (((lane & 7) + (lane >> 4) * 8) * FSTR
                                   + ((lane >> 3) & 1) * 8) * 2;
    const uint32_t vBase = vsb + (((lane & 7) + ((lane >> 3) & 1) * 8) * FSTR
                                   + (lane >> 4) * 8) * 2;

    const int nkb = 2 * qb + 2;
    for (int kb = 0; kb < nkb; kb++) {
        if (kb + 1 < nkb) {
            const int st = (kb + 1) & 1;
            const int kbase1 = (kb + 1) * 64;
            #pragma unroll
            for (int j = 0; j < 4; j++) {
                int c = tid + j * 256;
                int row = c >> 4, c8 = c & 15;
                size_t gi = (size_t)(kbase1 + row) * (NKV * HD) + kvh * HD + c8 * 8;
                CP_A16(ksb + st * KSTB + (row * FSTR + c8 * 8) * 2, Kh + gi);
                CP_A16(vsb + st * KSTB + (row * FSTR + c8 * 8) * 2, Vh + gi);
            }
            CP_COMMIT();
            CP_WAIT(1);
        } else {
            CP_WAIT(0);
        }
        __syncthreads();

        const uint32_t so = (kb & 1) * KSTB;
        const int kbase = kb * 64;

        // ---- S = Q K^T
        float s[8][4];
        #pragma unroll
        for (int ni = 0; ni < 8; ni++)
            #pragma unroll
            for (int r = 0; r < 4; r++) s[ni][r] = 0.0f;

        #pragma unroll
        for (int k0 = 0; k0 < HD; k0 += 16) {
            uint32_t aq[4];
            ldsm_x4(aq, qBase + k0 * 2);
            #pragma unroll
            for (int nj = 0; nj < 4; nj++) {
                uint32_t bk[4];
                ldsm_x4(bk, kBase + so + nj * (16 * FSTR * 2) + k0 * 2);
                mma16816(s[2 * nj],     aq, bk[0], bk[1]);
                mma16816(s[2 * nj + 1], aq, bk[2], bk[3]);
            }
        }

        // ---- causal mask
        if (kbase + 63 > qbase + wrow) {
            const int r1 = qbase + wrow + g;
            const int r2 = r1 + 8;
            #pragma unroll
            for (int ni = 0; ni < 8; ni++) {
                int c0 = kbase + ni * 8 + t4 * 2;
                if (c0     > r1) s[ni][0] = -1e30f;
                if (c0 + 1 > r1) s[ni][1] = -1e30f;
                if (c0     > r2) s[ni][2] = -1e30f;
                if (c0 + 1 > r2) s[ni][3] = -1e30f;
            }
        }

        // ---- online softmax
        float mx1 = -INFINITY, mx2 = -INFINITY;
        #pragma unroll
        for (int ni = 0; ni < 8; ni++) {
            mx1 = fmaxf(mx1, fmaxf(s[ni][0], s[ni][1]));
            mx2 = fmaxf(mx2, fmaxf(s[ni][2], s[ni][3]));
        }
        mx1 = fmaxf(mx1, __shfl_xor_sync(0xffffffffu, mx1, 1));
        mx1 = fmaxf(mx1, __shfl_xor_sync(0xffffffffu, mx1, 2));
        mx2 = fmaxf(mx2, __shfl_xor_sync(0xffffffffu, mx2, 1));
        mx2 = fmaxf(mx2, __shfl_xor_sync(0xffffffffu, mx2, 2));

        float mn1 = fmaxf(m1, mx1), mn2 = fmaxf(m2, mx2);
        float sc1 = __expf(m1 - mn1), sc2 = __expf(m2 - mn2);
        m1 = mn1; m2 = mn2;

        float ps1 = 0.0f, ps2 = 0.0f;
        #pragma unroll
        for (int ni = 0; ni < 8; ni++) {
            s[ni][0] = __expf(s[ni][0] - mn1);
            s[ni][1] = __expf(s[ni][1] - mn1);
            s[ni][2] = __expf(s[ni][2] - mn2);
            s[ni][3] = __expf(s[ni][3] - mn2);
            ps1 += s[ni][0] + s[ni][1];
            ps2 += s[ni][2] + s[ni][3];
        }
        ps1 += __shfl_xor_sync(0xffffffffu, ps1, 1);
        ps1 += __shfl_xor_sync(0xffffffffu, ps1, 2);
        ps2 += __shfl_xor_sync(0xffffffffu, ps2, 1);
        ps2 += __shfl_xor_sync(0xffffffffu, ps2, 2);
        l1 = l1 * sc1 + ps1;
        l2 = l2 * sc2 + ps2;

        #pragma unroll
        for (int ni = 0; ni < 16; ni++) {
            o[ni][0] *= sc1; o[ni][1] *= sc1;
            o[ni][2] *= sc2; o[ni][3] *= sc2;
        }

        // ---- O += P V
        #pragma unroll
        for (int j = 0; j < 4; j++) {
            uint32_t ap[4];
            ap[0] = pack_h2(s[2 * j][0],     s[2 * j][1]);
            ap[1] = pack_h2(s[2 * j][2],     s[2 * j][3]);
            ap[2] = pack_h2(s[2 * j + 1][0], s[2 * j + 1][1]);
            ap[3] = pack_h2(s[2 * j + 1][2], s[2 * j + 1][3]);
            #pragma unroll
            for (int nj = 0; nj < 8; nj++) {
                uint32_t bv[4];
                ldsm_x4_t(bv, vBase + so + j * (16 * FSTR * 2) + nj * 32);
                mma16816(o[2 * nj],     ap, bv[0], bv[1]);
                mma16816(o[2 * nj + 1], ap, bv[2], bv[3]);
            }
        }
        __syncthreads();
    }

    // ---- epilogue
    const float inv1 = 1.0f / l1;
    const float inv2 = 1.0f / l2;
    const int r1 = qbase + wrow + g;
    #pragma unroll
    for (int ni = 0; ni < 16; ni++) {
        int c = ni * 8 + t4 * 2;
        *(uint32_t*)(Oh + (size_t)r1 * (NQH * HD) + h * HD + c) =
            pack_h2(o[ni][0] * inv1, o[ni][1] * inv1);
        *(uint32_t*)(Oh + (size_t)(r1 + 8) * (NQH * HD) + h * HD + c) =
            pack_h2(o[ni][2] * inv2, o[ni][3] * inv2);
    }
}

// ---------------- launch ----------------
extern "C" void kernel_launch(void* const* d_in, const int* in_sizes, int n_in,
                              void* d_out, int out_size) {
    const float* x    = (const float*)d_in[0];
    const int*   pos  = (const int*)  d_in[1];
    const float* cosT = (const float*)d_in[2];
    const float* sinT = (const float*)d_in[3];
    // d_in[4] = attn_mask — replicated exactly by causal skip
    const float* Wq   = (const float*)d_in[5];
    const float* Wk   = (const float*)d_in[6];
    const float* Wv   = (const float*)d_in[7];
    const float* Wo   = (const float*)d_in[8];
    const float* qw   = (const float*)d_in[9];
    const float* kw   = (const float*)d_in[10];
    float* out = (float*)d_out;

    float *qp, *kp;
    __half *xh, *qh, *kh, *vh, *oh, *wqh, *wkh, *wvh, *woh;
    cudaGetSymbolAddress((void**)&qp, g_q);
    cudaGetSymbolAddress((void**)&kp, g_k);
    cudaGetSymbolAddress((void**)&xh, g_xh);
    cudaGetSymbolAddress((void**)&qh, g_qh);
    cudaGetSymbolAddress((void**)&kh, g_kh);
    cudaGetSymbolAddress((void**)&vh, g_vh);
    cudaGetSymbolAddress((void**)&oh, g_oh);
    cudaGetSymbolAddress((void**)&wqh, g_Wqh);
    cudaGetSymbolAddress((void**)&wkh, g_Wkh);
    cudaGetSymbolAddress((void**)&wvh, g_Wvh);
    cudaGetSymbolAddress((void**)&woh, g_Woh);

    cudaFuncSetAttribute(flash_h,   cudaFuncAttributeMaxDynamicSharedMemorySize, ATTN_SMEM);
    cudaFuncSetAttribute(hgemm_qkv, cudaFuncAttributeMaxDynamicSharedMemorySize, HG_SMEM);
    cudaFuncSetAttribute(hgemm_o,   cudaFuncAttributeMaxDynamicSharedMemorySize, HG_SMEM);

    // pre-pass: streaming fp32 -> fp16 (no transposes)
    cvt_f2h<<<SEQ * HID / 4 / 256, 256>>>(x, xh, SEQ * HID);
    cvt_f2h<<<HID * (NQH * HD) / 4 / 256, 256>>>(Wq, wqh, HID * NQH * HD);
    cvt_f2h<<<HID * (NKV * HD) / 4 / 256, 256>>>(Wk, wkh, HID * NKV * HD);
    cvt_f2h<<<HID * (NKV * HD) / 4 / 256, 256>>>(Wv, wvh, HID * NKV * HD);
    cvt_f2h<<<(NQH * HD) * HID / 4 / 256, 256>>>(Wo, woh, NQH * HD * HID);

    // fused QKV projection (row-major weights; V written directly as fp16)
    hgemm_qkv<<<dim3(24, SEQ / 128), 256, HG_SMEM>>>(xh, wqh, wkh, wvh, qp, kp, vh);

    // RMSNorm + RoPE -> fp16 (q pre-scaled by 128^-0.5)
    rmsnorm_rope_h<<<dim3(SEQ, NQH), 128>>>(qp, qh, qw, cosT, sinT, pos, NQH, 0.08838834764831845f);
    rmsnorm_rope_h<<<dim3(SEQ, NKV), 128>>>(kp, kh, kw, cosT, sinT, pos, NKV, 1.0f);

    // causal flash attention
    flash_h<<<dim3(SEQ / 128, NQH), 256, ATTN_SMEM>>>(qh, kh, vh, oh);

    // output projection
    hgemm_o<<<dim3(HID / 256, SEQ / 128), 256, HG_SMEM>>>(oh, woh, out);
}

// round 9
// speedup vs baseline: 8.5939x; 1.0521x over previous
#include <cuda_runtime.h>
#include <cuda_fp16.h>
#include <math.h>
#include <stdint.h>

#define SEQ 2048
#define HID 4096
#define NQH 32
#define NKV 8
#define HD  128

// ---------------- scratch (no cudaMalloc allowed) ----------------
__device__ float  g_q[SEQ * NQH * HD];
__device__ float  g_k[SEQ * NKV * HD];
__device__ __half g_xh[SEQ * HID];
__device__ __half g_qh[SEQ * NQH * HD];
__device__ __half g_kh[SEQ * NKV * HD];
__device__ __half g_vh[SEQ * NKV * HD];
__device__ __half g_oh[SEQ * NQH * HD];
__device__ __half g_Wqh[HID * (NQH * HD)];   // row-major [K, N] fp16
__device__ __half g_Wkh[HID * (NKV * HD)];
__device__ __half g_Wvh[HID * (NKV * HD)];
__device__ __half g_Woh[(NQH * HD) * HID];

// ---------------- asm helpers ----------------
__device__ __forceinline__ uint32_t smem_u32(const void* p) {
    uint32_t a;
    asm("{ .reg .u64 t; cvta.to.shared.u64 t, %1; cvt.u32.u64 %0, t; }" : "=r"(a) : "l"(p));
    return a;
}
#define CP_A16(dst, src) asm volatile("cp.async.cg.shared.global [%0], [%1], 16;" :: "r"(dst), "l"(src))
#define CP_COMMIT() asm volatile("cp.async.commit_group;")
#define CP_WAIT(n)  asm volatile("cp.async.wait_group %0;" :: "n"(n))

__device__ __forceinline__ void ldsm_x4(uint32_t* r, uint32_t a) {
    asm volatile("ldmatrix.sync.aligned.m8n8.x4.shared.b16 {%0,%1,%2,%3}, [%4];"
                 : "=r"(r[0]), "=r"(r[1]), "=r"(r[2]), "=r"(r[3]) : "r"(a));
}
__device__ __forceinline__ void ldsm_x4_t(uint32_t* r, uint32_t a) {
    asm volatile("ldmatrix.sync.aligned.m8n8.x4.trans.shared.b16 {%0,%1,%2,%3}, [%4];"
                 : "=r"(r[0]), "=r"(r[1]), "=r"(r[2]), "=r"(r[3]) : "r"(a));
}
__device__ __forceinline__ void mma16816(float (&d)[4], const uint32_t (&a)[4], uint32_t b0, uint32_t b1) {
    asm volatile(
        "mma.sync.aligned.m16n8k16.row.col.f32.f16.f16.f32 "
        "{%0,%1,%2,%3}, {%4,%5,%6,%7}, {%8,%9}, {%0,%1,%2,%3};"
        : "+f"(d[0]), "+f"(d[1]), "+f"(d[2]), "+f"(d[3])
        : "r"(a[0]), "r"(a[1]), "r"(a[2]), "r"(a[3]), "r"(b0), "r"(b1));
}
__device__ __forceinline__ uint32_t pack_h2(float lo, float hi) {
    __half2 h = __floats2half2_rn(lo, hi);
    return *(uint32_t*)&h;
}

// ---------------- pre-pass: fp32 -> fp16 streaming cvt ----------------
__global__ __launch_bounds__(256)
void cvt_f2h(const float* __restrict__ in, __half* __restrict__ out, int n) {
    int i = (blockIdx.x * 256 + threadIdx.x) * 4;
    if (i < n) {
        float4 v = *(const float4*)(in + i);
        *(uint2*)(out + i) = make_uint2(pack_h2(v.x, v.y), pack_h2(v.z, v.w));
    }
}

// ---------------- fp16 GEMM: C[M,N] = A[M,K](h,K-major) @ W[K,N](h,row-major) ----------------
// CTA tile 128(M) x 256(N), BK=32, 8 warps (2x4), warp tile 64x64.
// 4-stage cp.async ring, issue-ahead 2, ONE __syncthreads per iteration.
#define HA_STR 40                               // halves per A smem row (32 + 8 pad)
#define HB_STR 264                              // halves per B smem row (256 + 8 pad)
#define HA_ST  (128 * HA_STR * 2)               // 10240 B
#define HB_ST  (32 * HB_STR * 2)                // 16896 B
#define HG_SMEM (4 * (HA_ST + HB_ST))           // 108544 B

template <typename OT>
__device__ __forceinline__
void hgemm_rm(const __half* __restrict__ A, const __half* __restrict__ W,
              OT* __restrict__ C, int Ncols, int K, int bm, int bn) {
    extern __shared__ __align__(16) __half hsm[];
    const uint32_t asb = smem_u32(hsm);                  // A: 4 stages
    const uint32_t bsb = asb + 4 * HA_ST;                // B: 4 stages

    const int tid  = threadIdx.x;
    const int warp = tid >> 5;
    const int lane = tid & 31;
    const int g    = lane >> 2;
    const int t4   = lane & 3;
    const int wm   = warp >> 2;   // 0..1
    const int wn   = warp & 3;    // 0..3

    // A: 128x32 halves = 512 16B-chunks -> 2/thread
    const __half* Asrc[2];
    uint32_t Adst[2];
    #pragma unroll
    for (int j = 0; j < 2; j++) {
        int ch = tid + j * 256;
        int row = ch >> 2, kc = (ch & 3) * 8;
        Asrc[j] = A + (size_t)(bm + row) * K + kc;
        Adst[j] = asb + (row * HA_STR + kc) * 2;
    }
    // B: 32x256 halves = 1024 16B-chunks -> 4/thread
    const __half* Bsrc[4];
    uint32_t Bdst[4];
    #pragma unroll
    for (int j = 0; j < 4; j++) {
        int ch = tid + j * 256;
        int row = ch >> 5, c8 = ch & 31;
        Bsrc[j] = W + (size_t)row * Ncols + bn + c8 * 8;
        Bdst[j] = bsb + (row * HB_STR + c8 * 8) * 2;
    }

    const uint32_t aBase = asb + ((wm * 64 + (lane & 7) + ((lane >> 3) & 1) * 8) * HA_STR
                                  + (lane >> 4) * 8) * 2;
    const uint32_t bBase = bsb + (((lane & 7) + ((lane >> 3) & 1) * 8) * HB_STR
                                  + wn * 64 + (lane >> 4) * 8) * 2;

    float acc[4][8][4];
    #pragma unroll
    for (int mi = 0; mi < 4; mi++)
        #pragma unroll
        for (int ni = 0; ni < 8; ni++)
            #pragma unroll
            for (int r = 0; r < 4; r++) acc[mi][ni][r] = 0.0f;

    const int iters = K >> 5;
    const size_t bAdv = (size_t)32 * Ncols;

    // prologue: stages 0, 1
    #pragma unroll
    for (int j = 0; j < 2; j++) CP_A16(Adst[j], Asrc[j]);
    #pragma unroll
    for (int j = 0; j < 4; j++) CP_A16(Bdst[j], Bsrc[j]);
    CP_COMMIT();
    {
        const uint32_t ao = HA_ST, bo = HB_ST;
        #pragma unroll
        for (int j = 0; j < 2; j++) CP_A16(Adst[j] + ao, Asrc[j] + 32);
        #pragma unroll
        for (int j = 0; j < 4; j++) CP_A16(Bdst[j] + bo, Bsrc[j] + bAdv);
        CP_COMMIT();
    }

    for (int i = 0; i < iters; i++) {
        if (i + 2 < iters) {
            const uint32_t ao = ((i + 2) & 3) * HA_ST;
            const uint32_t bo = ((i + 2) & 3) * HB_ST;
            const int ko = (i + 2) << 5;
            #pragma unroll
            for (int j = 0; j < 2; j++) CP_A16(Adst[j] + ao, Asrc[j] + ko);
            #pragma unroll
            for (int j = 0; j < 4; j++) CP_A16(Bdst[j] + bo, Bsrc[j] + (size_t)(i + 2) * bAdv);
            CP_COMMIT();
            CP_WAIT(2);
        } else if (i + 1 < iters) {
            CP_WAIT(1);
        } else {
            CP_WAIT(0);
        }
        __syncthreads();   // single barrier per iter (4-stage ring makes end-barrier redundant)

        const uint32_t ao = (i & 3) * HA_ST;
        const uint32_t bo = (i & 3) * HB_ST;
        #pragma unroll
        for (int kb = 0; kb < 2; kb++) {
            uint32_t af[4][4];
            #pragma unroll
            for (int mi = 0; mi < 4; mi++)
                ldsm_x4(af[mi], aBase + ao + mi * (16 * HA_STR * 2) + kb * 32);
            uint32_t bf[4][4];
            #pragma unroll
            for (int nj = 0; nj < 4; nj++)
                ldsm_x4_t(bf[nj], bBase + bo + kb * (16 * HB_STR * 2) + nj * 32);
            #pragma unroll
            for (int mi = 0; mi < 4; mi++)
                #pragma unroll
                for (int nj = 0; nj < 4; nj++) {
                    mma16816(acc[mi][2 * nj],     af[mi], bf[nj][0], bf[nj][1]);
                    mma16816(acc[mi][2 * nj + 1], af[mi], bf[nj][2], bf[nj][3]);
                }
        }
    }

    #pragma unroll
    for (int mi = 0; mi < 4; mi++) {
        #pragma unroll
        for (int ni = 0; ni < 8; ni++) {
            int r1 = bm + wm * 64 + mi * 16 + g;
            int c  = bn + wn * 64 + ni * 8 + t4 * 2;
            if (sizeof(OT) == 2) {
                __half* Ch = (__half*)C;
                *(uint32_t*)(Ch + (size_t)r1 * Ncols + c)       = pack_h2(acc[mi][ni][0], acc[mi][ni][1]);
                *(uint32_t*)(Ch + (size_t)(r1 + 8) * Ncols + c) = pack_h2(acc[mi][ni][2], acc[mi][ni][3]);
            } else {
                float* Cf = (float*)C;
                *(float2*)(Cf + (size_t)r1 * Ncols + c)       = make_float2(acc[mi][ni][0], acc[mi][ni][1]);
                *(float2*)(Cf + (size_t)(r1 + 8) * Ncols + c) = make_float2(acc[mi][ni][2], acc[mi][ni][3]);
            }
        }
    }
}

// fused QKV: gridDim.x = 24 (0-15: Q->f32, 16-19: K->f32, 20-23: V->f16)
__global__ __launch_bounds__(256, 1)
void hgemm_qkv(const __half* __restrict__ A,
               const __half* __restrict__ Wq, const __half* __restrict__ Wk,
               const __half* __restrict__ Wv,
               float* __restrict__ Cq, float* __restrict__ Ck, __half* __restrict__ Cv) {
    const int bx = blockIdx.x;
    const int bm = blockIdx.y * 128;
    if (bx < 16)      hgemm_rm<float >(A, Wq, Cq, NQH * HD, HID, bm, bx * 256);
    else if (bx < 20) hgemm_rm<float >(A, Wk, Ck, NKV * HD, HID, bm, (bx - 16) * 256);
    else              hgemm_rm<__half>(A, Wv, Cv, NKV * HD, HID, bm, (bx - 20) * 256);
}

__global__ __launch_bounds__(256, 1)
void hgemm_o(const __half* __restrict__ A, const __half* __restrict__ W,
             float* __restrict__ C) {
    hgemm_rm<float>(A, W, C, HID, NQH * HD, blockIdx.y * 128, blockIdx.x * 256);
}

// ---------------- RMSNorm + RoPE (fp32 in, fp16 out) ----------------
__global__ __launch_bounds__(128)
void rmsnorm_rope_h(const float* __restrict__ buf, __half* __restrict__ outh,
                    const float* __restrict__ w,
                    const float* __restrict__ cosT, const float* __restrict__ sinT,
                    const int* __restrict__ pos_ids, int n_heads, float oscale) {
    const int s = blockIdx.x;
    const int h = blockIdx.y;
    const int d = threadIdx.x;

    const float* row = buf + (size_t)s * n_heads * HD + h * HD;
    float v = row[d];

    float ss = v * v;
    #pragma unroll
    for (int off = 16; off > 0; off >>= 1)
        ss += __shfl_xor_sync(0xffffffffu, ss, off);
    __shared__ float wsum[4];
    if ((d & 31) == 0) wsum[d >> 5] = ss;
    __syncthreads();
    float total = wsum[0] + wsum[1] + wsum[2] + wsum[3];
    float inv = rsqrtf(total * (1.0f / HD) + 1e-6f);

    float xn = v * inv * w[d];
    __shared__ float xs[HD];
    xs[d] = xn;
    __syncthreads();

    const int p = pos_ids[s];
    float c  = cosT[(size_t)p * HD + d];
    float sn = sinT[(size_t)p * HD + d];
    float rot = (d < HD / 2) ? -xs[d + HD / 2] : xs[d - HD / 2];
    outh[(size_t)s * n_heads * HD + h * HD + d] = __float2half((xn * c + rot * sn) * oscale);
}

// ---------------- fp16 flash attention (causal, GQA 4:1) ----------------
#define FSTR 136
#define FQ_HALVES (128 * FSTR)
#define FK_HALVES (64 * FSTR)
#define ATTN_SMEM ((FQ_HALVES + 4 * FK_HALVES) * 2)

__global__ __launch_bounds__(256, 1)
void flash_h(const __half* __restrict__ Qh, const __half* __restrict__ Kh,
             const __half* __restrict__ Vh, __half* __restrict__ Oh) {
    extern __shared__ __align__(16) __half fsm[];
    __half* Qs = fsm;
    __half* Ks = fsm + FQ_HALVES;
    __half* Vs = Ks + 2 * FK_HALVES;

    const int tid  = threadIdx.x;
    const int warp = tid >> 5;
    const int lane = tid & 31;
    const int g    = lane >> 2;
    const int t4   = lane & 3;
    const int wrow = warp * 16;

    const int qb    = gridDim.x - 1 - blockIdx.x;   // heavy blocks first
    const int h     = blockIdx.y;
    const int kvh   = h >> 2;
    const int qbase = qb * 128;

    const uint32_t qsb = smem_u32(Qs);
    const uint32_t ksb = smem_u32(Ks);
    const uint32_t vsb = smem_u32(Vs);
    const uint32_t KSTB = FK_HALVES * 2;

    // Q + KV tile 0
    {
        #pragma unroll
        for (int j = 0; j < 8; j++) {
            int c = tid + j * 256;
            int row = c >> 4, c8 = c & 15;
            CP_A16(qsb + (row * FSTR + c8 * 8) * 2,
                   Qh + (size_t)(qbase + row) * (NQH * HD) + h * HD + c8 * 8);
        }
        #pragma unroll
        for (int j = 0; j < 4; j++) {
            int c = tid + j * 256;
            int row = c >> 4, c8 = c & 15;
            size_t gi = (size_t)row * (NKV * HD) + kvh * HD + c8 * 8;
            CP_A16(ksb + (row * FSTR + c8 * 8) * 2, Kh + gi);
            CP_A16(vsb + (row * FSTR + c8 * 8) * 2, Vh + gi);
        }
        CP_COMMIT();
    }

    float o[16][4];
    #pragma unroll
    for (int ni = 0; ni < 16; ni++)
        #pragma unroll
        for (int r = 0; r < 4; r++) o[ni][r] = 0.0f;
    float m1 = -INFINITY, m2 = -INFINITY, l1 = 0.0f, l2 = 0.0f;

    const uint32_t qBase = qsb + ((wrow + (lane & 7) + ((lane >> 3) & 1) * 8) * FSTR
                                   + (lane >> 4) * 8) * 2;
    const uint32_t kBase = ksb + (((lane & 7) + (lane >> 4) * 8) * FSTR
                                   + ((lane >> 3) & 1) * 8) * 2;
    const uint32_t vBase = vsb + (((lane & 7) + ((lane >> 3) & 1) * 8) * FSTR
                                   + (lane >> 4) * 8) * 2;

    const int nkb = 2 * qb + 2;
    for (int kb = 0; kb < nkb; kb++) {
        if (kb + 1 < nkb) {
            const int st = (kb + 1) & 1;
            const int kbase1 = (kb + 1) * 64;
            #pragma unroll
            for (int j = 0; j < 4; j++) {
                int c = tid + j * 256;
                int row = c >> 4, c8 = c & 15;
                size_t gi = (size_t)(kbase1 + row) * (NKV * HD) + kvh * HD + c8 * 8;
                CP_A16(ksb + st * KSTB + (row * FSTR + c8 * 8) * 2, Kh + gi);
                CP_A16(vsb + st * KSTB + (row * FSTR + c8 * 8) * 2, Vh + gi);
            }
            CP_COMMIT();
            CP_WAIT(1);
        } else {
            CP_WAIT(0);
        }
        __syncthreads();

        const uint32_t so = (kb & 1) * KSTB;
        const int kbase = kb * 64;

        // ---- S = Q K^T
        float s[8][4];
        #pragma unroll
        for (int ni = 0; ni < 8; ni++)
            #pragma unroll
            for (int r = 0; r < 4; r++) s[ni][r] = 0.0f;

        #pragma unroll
        for (int k0 = 0; k0 < HD; k0 += 16) {
            uint32_t aq[4];
            ldsm_x4(aq, qBase + k0 * 2);
            #pragma unroll
            for (int nj = 0; nj < 4; nj++) {
                uint32_t bk[4];
                ldsm_x4(bk, kBase + so + nj * (16 * FSTR * 2) + k0 * 2);
                mma16816(s[2 * nj],     aq, bk[0], bk[1]);
                mma16816(s[2 * nj + 1], aq, bk[2], bk[3]);
            }
        }

        // ---- causal mask
        if (kbase + 63 > qbase + wrow) {
            const int r1 = qbase + wrow + g;
            const int r2 = r1 + 8;
            #pragma unroll
            for (int ni = 0; ni < 8; ni++) {
                int c0 = kbase + ni * 8 + t4 * 2;
                if (c0     > r1) s[ni][0] = -1e30f;
                if (c0 + 1 > r1) s[ni][1] = -1e30f;
                if (c0     > r2) s[ni][2] = -1e30f;
                if (c0 + 1 > r2) s[ni][3] = -1e30f;
            }
        }

        // ---- online softmax
        float mx1 = -INFINITY, mx2 = -INFINITY;
        #pragma unroll
        for (int ni = 0; ni < 8; ni++) {
            mx1 = fmaxf(mx1, fmaxf(s[ni][0], s[ni][1]));
            mx2 = fmaxf(mx2, fmaxf(s[ni][2], s[ni][3]));
        }
        mx1 = fmaxf(mx1, __shfl_xor_sync(0xffffffffu, mx1, 1));
        mx1 = fmaxf(mx1, __shfl_xor_sync(0xffffffffu, mx1, 2));
        mx2 = fmaxf(mx2, __shfl_xor_sync(0xffffffffu, mx2, 1));
        mx2 = fmaxf(mx2, __shfl_xor_sync(0xffffffffu, mx2, 2));

        float mn1 = fmaxf(m1, mx1), mn2 = fmaxf(m2, mx2);
        float sc1 = __expf(m1 - mn1), sc2 = __expf(m2 - mn2);
        m1 = mn1; m2 = mn2;

        float ps1 = 0.0f, ps2 = 0.0f;
        #pragma unroll
        for (int ni = 0; ni < 8; ni++) {
            s[ni][0] = __expf(s[ni][0] - mn1);
            s[ni][1] = __expf(s[ni][1] - mn1);
            s[ni][2] = __expf(s[ni][2] - mn2);
            s[ni][3] = __expf(s[ni][3] - mn2);
            ps1 += s[ni][0] + s[ni][1];
            ps2 += s[ni][2] + s[ni][3];
        }
        ps1 += __shfl_xor_sync(0xffffffffu, ps1, 1);
        ps1 += __shfl_xor_sync(0xffffffffu, ps1, 2);
        ps2 += __shfl_xor_sync(0xffffffffu, ps2, 1);
        ps2 += __shfl_xor_sync(0xffffffffu, ps2, 2);
        l1 = l1 * sc1 + ps1;
        l2 = l2 * sc2 + ps2;

        #pragma unroll
        for (int ni = 0; ni < 16; ni++) {
            o[ni][0] *= sc1; o[ni][1] *= sc1;
            o[ni][2] *= sc2; o[ni][3] *= sc2;
        }

        // ---- O += P V
        #pragma unroll
        for (int j = 0; j < 4; j++) {
            uint32_t ap[4];
            ap[0] = pack_h2(s[2 * j][0],     s[2 * j][1]);
            ap[1] = pack_h2(s[2 * j][2],     s[2 * j][3]);
            ap[2] = pack_h2(s[2 * j + 1][0], s[2 * j + 1][1]);
            ap[3] = pack_h2(s[2 * j + 1][2], s[2 * j + 1][3]);
            #pragma unroll
            for (int nj = 0; nj < 8; nj++) {
                uint32_t bv[4];
                ldsm_x4_t(bv, vBase + so + j * (16 * FSTR * 2) + nj * 32);
                mma16816(o[2 * nj],     ap, bv[0], bv[1]);
                mma16816(o[2 * nj + 1], ap, bv[2], bv[3]);
            }
        }
        __syncthreads();
    }

    // ---- epilogue
    const float inv1 = 1.0f / l1;
    const float inv2 = 1.0f / l2;
    const int r1 = qbase + wrow + g;
    #pragma unroll
    for (int ni = 0; ni < 16; ni++) {
        int c = ni * 8 + t4 * 2;
        *(uint32_t*)(Oh + (size_t)r1 * (NQH * HD) + h * HD + c) =
            pack_h2(o[ni][0] * inv1, o[ni][1] * inv1);
        *(uint32_t*)(Oh + (size_t)(r1 + 8) * (NQH * HD) + h * HD + c) =
            pack_h2(o[ni][2] * inv2, o[ni][3] * inv2);
    }
}

// ---------------- launch ----------------
extern "C" void kernel_launch(void* const* d_in, const int* in_sizes, int n_in,
                              void* d_out, int out_size) {
    const float* x    = (const float*)d_in[0];
    const int*   pos  = (const int*)  d_in[1];
    const float* cosT = (const float*)d_in[2];
    const float* sinT = (const float*)d_in[3];
    // d_in[4] = attn_mask — replicated exactly by causal skip
    const float* Wq   = (const float*)d_in[5];
    const float* Wk   = (const float*)d_in[6];
    const float* Wv   = (const float*)d_in[7];
    const float* Wo   = (const float*)d_in[8];
    const float* qw   = (const float*)d_in[9];
    const float* kw   = (const float*)d_in[10];
    float* out = (float*)d_out;

    float *qp, *kp;
    __half *xh, *qh, *kh, *vh, *oh, *wqh, *wkh, *wvh, *woh;
    cudaGetSymbolAddress((void**)&qp, g_q);
    cudaGetSymbolAddress((void**)&kp, g_k);
    cudaGetSymbolAddress((void**)&xh, g_xh);
    cudaGetSymbolAddress((void**)&qh, g_qh);
    cudaGetSymbolAddress((void**)&kh, g_kh);
    cudaGetSymbolAddress((void**)&vh, g_vh);
    cudaGetSymbolAddress((void**)&oh, g_oh);
    cudaGetSymbolAddress((void**)&wqh, g_Wqh);
    cudaGetSymbolAddress((void**)&wkh, g_Wkh);
    cudaGetSymbolAddress((void**)&wvh, g_Wvh);
    cudaGetSymbolAddress((void**)&woh, g_Woh);

    cudaFuncSetAttribute(flash_h,   cudaFuncAttributeMaxDynamicSharedMemorySize, ATTN_SMEM);
    cudaFuncSetAttribute(hgemm_qkv, cudaFuncAttributeMaxDynamicSharedMemorySize, HG_SMEM);
    cudaFuncSetAttribute(hgemm_o,   cudaFuncAttributeMaxDynamicSharedMemorySize, HG_SMEM);

    // pre-pass: streaming fp32 -> fp16
    cvt_f2h<<<SEQ * HID / 4 / 256, 256>>>(x, xh, SEQ * HID);
    cvt_f2h<<<HID * (NQH * HD) / 4 / 256, 256>>>(Wq, wqh, HID * NQH * HD);
    cvt_f2h<<<HID * (NKV * HD) / 4 / 256, 256>>>(Wk, wkh, HID * NKV * HD);
    cvt_f2h<<<HID * (NKV * HD) / 4 / 256, 256>>>(Wv, wvh, HID * NKV * HD);
    cvt_f2h<<<(NQH * HD) * HID / 4 / 256, 256>>>(Wo, woh, NQH * HD * HID);

    // fused QKV projection
    hgemm_qkv<<<dim3(24, SEQ / 128), 256, HG_SMEM>>>(xh, wqh, wkh, wvh, qp, kp, vh);

    // RMSNorm + RoPE -> fp16 (q pre-scaled by 128^-0.5)
    rmsnorm_rope_h<<<dim3(SEQ, NQH), 128>>>(qp, qh, qw, cosT, sinT, pos, NQH, 0.08838834764831845f);
    rmsnorm_rope_h<<<dim3(SEQ, NKV), 128>>>(kp, kh, kw, cosT, sinT, pos, NKV, 1.0f);

    // causal flash attention (heavy CTAs first)
    flash_h<<<dim3(SEQ / 128, NQH), 256, ATTN_SMEM>>>(qh, kh, vh, oh);

    // output projection
    hgemm_o<<<dim3(HID / 256, SEQ / 128), 256, HG_SMEM>>>(oh, woh, out);
}

// round 10
// speedup vs baseline: 8.9733x; 1.0441x over previous
#include <cuda_runtime.h>
#include <cuda_fp16.h>
#include <math.h>
#include <stdint.h>

#define SEQ 2048
#define HID 4096
#define NQH 32
#define NKV 8
#define HD  128

// ---------------- scratch (no cudaMalloc allowed) ----------------
__device__ float  g_q[SEQ * NQH * HD];
__device__ float  g_k[SEQ * NKV * HD];
__device__ __half g_xh[SEQ * HID];
__device__ __half g_qh[SEQ * NQH * HD];
__device__ __half g_kh[SEQ * NKV * HD];
__device__ __half g_vh[SEQ * NKV * HD];
__device__ __half g_oh[SEQ * NQH * HD];
__device__ __half g_Wqh[HID * (NQH * HD)];   // row-major [K, N] fp16
__device__ __half g_Wkh[HID * (NKV * HD)];
__device__ __half g_Wvh[HID * (NKV * HD)];
__device__ __half g_Woh[(NQH * HD) * HID];

// ---------------- asm helpers ----------------
__device__ __forceinline__ uint32_t smem_u32(const void* p) {
    uint32_t a;
    asm("{ .reg .u64 t; cvta.to.shared.u64 t, %1; cvt.u32.u64 %0, t; }" : "=r"(a) : "l"(p));
    return a;
}
#define CP_A16(dst, src) asm volatile("cp.async.cg.shared.global [%0], [%1], 16;" :: "r"(dst), "l"(src))
#define CP_COMMIT() asm volatile("cp.async.commit_group;")
#define CP_WAIT(n)  asm volatile("cp.async.wait_group %0;" :: "n"(n))

__device__ __forceinline__ void ldsm_x4(uint32_t* r, uint32_t a) {
    asm volatile("ldmatrix.sync.aligned.m8n8.x4.shared.b16 {%0,%1,%2,%3}, [%4];"
                 : "=r"(r[0]), "=r"(r[1]), "=r"(r[2]), "=r"(r[3]) : "r"(a));
}
__device__ __forceinline__ void ldsm_x4_t(uint32_t* r, uint32_t a) {
    asm volatile("ldmatrix.sync.aligned.m8n8.x4.trans.shared.b16 {%0,%1,%2,%3}, [%4];"
                 : "=r"(r[0]), "=r"(r[1]), "=r"(r[2]), "=r"(r[3]) : "r"(a));
}
__device__ __forceinline__ void mma16816(float (&d)[4], const uint32_t (&a)[4], uint32_t b0, uint32_t b1) {
    asm volatile(
        "mma.sync.aligned.m16n8k16.row.col.f32.f16.f16.f32 "
        "{%0,%1,%2,%3}, {%4,%5,%6,%7}, {%8,%9}, {%0,%1,%2,%3};"
        : "+f"(d[0]), "+f"(d[1]), "+f"(d[2]), "+f"(d[3])
        : "r"(a[0]), "r"(a[1]), "r"(a[2]), "r"(a[3]), "r"(b0), "r"(b1));
}
__device__ __forceinline__ uint32_t pack_h2(float lo, float hi) {
    __half2 h = __floats2half2_rn(lo, hi);
    return *(uint32_t*)&h;
}

// ---------------- pre-pass: fp32 -> fp16, 16 elem/thread (MLP=4) ----------------
// n must be a multiple of 4096; grid = n / 4096, block 256.
__global__ __launch_bounds__(256)
void cvt_f2h(const float* __restrict__ in, __half* __restrict__ out, int n) {
    const int base = blockIdx.x * 4096 + threadIdx.x * 4;
    float4 v0 = *(const float4*)(in + base);
    float4 v1 = *(const float4*)(in + base + 1024);
    float4 v2 = *(const float4*)(in + base + 2048);
    float4 v3 = *(const float4*)(in + base + 3072);
    *(uint2*)(out + base)        = make_uint2(pack_h2(v0.x, v0.y), pack_h2(v0.z, v0.w));
    *(uint2*)(out + base + 1024) = make_uint2(pack_h2(v1.x, v1.y), pack_h2(v1.z, v1.w));
    *(uint2*)(out + base + 2048) = make_uint2(pack_h2(v2.x, v2.y), pack_h2(v2.z, v2.w));
    *(uint2*)(out + base + 3072) = make_uint2(pack_h2(v3.x, v3.y), pack_h2(v3.z, v3.w));
}

// ---------------- fp16 GEMM: C[M,N] = A[M,K](h,K-major) @ W[K,N](h,row-major) ----------------
// CTA tile 128(M) x 256(N), BK=32, 8 warps (2x4), warp tile 64x64.
// 4-stage cp.async ring, issue-ahead 2, ONE __syncthreads per iteration.
#define HA_STR 40
#define HB_STR 264
#define HA_ST  (128 * HA_STR * 2)
#define HB_ST  (32 * HB_STR * 2)
#define HG_SMEM (4 * (HA_ST + HB_ST))

template <typename OT>
__device__ __forceinline__
void hgemm_rm(const __half* __restrict__ A, const __half* __restrict__ W,
              OT* __restrict__ C, int Ncols, int K, int bm, int bn) {
    extern __shared__ __align__(16) __half hsm[];
    const uint32_t asb = smem_u32(hsm);
    const uint32_t bsb = asb + 4 * HA_ST;

    const int tid  = threadIdx.x;
    const int warp = tid >> 5;
    const int lane = tid & 31;
    const int g    = lane >> 2;
    const int t4   = lane & 3;
    const int wm   = warp >> 2;
    const int wn   = warp & 3;

    const __half* Asrc[2];
    uint32_t Adst[2];
    #pragma unroll
    for (int j = 0; j < 2; j++) {
        int ch = tid + j * 256;
        int row = ch >> 2, kc = (ch & 3) * 8;
        Asrc[j] = A + (size_t)(bm + row) * K + kc;
        Adst[j] = asb + (row * HA_STR + kc) * 2;
    }
    const __half* Bsrc[4];
    uint32_t Bdst[4];
    #pragma unroll
    for (int j = 0; j < 4; j++) {
        int ch = tid + j * 256;
        int row = ch >> 5, c8 = ch & 31;
        Bsrc[j] = W + (size_t)row * Ncols + bn + c8 * 8;
        Bdst[j] = bsb + (row * HB_STR + c8 * 8) * 2;
    }

    const uint32_t aBase = asb + ((wm * 64 + (lane & 7) + ((lane >> 3) & 1) * 8) * HA_STR
                                  + (lane >> 4) * 8) * 2;
    const uint32_t bBase = bsb + (((lane & 7) + ((lane >> 3) & 1) * 8) * HB_STR
                                  + wn * 64 + (lane >> 4) * 8) * 2;

    float acc[4][8][4];
    #pragma unroll
    for (int mi = 0; mi < 4; mi++)
        #pragma unroll
        for (int ni = 0; ni < 8; ni++)
            #pragma unroll
            for (int r = 0; r < 4; r++) acc[mi][ni][r] = 0.0f;

    const int iters = K >> 5;
    const size_t bAdv = (size_t)32 * Ncols;

    #pragma unroll
    for (int j = 0; j < 2; j++) CP_A16(Adst[j], Asrc[j]);
    #pragma unroll
    for (int j = 0; j < 4; j++) CP_A16(Bdst[j], Bsrc[j]);
    CP_COMMIT();
    {
        #pragma unroll
        for (int j = 0; j < 2; j++) CP_A16(Adst[j] + HA_ST, Asrc[j] + 32);
        #pragma unroll
        for (int j = 0; j < 4; j++) CP_A16(Bdst[j] + HB_ST, Bsrc[j] + bAdv);
        CP_COMMIT();
    }

    for (int i = 0; i < iters; i++) {
        if (i + 2 < iters) {
            const uint32_t ao = ((i + 2) & 3) * HA_ST;
            const uint32_t bo = ((i + 2) & 3) * HB_ST;
            const int ko = (i + 2) << 5;
            #pragma unroll
            for (int j = 0; j < 2; j++) CP_A16(Adst[j] + ao, Asrc[j] + ko);
            #pragma unroll
            for (int j = 0; j < 4; j++) CP_A16(Bdst[j] + bo, Bsrc[j] + (size_t)(i + 2) * bAdv);
            CP_COMMIT();
            CP_WAIT(2);
        } else if (i + 1 < iters) {
            CP_WAIT(1);
        } else {
            CP_WAIT(0);
        }
        __syncthreads();

        const uint32_t ao = (i & 3) * HA_ST;
        const uint32_t bo = (i & 3) * HB_ST;
        #pragma unroll
        for (int kb = 0; kb < 2; kb++) {
            uint32_t af[4][4];
            #pragma unroll
            for (int mi = 0; mi < 4; mi++)
                ldsm_x4(af[mi], aBase + ao + mi * (16 * HA_STR * 2) + kb * 32);
            uint32_t bf[4][4];
            #pragma unroll
            for (int nj = 0; nj < 4; nj++)
                ldsm_x4_t(bf[nj], bBase + bo + kb * (16 * HB_STR * 2) + nj * 32);
            #pragma unroll
            for (int mi = 0; mi < 4; mi++)
                #pragma unroll
                for (int nj = 0; nj < 4; nj++) {
                    mma16816(acc[mi][2 * nj],     af[mi], bf[nj][0], bf[nj][1]);
                    mma16816(acc[mi][2 * nj + 1], af[mi], bf[nj][2], bf[nj][3]);
                }
        }
    }

    #pragma unroll
    for (int mi = 0; mi < 4; mi++) {
        #pragma unroll
        for (int ni = 0; ni < 8; ni++) {
            int r1 = bm + wm * 64 + mi * 16 + g;
            int c  = bn + wn * 64 + ni * 8 + t4 * 2;
            if (sizeof(OT) == 2) {
                __half* Ch = (__half*)C;
                *(uint32_t*)(Ch + (size_t)r1 * Ncols + c)       = pack_h2(acc[mi][ni][0], acc[mi][ni][1]);
                *(uint32_t*)(Ch + (size_t)(r1 + 8) * Ncols + c) = pack_h2(acc[mi][ni][2], acc[mi][ni][3]);
            } else {
                float* Cf = (float*)C;
                *(float2*)(Cf + (size_t)r1 * Ncols + c)       = make_float2(acc[mi][ni][0], acc[mi][ni][1]);
                *(float2*)(Cf + (size_t)(r1 + 8) * Ncols + c) = make_float2(acc[mi][ni][2], acc[mi][ni][3]);
            }
        }
    }
}

__global__ __launch_bounds__(256, 1)
void hgemm_qkv(const __half* __restrict__ A,
               const __half* __restrict__ Wq, const __half* __restrict__ Wk,
               const __half* __restrict__ Wv,
               float* __restrict__ Cq, float* __restrict__ Ck, __half* __restrict__ Cv) {
    const int bx = blockIdx.x;
    const int bm = blockIdx.y * 128;
    if (bx < 16)      hgemm_rm<float >(A, Wq, Cq, NQH * HD, HID, bm, bx * 256);
    else if (bx < 20) hgemm_rm<float >(A, Wk, Ck, NKV * HD, HID, bm, (bx - 16) * 256);
    else              hgemm_rm<__half>(A, Wv, Cv, NKV * HD, HID, bm, (bx - 20) * 256);
}

__global__ __launch_bounds__(256, 1)
void hgemm_o(const __half* __restrict__ A, const __half* __restrict__ W,
             float* __restrict__ C) {
    hgemm_rm<float>(A, W, C, HID, NQH * HD, blockIdx.y * 128, blockIdx.x * 256);
}

// ---------------- RMSNorm + RoPE: one warp per 128-wide row, float4/lane ----------------
// rows = SEQ * n_heads; row r -> buf offset r*128, s = r / n_heads.
// grid = rows/8, block 256 (8 warps).
__global__ __launch_bounds__(256)
void rmsnorm_rope_w(const float* __restrict__ buf, __half* __restrict__ outh,
                    const float* __restrict__ w,
                    const float* __restrict__ cosT, const float* __restrict__ sinT,
                    const int* __restrict__ pos_ids, int n_heads, float oscale) {
    const int lane = threadIdx.x & 31;
    const int row  = blockIdx.x * 8 + (threadIdx.x >> 5);
    const int s    = row / n_heads;
    const int c0   = lane * 4;

    const float* rp = buf + (size_t)row * HD;
    float4 v  = *(const float4*)(rp + c0);
    float4 wv = *(const float4*)(w + c0);

    float ss = v.x * v.x + v.y * v.y + v.z * v.z + v.w * v.w;
    #pragma unroll
    for (int off = 16; off > 0; off >>= 1)
        ss += __shfl_xor_sync(0xffffffffu, ss, off);
    const float inv = rsqrtf(ss * (1.0f / HD) + 1e-6f);

    float4 xn;
    xn.x = v.x * inv * wv.x; xn.y = v.y * inv * wv.y;
    xn.z = v.z * inv * wv.z; xn.w = v.w * inv * wv.w;

    // RoPE partner: lane^16 holds columns c0 +- 64 (same component index)
    float px = __shfl_xor_sync(0xffffffffu, xn.x, 16);
    float py = __shfl_xor_sync(0xffffffffu, xn.y, 16);
    float pz = __shfl_xor_sync(0xffffffffu, xn.z, 16);
    float pw = __shfl_xor_sync(0xffffffffu, xn.w, 16);
    const float sgn = (lane < 16) ? -1.0f : 1.0f;

    const int p = pos_ids[s];
    float4 c  = *(const float4*)(cosT + (size_t)p * HD + c0);
    float4 sn = *(const float4*)(sinT + (size_t)p * HD + c0);

    float ox = (xn.x * c.x + sgn * px * sn.x) * oscale;
    float oy = (xn.y * c.y + sgn * py * sn.y) * oscale;
    float oz = (xn.z * c.z + sgn * pz * sn.z) * oscale;
    float ow = (xn.w * c.w + sgn * pw * sn.w) * oscale;

    *(uint2*)(outh + (size_t)row * HD + c0) = make_uint2(pack_h2(ox, oy), pack_h2(oz, ow));
}

// ---------------- fp16 flash attention (causal, GQA 4:1) ----------------
#define FSTR 136
#define FQ_HALVES (128 * FSTR)
#define FK_HALVES (64 * FSTR)
#define ATTN_SMEM ((FQ_HALVES + 4 * FK_HALVES) * 2)

__global__ __launch_bounds__(256, 1)
void flash_h(const __half* __restrict__ Qh, const __half* __restrict__ Kh,
             const __half* __restrict__ Vh, __half* __restrict__ Oh) {
    extern __shared__ __align__(16) __half fsm[];
    __half* Qs = fsm;
    __half* Ks = fsm + FQ_HALVES;
    __half* Vs = Ks + 2 * FK_HALVES;

    const int tid  = threadIdx.x;
    const int warp = tid >> 5;
    const int lane = tid & 31;
    const int g    = lane >> 2;
    const int t4   = lane & 3;
    const int wrow = warp * 16;

    const int qb    = gridDim.x - 1 - blockIdx.x;   // heavy blocks first
    const int h     = blockIdx.y;
    const int kvh   = h >> 2;
    const int qbase = qb * 128;

    const uint32_t qsb = smem_u32(Qs);
    const uint32_t ksb = smem_u32(Ks);
    const uint32_t vsb = smem_u32(Vs);
    const uint32_t KSTB = FK_HALVES * 2;

    {
        #pragma unroll
        for (int j = 0; j < 8; j++) {
            int c = tid + j * 256;
            int row = c >> 4, c8 = c & 15;
            CP_A16(qsb + (row * FSTR + c8 * 8) * 2,
                   Qh + (size_t)(qbase + row) * (NQH * HD) + h * HD + c8 * 8);
        }
        #pragma unroll
        for (int j = 0; j < 4; j++) {
            int c = tid + j * 256;
            int row = c >> 4, c8 = c & 15;
            size_t gi = (size_t)row * (NKV * HD) + kvh * HD + c8 * 8;
            CP_A16(ksb + (row * FSTR + c8 * 8) * 2, Kh + gi);
            CP_A16(vsb + (row * FSTR + c8 * 8) * 2, Vh + gi);
        }
        CP_COMMIT();
    }

    float o[16][4];
    #pragma unroll
    for (int ni = 0; ni < 16; ni++)
        #pragma unroll
        for (int r = 0; r < 4; r++) o[ni][r] = 0.0f;
    float m1 = -INFINITY, m2 = -INFINITY, l1 = 0.0f, l2 = 0.0f;

    const uint32_t qBase = qsb + ((wrow + (lane & 7) + ((lane >> 3) & 1) * 8) * FSTR
                                   + (lane >> 4) * 8) * 2;
    const uint32_t kBase = ksb + (((lane & 7) + (lane >> 4) * 8) * FSTR
                                   + ((lane >> 3) & 1) * 8) * 2;
    const uint32_t vBase = vsb + (((lane & 7) + ((lane >> 3) & 1) * 8) * FSTR
                                   + (lane >> 4) * 8) * 2;

    const int nkb = 2 * qb + 2;
    for (int kb = 0; kb < nkb; kb++) {
        if (kb + 1 < nkb) {
            const int st = (kb + 1) & 1;
            const int kbase1 = (kb + 1) * 64;
            #pragma unroll
            for (int j = 0; j < 4; j++) {
                int c = tid + j * 256;
                int row = c >> 4, c8 = c & 15;
                size_t gi = (size_t)(kbase1 + row) * (NKV * HD) + kvh * HD + c8 * 8;
                CP_A16(ksb + st * KSTB + (row * FSTR + c8 * 8) * 2, Kh + gi);
                CP_A16(vsb + st * KSTB + (row * FSTR + c8 * 8) * 2, Vh + gi);
            }
            CP_COMMIT();
            CP_WAIT(1);
        } else {
            CP_WAIT(0);
        }
        __syncthreads();

        const uint32_t so = (kb & 1) * KSTB;
        const int kbase = kb * 64;

        float s[8][4];
        #pragma unroll
        for (int ni = 0; ni < 8; ni++)
            #pragma unroll
            for (int r = 0; r < 4; r++) s[ni][r] = 0.0f;

        #pragma unroll
        for (int k0 = 0; k0 < HD; k0 += 16) {
            uint32_t aq[4];
            ldsm_x4(aq, qBase + k0 * 2);
            #pragma unroll
            for (int nj = 0; nj < 4; nj++) {
                uint32_t bk[4];
                ldsm_x4(bk, kBase + so + nj * (16 * FSTR * 2) + k0 * 2);
                mma16816(s[2 * nj],     aq, bk[0], bk[1]);
                mma16816(s[2 * nj + 1], aq, bk[2], bk[3]);
            }
        }

        if (kbase + 63 > qbase + wrow) {
            const int r1 = qbase + wrow + g;
            const int r2 = r1 + 8;
            #pragma unroll
            for (int ni = 0; ni < 8; ni++) {
                int c0 = kbase + ni * 8 + t4 * 2;
                if (c0     > r1) s[ni][0] = -1e30f;
                if (c0 + 1 > r1) s[ni][1] = -1e30f;
                if (c0     > r2) s[ni][2] = -1e30f;
                if (c0 + 1 > r2) s[ni][3] = -1e30f;
            }
        }

        float mx1 = -INFINITY, mx2 = -INFINITY;
        #pragma unroll
        for (int ni = 0; ni < 8; ni++) {
            mx1 = fmaxf(mx1, fmaxf(s[ni][0], s[ni][1]));
            mx2 = fmaxf(mx2, fmaxf(s[ni][2], s[ni][3]));
        }
        mx1 = fmaxf(mx1, __shfl_xor_sync(0xffffffffu, mx1, 1));
        mx1 = fmaxf(mx1, __shfl_xor_sync(0xffffffffu, mx1, 2));
        mx2 = fmaxf(mx2, __shfl_xor_sync(0xffffffffu, mx2, 1));
        mx2 = fmaxf(mx2, __shfl_xor_sync(0xffffffffu, mx2, 2));

        float mn1 = fmaxf(m1, mx1), mn2 = fmaxf(m2, mx2);
        float sc1 = __expf(m1 - mn1), sc2 = __expf(m2 - mn2);
        m1 = mn1; m2 = mn2;

        float ps1 = 0.0f, ps2 = 0.0f;
        #pragma unroll
        for (int ni = 0; ni < 8; ni++) {
            s[ni][0] = __expf(s[ni][0] - mn1);
            s[ni][1] = __expf(s[ni][1] - mn1);
            s[ni][2] = __expf(s[ni][2] - mn2);
            s[ni][3] = __expf(s[ni][3] - mn2);
            ps1 += s[ni][0] + s[ni][1];
            ps2 += s[ni][2] + s[ni][3];
        }
        ps1 += __shfl_xor_sync(0xffffffffu, ps1, 1);
        ps1 += __shfl_xor_sync(0xffffffffu, ps1, 2);
        ps2 += __shfl_xor_sync(0xffffffffu, ps2, 1);
        ps2 += __shfl_xor_sync(0xffffffffu, ps2, 2);
        l1 = l1 * sc1 + ps1;
        l2 = l2 * sc2 + ps2;

        #pragma unroll
        for (int ni = 0; ni < 16; ni++) {
            o[ni][0] *= sc1; o[ni][1] *= sc1;
            o[ni][2] *= sc2; o[ni][3] *= sc2;
        }

        #pragma unroll
        for (int j = 0; j < 4; j++) {
            uint32_t ap[4];
            ap[0] = pack_h2(s[2 * j][0],     s[2 * j][1]);
            ap[1] = pack_h2(s[2 * j][2],     s[2 * j][3]);
            ap[2] = pack_h2(s[2 * j + 1][0], s[2 * j + 1][1]);
            ap[3] = pack_h2(s[2 * j + 1][2], s[2 * j + 1][3]);
            #pragma unroll
            for (int nj = 0; nj < 8; nj++) {
                uint32_t bv[4];
                ldsm_x4_t(bv, vBase + so + j * (16 * FSTR * 2) + nj * 32);
                mma16816(o[2 * nj],     ap, bv[0], bv[1]);
                mma16816(o[2 * nj + 1], ap, bv[2], bv[3]);
            }
        }
        __syncthreads();
    }

    const float inv1 = 1.0f / l1;
    const float inv2 = 1.0f / l2;
    const int r1 = qbase + wrow + g;
    #pragma unroll
    for (int ni = 0; ni < 16; ni++) {
        int c = ni * 8 + t4 * 2;
        *(uint32_t*)(Oh + (size_t)r1 * (NQH * HD) + h * HD + c) =
            pack_h2(o[ni][0] * inv1, o[ni][1] * inv1);
        *(uint32_t*)(Oh + (size_t)(r1 + 8) * (NQH * HD) + h * HD + c) =
            pack_h2(o[ni][2] * inv2, o[ni][3] * inv2);
    }
}

// ---------------- launch ----------------
extern "C" void kernel_launch(void* const* d_in, const int* in_sizes, int n_in,
                              void* d_out, int out_size) {
    const float* x    = (const float*)d_in[0];
    const int*   pos  = (const int*)  d_in[1];
    const float* cosT = (const float*)d_in[2];
    const float* sinT = (const float*)d_in[3];
    // d_in[4] = attn_mask — replicated exactly by causal skip
    const float* Wq   = (const float*)d_in[5];
    const float* Wk   = (const float*)d_in[6];
    const float* Wv   = (const float*)d_in[7];
    const float* Wo   = (const float*)d_in[8];
    const float* qw   = (const float*)d_in[9];
    const float* kw   = (const float*)d_in[10];
    float* out = (float*)d_out;

    float *qp, *kp;
    __half *xh, *qh, *kh, *vh, *oh, *wqh, *wkh, *wvh, *woh;
    cudaGetSymbolAddress((void**)&qp, g_q);
    cudaGetSymbolAddress((void**)&kp, g_k);
    cudaGetSymbolAddress((void**)&xh, g_xh);
    cudaGetSymbolAddress((void**)&qh, g_qh);
    cudaGetSymbolAddress((void**)&kh, g_kh);
    cudaGetSymbolAddress((void**)&vh, g_vh);
    cudaGetSymbolAddress((void**)&oh, g_oh);
    cudaGetSymbolAddress((void**)&wqh, g_Wqh);
    cudaGetSymbolAddress((void**)&wkh, g_Wkh);
    cudaGetSymbolAddress((void**)&wvh, g_Wvh);
    cudaGetSymbolAddress((void**)&woh, g_Woh);

    cudaFuncSetAttribute(flash_h,   cudaFuncAttributeMaxDynamicSharedMemorySize, ATTN_SMEM);
    cudaFuncSetAttribute(hgemm_qkv, cudaFuncAttributeMaxDynamicSharedMemorySize, HG_SMEM);
    cudaFuncSetAttribute(hgemm_o,   cudaFuncAttributeMaxDynamicSharedMemorySize, HG_SMEM);

    // pre-pass: streaming fp32 -> fp16 (MLP=4 per thread)
    cvt_f2h<<<SEQ * HID / 4096, 256>>>(x, xh, SEQ * HID);
    cvt_f2h<<<HID * (NQH * HD) / 4096, 256>>>(Wq, wqh, HID * NQH * HD);
    cvt_f2h<<<HID * (NKV * HD) / 4096, 256>>>(Wk, wkh, HID * NKV * HD);
    cvt_f2h<<<HID * (NKV * HD) / 4096, 256>>>(Wv, wvh, HID * NKV * HD);
    cvt_f2h<<<(NQH * HD) * HID / 4096, 256>>>(Wo, woh, NQH * HD * HID);

    // fused QKV projection
    hgemm_qkv<<<dim3(24, SEQ / 128), 256, HG_SMEM>>>(xh, wqh, wkh, wvh, qp, kp, vh);

    // RMSNorm + RoPE -> fp16 (warp-per-row; q pre-scaled by 128^-0.5)
    rmsnorm_rope_w<<<SEQ * NQH / 8, 256>>>(qp, qh, qw, cosT, sinT, pos, NQH, 0.08838834764831845f);
    rmsnorm_rope_w<<<SEQ * NKV / 8, 256>>>(kp, kh, kw, cosT, sinT, pos, NKV, 1.0f);

    // causal flash attention (heavy CTAs first)
    flash_h<<<dim3(SEQ / 128, NQH), 256, ATTN_SMEM>>>(qh, kh, vh, oh);

    // output projection
    hgemm_o<<<dim3(HID / 256, SEQ / 128), 256, HG_SMEM>>>(oh, woh, out);
}

// round 11
// speedup vs baseline: 9.0111x; 1.0042x over previous
#include <cuda_runtime.h>
#include <cuda_fp16.h>
#include <math.h>
#include <stdint.h>

#define SEQ 2048
#define HID 4096
#define NQH 32
#define NKV 8
#define HD  128

// ---------------- scratch (no cudaMalloc allowed) ----------------
__device__ __half g_xh[SEQ * HID];
__device__ __half g_qh[SEQ * NQH * HD];
__device__ __half g_kh[SEQ * NKV * HD];
__device__ __half g_vh[SEQ * NKV * HD];
__device__ __half g_oh[SEQ * NQH * HD];
__device__ __half g_Wqh[HID * (NQH * HD)];   // row-major [K, N] fp16
__device__ __half g_Wkh[HID * (NKV * HD)];
__device__ __half g_Wvh[HID * (NKV * HD)];
__device__ __half g_Woh[(NQH * HD) * HID];

// ---------------- asm helpers ----------------
__device__ __forceinline__ uint32_t smem_u32(const void* p) {
    uint32_t a;
    asm("{ .reg .u64 t; cvta.to.shared.u64 t, %1; cvt.u32.u64 %0, t; }" : "=r"(a) : "l"(p));
    return a;
}
#define CP_A16(dst, src) asm volatile("cp.async.cg.shared.global [%0], [%1], 16;" :: "r"(dst), "l"(src))
#define CP_COMMIT() asm volatile("cp.async.commit_group;")
#define CP_WAIT(n)  asm volatile("cp.async.wait_group %0;" :: "n"(n))

__device__ __forceinline__ void ldsm_x4(uint32_t* r, uint32_t a) {
    asm volatile("ldmatrix.sync.aligned.m8n8.x4.shared.b16 {%0,%1,%2,%3}, [%4];"
                 : "=r"(r[0]), "=r"(r[1]), "=r"(r[2]), "=r"(r[3]) : "r"(a));
}
__device__ __forceinline__ void ldsm_x4_t(uint32_t* r, uint32_t a) {
    asm volatile("ldmatrix.sync.aligned.m8n8.x4.trans.shared.b16 {%0,%1,%2,%3}, [%4];"
                 : "=r"(r[0]), "=r"(r[1]), "=r"(r[2]), "=r"(r[3]) : "r"(a));
}
__device__ __forceinline__ void mma16816(float (&d)[4], const uint32_t (&a)[4], uint32_t b0, uint32_t b1) {
    asm volatile(
        "mma.sync.aligned.m16n8k16.row.col.f32.f16.f16.f32 "
        "{%0,%1,%2,%3}, {%4,%5,%6,%7}, {%8,%9}, {%0,%1,%2,%3};"
        : "+f"(d[0]), "+f"(d[1]), "+f"(d[2]), "+f"(d[3])
        : "r"(a[0]), "r"(a[1]), "r"(a[2]), "r"(a[3]), "r"(b0), "r"(b1));
}
__device__ __forceinline__ uint32_t pack_h2(float lo, float hi) {
    __half2 h = __floats2half2_rn(lo, hi);
    return *(uint32_t*)&h;
}

// ---------------- pre-pass: ALL fp32 -> fp16 conversions in ONE launch ----------------
// Regions (element counts, all multiples of 4096):
//   x: 8M, Wq: 16M, Wk: 4M, Wv: 4M, Wo: 16M. 16 elem/thread, 4096/CTA.
#define N_X  (SEQ * HID)
#define N_WQ (HID * NQH * HD)
#define N_WK (HID * NKV * HD)
#define N_WV (HID * NKV * HD)
#define N_WO (NQH * HD * HID)

__global__ __launch_bounds__(256)
void cvt_all(const float* __restrict__ x,  const float* __restrict__ wq,
             const float* __restrict__ wk, const float* __restrict__ wv,
             const float* __restrict__ wo,
             __half* __restrict__ xh,  __half* __restrict__ wqh,
             __half* __restrict__ wkh, __half* __restrict__ wvh,
             __half* __restrict__ woh) {
    int b = blockIdx.x;
    const float* in;
    __half* out;
    if (b < N_X / 4096)                          { in = x;  out = xh;  }
    else if ((b -= N_X / 4096)  < N_WQ / 4096)   { in = wq; out = wqh; }
    else if ((b -= N_WQ / 4096) < N_WK / 4096)   { in = wk; out = wkh; }
    else if ((b -= N_WK / 4096) < N_WV / 4096)   { in = wv; out = wvh; }
    else    { b -= N_WV / 4096;                    in = wo; out = woh; }

    const int base = b * 4096 + threadIdx.x * 4;
    float4 v0 = *(const float4*)(in + base);
    float4 v1 = *(const float4*)(in + base + 1024);
    float4 v2 = *(const float4*)(in + base + 2048);
    float4 v3 = *(const float4*)(in + base + 3072);
    *(uint2*)(out + base)        = make_uint2(pack_h2(v0.x, v0.y), pack_h2(v0.z, v0.w));
    *(uint2*)(out + base + 1024) = make_uint2(pack_h2(v1.x, v1.y), pack_h2(v1.z, v1.w));
    *(uint2*)(out + base + 2048) = make_uint2(pack_h2(v2.x, v2.y), pack_h2(v2.z, v2.w));
    *(uint2*)(out + base + 3072) = make_uint2(pack_h2(v3.x, v3.y), pack_h2(v3.z, v3.w));
}
#define CVT_GRID ((N_X + N_WQ + N_WK + N_WV + N_WO) / 4096)

// ---------------- fp16 GEMM: C[M,N](h) = A[M,K](h,K-major) @ W[K,N](h,row-major) ----------------
// CTA tile 128(M) x 256(N), BK=32, 8 warps (2x4), warp tile 64x64.
// 4-stage cp.async ring, issue-ahead 2, ONE __syncthreads per iteration.
#define HA_STR 40
#define HB_STR 264
#define HA_ST  (128 * HA_STR * 2)
#define HB_ST  (32 * HB_STR * 2)
#define HG_SMEM (4 * (HA_ST + HB_ST))

template <typename OT>
__device__ __forceinline__
void hgemm_rm(const __half* __restrict__ A, const __half* __restrict__ W,
              OT* __restrict__ C, int Ncols, int K, int bm, int bn) {
    extern __shared__ __align__(16) __half hsm[];
    const uint32_t asb = smem_u32(hsm);
    const uint32_t bsb = asb + 4 * HA_ST;

    const int tid  = threadIdx.x;
    const int warp = tid >> 5;
    const int lane = tid & 31;
    const int g    = lane >> 2;
    const int t4   = lane & 3;
    const int wm   = warp >> 2;
    const int wn   = warp & 3;

    const __half* Asrc[2];
    uint32_t Adst[2];
    #pragma unroll
    for (int j = 0; j < 2; j++) {
        int ch = tid + j * 256;
        int row = ch >> 2, kc = (ch & 3) * 8;
        Asrc[j] = A + (size_t)(bm + row) * K + kc;
        Adst[j] = asb + (row * HA_STR + kc) * 2;
    }
    const __half* Bsrc[4];
    uint32_t Bdst[4];
    #pragma unroll
    for (int j = 0; j < 4; j++) {
        int ch = tid + j * 256;
        int row = ch >> 5, c8 = ch & 31;
        Bsrc[j] = W + (size_t)row * Ncols + bn + c8 * 8;
        Bdst[j] = bsb + (row * HB_STR + c8 * 8) * 2;
    }

    const uint32_t aBase = asb + ((wm * 64 + (lane & 7) + ((lane >> 3) & 1) * 8) * HA_STR
                                  + (lane >> 4) * 8) * 2;
    const uint32_t bBase = bsb + (((lane & 7) + ((lane >> 3) & 1) * 8) * HB_STR
                                  + wn * 64 + (lane >> 4) * 8) * 2;

    float acc[4][8][4];
    #pragma unroll
    for (int mi = 0; mi < 4; mi++)
        #pragma unroll
        for (int ni = 0; ni < 8; ni++)
            #pragma unroll
            for (int r = 0; r < 4; r++) acc[mi][ni][r] = 0.0f;

    const int iters = K >> 5;
    const size_t bAdv = (size_t)32 * Ncols;

    #pragma unroll
    for (int j = 0; j < 2; j++) CP_A16(Adst[j], Asrc[j]);
    #pragma unroll
    for (int j = 0; j < 4; j++) CP_A16(Bdst[j], Bsrc[j]);
    CP_COMMIT();
    {
        #pragma unroll
        for (int j = 0; j < 2; j++) CP_A16(Adst[j] + HA_ST, Asrc[j] + 32);
        #pragma unroll
        for (int j = 0; j < 4; j++) CP_A16(Bdst[j] + HB_ST, Bsrc[j] + bAdv);
        CP_COMMIT();
    }

    for (int i = 0; i < iters; i++) {
        if (i + 2 < iters) {
            const uint32_t ao = ((i + 2) & 3) * HA_ST;
            const uint32_t bo = ((i + 2) & 3) * HB_ST;
            const int ko = (i + 2) << 5;
            #pragma unroll
            for (int j = 0; j < 2; j++) CP_A16(Adst[j] + ao, Asrc[j] + ko);
            #pragma unroll
            for (int j = 0; j < 4; j++) CP_A16(Bdst[j] + bo, Bsrc[j] + (size_t)(i + 2) * bAdv);
            CP_COMMIT();
            CP_WAIT(2);
        } else if (i + 1 < iters) {
            CP_WAIT(1);
        } else {
            CP_WAIT(0);
        }
        __syncthreads();

        const uint32_t ao = (i & 3) * HA_ST;
        const uint32_t bo = (i & 3) * HB_ST;
        #pragma unroll
        for (int kb = 0; kb < 2; kb++) {
            uint32_t af[4][4];
            #pragma unroll
            for (int mi = 0; mi < 4; mi++)
                ldsm_x4(af[mi], aBase + ao + mi * (16 * HA_STR * 2) + kb * 32);
            uint32_t bf[4][4];
            #pragma unroll
            for (int nj = 0; nj < 4; nj++)
                ldsm_x4_t(bf[nj], bBase + bo + kb * (16 * HB_STR * 2) + nj * 32);
            #pragma unroll
            for (int mi = 0; mi < 4; mi++)
                #pragma unroll
                for (int nj = 0; nj < 4; nj++) {
                    mma16816(acc[mi][2 * nj],     af[mi], bf[nj][0], bf[nj][1]);
                    mma16816(acc[mi][2 * nj + 1], af[mi], bf[nj][2], bf[nj][3]);
                }
        }
    }

    #pragma unroll
    for (int mi = 0; mi < 4; mi++) {
        #pragma unroll
        for (int ni = 0; ni < 8; ni++) {
            int r1 = bm + wm * 64 + mi * 16 + g;
            int c  = bn + wn * 64 + ni * 8 + t4 * 2;
            if (sizeof(OT) == 2) {
                __half* Ch = (__half*)C;
                *(uint32_t*)(Ch + (size_t)r1 * Ncols + c)       = pack_h2(acc[mi][ni][0], acc[mi][ni][1]);
                *(uint32_t*)(Ch + (size_t)(r1 + 8) * Ncols + c) = pack_h2(acc[mi][ni][2], acc[mi][ni][3]);
            } else {
                float* Cf = (float*)C;
                *(float2*)(Cf + (size_t)r1 * Ncols + c)       = make_float2(acc[mi][ni][0], acc[mi][ni][1]);
                *(float2*)(Cf + (size_t)(r1 + 8) * Ncols + c) = make_float2(acc[mi][ni][2], acc[mi][ni][3]);
            }
        }
    }
}

// fused QKV: gridDim.x = 24; ALL outputs fp16 (norm runs in-place on fp16)
__global__ __launch_bounds__(256, 1)
void hgemm_qkv(const __half* __restrict__ A,
               const __half* __restrict__ Wq, const __half* __restrict__ Wk,
               const __half* __restrict__ Wv,
               __half* __restrict__ Cq, __half* __restrict__ Ck, __half* __restrict__ Cv) {
    const int bx = blockIdx.x;
    const int bm = blockIdx.y * 128;
    if (bx < 16)      hgemm_rm<__half>(A, Wq, Cq, NQH * HD, HID, bm, bx * 256);
    else if (bx < 20) hgemm_rm<__half>(A, Wk, Ck, NKV * HD, HID, bm, (bx - 16) * 256);
    else              hgemm_rm<__half>(A, Wv, Cv, NKV * HD, HID, bm, (bx - 20) * 256);
}

__global__ __launch_bounds__(256, 1)
void hgemm_o(const __half* __restrict__ A, const __half* __restrict__ W,
             float* __restrict__ C) {
    hgemm_rm<float>(A, W, C, HID, NQH * HD, blockIdx.y * 128, blockIdx.x * 256);
}

// ---------------- RMSNorm + RoPE, in-place on fp16: one warp per 128-wide row ----------------
__global__ __launch_bounds__(256)
void rmsnorm_rope_w(__half* __restrict__ buf, const float* __restrict__ w,
                    const float* __restrict__ cosT, const float* __restrict__ sinT,
                    const int* __restrict__ pos_ids, int n_heads, float oscale) {
    const int lane = threadIdx.x & 31;
    const int row  = blockIdx.x * 8 + (threadIdx.x >> 5);
    const int s    = row / n_heads;
    const int c0   = lane * 4;

    __half* rp = buf + (size_t)row * HD;
    uint2 raw = *(const uint2*)(rp + c0);
    __half2 h01 = *(__half2*)&raw.x;
    __half2 h23 = *(__half2*)&raw.y;
    float4 v = make_float4(__low2float(h01), __high2float(h01),
                           __low2float(h23), __high2float(h23));
    float4 wv = *(const float4*)(w + c0);

    float ss = v.x * v.x + v.y * v.y + v.z * v.z + v.w * v.w;
    #pragma unroll
    for (int off = 16; off > 0; off >>= 1)
        ss += __shfl_xor_sync(0xffffffffu, ss, off);
    const float inv = rsqrtf(ss * (1.0f / HD) + 1e-6f);

    float4 xn;
    xn.x = v.x * inv * wv.x; xn.y = v.y * inv * wv.y;
    xn.z = v.z * inv * wv.z; xn.w = v.w * inv * wv.w;

    float px = __shfl_xor_sync(0xffffffffu, xn.x, 16);
    float py = __shfl_xor_sync(0xffffffffu, xn.y, 16);
    float pz = __shfl_xor_sync(0xffffffffu, xn.z, 16);
    float pw = __shfl_xor_sync(0xffffffffu, xn.w, 16);
    const float sgn = (lane < 16) ? -1.0f : 1.0f;

    const int p = pos_ids[s];
    float4 c  = *(const float4*)(cosT + (size_t)p * HD + c0);
    float4 sn = *(const float4*)(sinT + (size_t)p * HD + c0);

    float ox = (xn.x * c.x + sgn * px * sn.x) * oscale;
    float oy = (xn.y * c.y + sgn * py * sn.y) * oscale;
    float oz = (xn.z * c.z + sgn * pz * sn.z) * oscale;
    float ow = (xn.w * c.w + sgn * pw * sn.w) * oscale;

    *(uint2*)(rp + c0) = make_uint2(pack_h2(ox, oy), pack_h2(oz, ow));
}

// ---------------- fp16 flash attention (causal, GQA 4:1), 2 CTAs/SM ----------------
#define FSTR 136
#define FQ_HALVES (128 * FSTR)
#define FK_HALVES (64 * FSTR)
#define ATTN_SMEM ((FQ_HALVES + 4 * FK_HALVES) * 2)

__global__ __launch_bounds__(256, 2)
void flash_h(const __half* __restrict__ Qh, const __half* __restrict__ Kh,
             const __half* __restrict__ Vh, __half* __restrict__ Oh) {
    extern __shared__ __align__(16) __half fsm[];
    __half* Qs = fsm;
    __half* Ks = fsm + FQ_HALVES;
    __half* Vs = Ks + 2 * FK_HALVES;

    const int tid  = threadIdx.x;
    const int warp = tid >> 5;
    const int lane = tid & 31;
    const int g    = lane >> 2;
    const int t4   = lane & 3;
    const int wrow = warp * 16;

    const int qb    = gridDim.x - 1 - blockIdx.x;   // heavy blocks first
    const int h     = blockIdx.y;
    const int kvh   = h >> 2;
    const int qbase = qb * 128;

    const uint32_t qsb = smem_u32(Qs);
    const uint32_t ksb = smem_u32(Ks);
    const uint32_t vsb = smem_u32(Vs);
    const uint32_t KSTB = FK_HALVES * 2;

    {
        #pragma unroll
        for (int j = 0; j < 8; j++) {
            int c = tid + j * 256;
            int row = c >> 4, c8 = c & 15;
            CP_A16(qsb + (row * FSTR + c8 * 8) * 2,
                   Qh + (size_t)(qbase + row) * (NQH * HD) + h * HD + c8 * 8);
        }
        #pragma unroll
        for (int j = 0; j < 4; j++) {
            int c = tid + j * 256;
            int row = c >> 4, c8 = c & 15;
            size_t gi = (size_t)row * (NKV * HD) + kvh * HD + c8 * 8;
            CP_A16(ksb + (row * FSTR + c8 * 8) * 2, Kh + gi);
            CP_A16(vsb + (row * FSTR + c8 * 8) * 2, Vh + gi);
        }
        CP_COMMIT();
    }

    float o[16][4];
    #pragma unroll
    for (int ni = 0; ni < 16; ni++)
        #pragma unroll
        for (int r = 0; r < 4; r++) o[ni][r] = 0.0f;
    float m1 = -INFINITY, m2 = -INFINITY, l1 = 0.0f, l2 = 0.0f;

    const uint32_t qBase = qsb + ((wrow + (lane & 7) + ((lane >> 3) & 1) * 8) * FSTR
                                   + (lane >> 4) * 8) * 2;
    const uint32_t kBase = ksb + (((lane & 7) + (lane >> 4) * 8) * FSTR
                                   + ((lane >> 3) & 1) * 8) * 2;
    const uint32_t vBase = vsb + (((lane & 7) + ((lane >> 3) & 1) * 8) * FSTR
                                   + (lane >> 4) * 8) * 2;

    const int nkb = 2 * qb + 2;
    for (int kb = 0; kb < nkb; kb++) {
        if (kb + 1 < nkb) {
            const int st = (kb + 1) & 1;
            const int kbase1 = (kb + 1) * 64;
            #pragma unroll
            for (int j = 0; j < 4; j++) {
                int c = tid + j * 256;
                int row = c >> 4, c8 = c & 15;
                size_t gi = (size_t)(kbase1 + row) * (NKV * HD) + kvh * HD + c8 * 8;
                CP_A16(ksb + st * KSTB + (row * FSTR + c8 * 8) * 2, Kh + gi);
                CP_A16(vsb + st * KSTB + (row * FSTR + c8 * 8) * 2, Vh + gi);
            }
            CP_COMMIT();
            CP_WAIT(1);
        } else {
            CP_WAIT(0);
        }
        __syncthreads();

        const uint32_t so = (kb & 1) * KSTB;
        const int kbase = kb * 64;

        float s[8][4];
        #pragma unroll
        for (int ni = 0; ni < 8; ni++)
            #pragma unroll
            for (int r = 0; r < 4; r++) s[ni][r] = 0.0f;

        #pragma unroll
        for (int k0 = 0; k0 < HD; k0 += 16) {
            uint32_t aq[4];
            ldsm_x4(aq, qBase + k0 * 2);
            #pragma unroll
            for (int nj = 0; nj < 4; nj++) {
                uint32_t bk[4];
                ldsm_x4(bk, kBase + so + nj * (16 * FSTR * 2) + k0 * 2);
                mma16816(s[2 * nj],     aq, bk[0], bk[1]);
                mma16816(s[2 * nj + 1], aq, bk[2], bk[3]);
            }
        }

        if (kbase + 63 > qbase + wrow) {
            const int r1 = qbase + wrow + g;
            const int r2 = r1 + 8;
            #pragma unroll
            for (int ni = 0; ni < 8; ni++) {
                int c0 = kbase + ni * 8 + t4 * 2;
                if (c0     > r1) s[ni][0] = -1e30f;
                if (c0 + 1 > r1) s[ni][1] = -1e30f;
                if (c0     > r2) s[ni][2] = -1e30f;
                if (c0 + 1 > r2) s[ni][3] = -1e30f;
            }
        }

        float mx1 = -INFINITY, mx2 = -INFINITY;
        #pragma unroll
        for (int ni = 0; ni < 8; ni++) {
            mx1 = fmaxf(mx1, fmaxf(s[ni][0], s[ni][1]));
            mx2 = fmaxf(mx2, fmaxf(s[ni][2], s[ni][3]));
        }
        mx1 = fmaxf(mx1, __shfl_xor_sync(0xffffffffu, mx1, 1));
        mx1 = fmaxf(mx1, __shfl_xor_sync(0xffffffffu, mx1, 2));
        mx2 = fmaxf(mx2, __shfl_xor_sync(0xffffffffu, mx2, 1));
        mx2 = fmaxf(mx2, __shfl_xor_sync(0xffffffffu, mx2, 2));

        float mn1 = fmaxf(m1, mx1), mn2 = fmaxf(m2, mx2);
        float sc1 = __expf(m1 - mn1), sc2 = __expf(m2 - mn2);
        m1 = mn1; m2 = mn2;

        float ps1 = 0.0f, ps2 = 0.0f;
        #pragma unroll
        for (int ni = 0; ni < 8; ni++) {
            s[ni][0] = __expf(s[ni][0] - mn1);
            s[ni][1] = __expf(s[ni][1] - mn1);
            s[ni][2] = __expf(s[ni][2] - mn2);
            s[ni][3] = __expf(s[ni][3] - mn2);
            ps1 += s[ni][0] + s[ni][1];
            ps2 += s[ni][2] + s[ni][3];
        }
        ps1 += __shfl_xor_sync(0xffffffffu, ps1, 1);
        ps1 += __shfl_xor_sync(0xffffffffu, ps1, 2);
        ps2 += __shfl_xor_sync(0xffffffffu, ps2, 1);
        ps2 += __shfl_xor_sync(0xffffffffu, ps2, 2);
        l1 = l1 * sc1 + ps1;
        l2 = l2 * sc2 + ps2;

        #pragma unroll
        for (int ni = 0; ni < 16; ni++) {
            o[ni][0] *= sc1; o[ni][1] *= sc1;
            o[ni][2] *= sc2; o[ni][3] *= sc2;
        }

        #pragma unroll
        for (int j = 0; j < 4; j++) {
            uint32_t ap[4];
            ap[0] = pack_h2(s[2 * j][0],     s[2 * j][1]);
            ap[1] = pack_h2(s[2 * j][2],     s[2 * j][3]);
            ap[2] = pack_h2(s[2 * j + 1][0], s[2 * j + 1][1]);
            ap[3] = pack_h2(s[2 * j + 1][2], s[2 * j + 1][3]);
            #pragma unroll
            for (int nj = 0; nj < 8; nj++) {
                uint32_t bv[4];
                ldsm_x4_t(bv, vBase + so + j * (16 * FSTR * 2) + nj * 32);
                mma16816(o[2 * nj],     ap, bv[0], bv[1]);
                mma16816(o[2 * nj + 1], ap, bv[2], bv[3]);
            }
        }
        __syncthreads();
    }

    const float inv1 = 1.0f / l1;
    const float inv2 = 1.0f / l2;
    const int r1 = qbase + wrow + g;
    #pragma unroll
    for (int ni = 0; ni < 16; ni++) {
        int c = ni * 8 + t4 * 2;
        *(uint32_t*)(Oh + (size_t)r1 * (NQH * HD) + h * HD + c) =
            pack_h2(o[ni][0] * inv1, o[ni][1] * inv1);
        *(uint32_t*)(Oh + (size_t)(r1 + 8) * (NQH * HD) + h * HD + c) =
            pack_h2(o[ni][2] * inv2, o[ni][3] * inv2);
    }
}

// ---------------- launch ----------------
extern "C" void kernel_launch(void* const* d_in, const int* in_sizes, int n_in,
                              void* d_out, int out_size) {
    const float* x    = (const float*)d_in[0];
    const int*   pos  = (const int*)  d_in[1];
    const float* cosT = (const float*)d_in[2];
    const float* sinT = (const float*)d_in[3];
    // d_in[4] = attn_mask — replicated exactly by causal skip
    const float* Wq   = (const float*)d_in[5];
    const float* Wk   = (const float*)d_in[6];
    const float* Wv   = (const float*)d_in[7];
    const float* Wo   = (const float*)d_in[8];
    const float* qw   = (const float*)d_in[9];
    const float* kw   = (const float*)d_in[10];
    float* out = (float*)d_out;

    __half *xh, *qh, *kh, *vh, *oh, *wqh, *wkh, *wvh, *woh;
    cudaGetSymbolAddress((void**)&xh, g_xh);
    cudaGetSymbolAddress((void**)&qh, g_qh);
    cudaGetSymbolAddress((void**)&kh, g_kh);
    cudaGetSymbolAddress((void**)&vh, g_vh);
    cudaGetSymbolAddress((void**)&oh, g_oh);
    cudaGetSymbolAddress((void**)&wqh, g_Wqh);
    cudaGetSymbolAddress((void**)&wkh, g_Wkh);
    cudaGetSymbolAddress((void**)&wvh, g_Wvh);
    cudaGetSymbolAddress((void**)&woh, g_Woh);

    cudaFuncSetAttribute(flash_h,   cudaFuncAttributeMaxDynamicSharedMemorySize, ATTN_SMEM);
    cudaFuncSetAttribute(hgemm_qkv, cudaFuncAttributeMaxDynamicSharedMemorySize, HG_SMEM);
    cudaFuncSetAttribute(hgemm_o,   cudaFuncAttributeMaxDynamicSharedMemorySize, HG_SMEM);

    // pre-pass: single fused fp32 -> fp16 conversion launch
    cvt_all<<<CVT_GRID, 256>>>(x, Wq, Wk, Wv, Wo, xh, wqh, wkh, wvh, woh);

    // fused QKV projection (all outputs fp16)
    hgemm_qkv<<<dim3(24, SEQ / 128), 256, HG_SMEM>>>(xh, wqh, wkh, wvh, qh, kh, vh);

    // RMSNorm + RoPE in-place on fp16 (q pre-scaled by 128^-0.5)
    rmsnorm_rope_w<<<SEQ * NQH / 8, 256>>>(qh, qw, cosT, sinT, pos, NQH, 0.08838834764831845f);
    rmsnorm_rope_w<<<SEQ * NKV / 8, 256>>>(kh, kw, cosT, sinT, pos, NKV, 1.0f);

    // causal flash attention (heavy CTAs first, 2 CTAs/SM)
    flash_h<<<dim3(SEQ / 128, NQH), 256, ATTN_SMEM>>>(qh, kh, vh, oh);

    // output projection
    hgemm_o<<<dim3(HID / 256, SEQ / 128), 256, HG_SMEM>>>(oh, woh, out);
}

// round 12
// speedup vs baseline: 9.2652x; 1.0282x over previous
#include <cuda_runtime.h>
#include <cuda_fp16.h>
#include <math.h>
#include <stdint.h>

#define SEQ 2048
#define HID 4096
#define NQH 32
#define NKV 8
#define HD  128

// ---------------- scratch (no cudaMalloc allowed) ----------------
__device__ __half g_xh[SEQ * HID];
__device__ __half g_qh[SEQ * NQH * HD];
__device__ __half g_kh[SEQ * NKV * HD];
__device__ __half g_vh[SEQ * NKV * HD];
__device__ __half g_oh[SEQ * NQH * HD];
__device__ __half g_Wqh[HID * (NQH * HD)];   // row-major [K, N] fp16
__device__ __half g_Wkh[HID * (NKV * HD)];
__device__ __half g_Wvh[HID * (NKV * HD)];
__device__ __half g_Woh[(NQH * HD) * HID];

// ---------------- asm helpers ----------------
__device__ __forceinline__ uint32_t smem_u32(const void* p) {
    uint32_t a;
    asm("{ .reg .u64 t; cvta.to.shared.u64 t, %1; cvt.u32.u64 %0, t; }" : "=r"(a) : "l"(p));
    return a;
}
#define CP_A16(dst, src) asm volatile("cp.async.cg.shared.global [%0], [%1], 16;" :: "r"(dst), "l"(src))
#define CP_COMMIT() asm volatile("cp.async.commit_group;")
#define CP_WAIT(n)  asm volatile("cp.async.wait_group %0;" :: "n"(n))

__device__ __forceinline__ void ldsm_x4(uint32_t* r, uint32_t a) {
    asm volatile("ldmatrix.sync.aligned.m8n8.x4.shared.b16 {%0,%1,%2,%3}, [%4];"
                 : "=r"(r[0]), "=r"(r[1]), "=r"(r[2]), "=r"(r[3]) : "r"(a));
}
__device__ __forceinline__ void ldsm_x4_t(uint32_t* r, uint32_t a) {
    asm volatile("ldmatrix.sync.aligned.m8n8.x4.trans.shared.b16 {%0,%1,%2,%3}, [%4];"
                 : "=r"(r[0]), "=r"(r[1]), "=r"(r[2]), "=r"(r[3]) : "r"(a));
}
__device__ __forceinline__ void mma16816(float (&d)[4], const uint32_t (&a)[4], uint32_t b0, uint32_t b1) {
    asm volatile(
        "mma.sync.aligned.m16n8k16.row.col.f32.f16.f16.f32 "
        "{%0,%1,%2,%3}, {%4,%5,%6,%7}, {%8,%9}, {%0,%1,%2,%3};"
        : "+f"(d[0]), "+f"(d[1]), "+f"(d[2]), "+f"(d[3])
        : "r"(a[0]), "r"(a[1]), "r"(a[2]), "r"(a[3]), "r"(b0), "r"(b1));
}
__device__ __forceinline__ uint32_t pack_h2(float lo, float hi) {
    __half2 h = __floats2half2_rn(lo, hi);
    return *(uint32_t*)&h;
}

// ---------------- pre-pass: ALL fp32 -> fp16 conversions in ONE launch ----------------
#define N_X  (SEQ * HID)
#define N_WQ (HID * NQH * HD)
#define N_WK (HID * NKV * HD)
#define N_WV (HID * NKV * HD)
#define N_WO (NQH * HD * HID)

__global__ __launch_bounds__(256)
void cvt_all(const float* __restrict__ x,  const float* __restrict__ wq,
             const float* __restrict__ wk, const float* __restrict__ wv,
             const float* __restrict__ wo,
             __half* __restrict__ xh,  __half* __restrict__ wqh,
             __half* __restrict__ wkh, __half* __restrict__ wvh,
             __half* __restrict__ woh) {
    int b = blockIdx.x;
    const float* in;
    __half* out;
    if (b < N_X / 4096)                          { in = x;  out = xh;  }
    else if ((b -= N_X / 4096)  < N_WQ / 4096)   { in = wq; out = wqh; }
    else if ((b -= N_WQ / 4096) < N_WK / 4096)   { in = wk; out = wkh; }
    else if ((b -= N_WK / 4096) < N_WV / 4096)   { in = wv; out = wvh; }
    else    { b -= N_WV / 4096;                    in = wo; out = woh; }

    const int base = b * 4096 + threadIdx.x * 4;
    float4 v0 = *(const float4*)(in + base);
    float4 v1 = *(const float4*)(in + base + 1024);
    float4 v2 = *(const float4*)(in + base + 2048);
    float4 v3 = *(const float4*)(in + base + 3072);
    *(uint2*)(out + base)        = make_uint2(pack_h2(v0.x, v0.y), pack_h2(v0.z, v0.w));
    *(uint2*)(out + base + 1024) = make_uint2(pack_h2(v1.x, v1.y), pack_h2(v1.z, v1.w));
    *(uint2*)(out + base + 2048) = make_uint2(pack_h2(v2.x, v2.y), pack_h2(v2.z, v2.w));
    *(uint2*)(out + base + 3072) = make_uint2(pack_h2(v3.x, v3.y), pack_h2(v3.z, v3.w));
}
#define CVT_GRID ((N_X + N_WQ + N_WK + N_WV + N_WO) / 4096)

// ---------------- fp16 GEMM (unchanged from round 11) ----------------
#define HA_STR 40
#define HB_STR 264
#define HA_ST  (128 * HA_STR * 2)
#define HB_ST  (32 * HB_STR * 2)
#define HG_SMEM (4 * (HA_ST + HB_ST))

template <typename OT>
__device__ __forceinline__
void hgemm_rm(const __half* __restrict__ A, const __half* __restrict__ W,
              OT* __restrict__ C, int Ncols, int K, int bm, int bn) {
    extern __shared__ __align__(16) __half hsm[];
    const uint32_t asb = smem_u32(hsm);
    const uint32_t bsb = asb + 4 * HA_ST;

    const int tid  = threadIdx.x;
    const int warp = tid >> 5;
    const int lane = tid & 31;
    const int g    = lane >> 2;
    const int t4   = lane & 3;
    const int wm   = warp >> 2;
    const int wn   = warp & 3;

    const __half* Asrc[2];
    uint32_t Adst[2];
    #pragma unroll
    for (int j = 0; j < 2; j++) {
        int ch = tid + j * 256;
        int row = ch >> 2, kc = (ch & 3) * 8;
        Asrc[j] = A + (size_t)(bm + row) * K + kc;
        Adst[j] = asb + (row * HA_STR + kc) * 2;
    }
    const __half* Bsrc[4];
    uint32_t Bdst[4];
    #pragma unroll
    for (int j = 0; j < 4; j++) {
        int ch = tid + j * 256;
        int row = ch >> 5, c8 = ch & 31;
        Bsrc[j] = W + (size_t)row * Ncols + bn + c8 * 8;
        Bdst[j] = bsb + (row * HB_STR + c8 * 8) * 2;
    }

    const uint32_t aBase = asb + ((wm * 64 + (lane & 7) + ((lane >> 3) & 1) * 8) * HA_STR
                                  + (lane >> 4) * 8) * 2;
    const uint32_t bBase = bsb + (((lane & 7) + ((lane >> 3) & 1) * 8) * HB_STR
                                  + wn * 64 + (lane >> 4) * 8) * 2;

    float acc[4][8][4];
    #pragma unroll
    for (int mi = 0; mi < 4; mi++)
        #pragma unroll
        for (int ni = 0; ni < 8; ni++)
            #pragma unroll
            for (int r = 0; r < 4; r++) acc[mi][ni][r] = 0.0f;

    const int iters = K >> 5;
    const size_t bAdv = (size_t)32 * Ncols;

    #pragma unroll
    for (int j = 0; j < 2; j++) CP_A16(Adst[j], Asrc[j]);
    #pragma unroll
    for (int j = 0; j < 4; j++) CP_A16(Bdst[j], Bsrc[j]);
    CP_COMMIT();
    {
        #pragma unroll
        for (int j = 0; j < 2; j++) CP_A16(Adst[j] + HA_ST, Asrc[j] + 32);
        #pragma unroll
        for (int j = 0; j < 4; j++) CP_A16(Bdst[j] + HB_ST, Bsrc[j] + bAdv);
        CP_COMMIT();
    }

    for (int i = 0; i < iters; i++) {
        if (i + 2 < iters) {
            const uint32_t ao = ((i + 2) & 3) * HA_ST;
            const uint32_t bo = ((i + 2) & 3) * HB_ST;
            const int ko = (i + 2) << 5;
            #pragma unroll
            for (int j = 0; j < 2; j++) CP_A16(Adst[j] + ao, Asrc[j] + ko);
            #pragma unroll
            for (int j = 0; j < 4; j++) CP_A16(Bdst[j] + bo, Bsrc[j] + (size_t)(i + 2) * bAdv);
            CP_COMMIT();
            CP_WAIT(2);
        } else if (i + 1 < iters) {
            CP_WAIT(1);
        } else {
            CP_WAIT(0);
        }
        __syncthreads();

        const uint32_t ao = (i & 3) * HA_ST;
        const uint32_t bo = (i & 3) * HB_ST;
        #pragma unroll
        for (int kb = 0; kb < 2; kb++) {
            uint32_t af[4][4];
            #pragma unroll
            for (int mi = 0; mi < 4; mi++)
                ldsm_x4(af[mi], aBase + ao + mi * (16 * HA_STR * 2) + kb * 32);
            uint32_t bf[4][4];
            #pragma unroll
            for (int nj = 0; nj < 4; nj++)
                ldsm_x4_t(bf[nj], bBase + bo + kb * (16 * HB_STR * 2) + nj * 32);
            #pragma unroll
            for (int mi = 0; mi < 4; mi++)
                #pragma unroll
                for (int nj = 0; nj < 4; nj++) {
                    mma16816(acc[mi][2 * nj],     af[mi], bf[nj][0], bf[nj][1]);
                    mma16816(acc[mi][2 * nj + 1], af[mi], bf[nj][2], bf[nj][3]);
                }
        }
    }

    #pragma unroll
    for (int mi = 0; mi < 4; mi++) {
        #pragma unroll
        for (int ni = 0; ni < 8; ni++) {
            int r1 = bm + wm * 64 + mi * 16 + g;
            int c  = bn + wn * 64 + ni * 8 + t4 * 2;
            if (sizeof(OT) == 2) {
                __half* Ch = (__half*)C;
                *(uint32_t*)(Ch + (size_t)r1 * Ncols + c)       = pack_h2(acc[mi][ni][0], acc[mi][ni][1]);
                *(uint32_t*)(Ch + (size_t)(r1 + 8) * Ncols + c) = pack_h2(acc[mi][ni][2], acc[mi][ni][3]);
            } else {
                float* Cf = (float*)C;
                *(float2*)(Cf + (size_t)r1 * Ncols + c)       = make_float2(acc[mi][ni][0], acc[mi][ni][1]);
                *(float2*)(Cf + (size_t)(r1 + 8) * Ncols + c) = make_float2(acc[mi][ni][2], acc[mi][ni][3]);
            }
        }
    }
}

__global__ __launch_bounds__(256, 1)
void hgemm_qkv(const __half* __restrict__ A,
               const __half* __restrict__ Wq, const __half* __restrict__ Wk,
               const __half* __restrict__ Wv,
               __half* __restrict__ Cq, __half* __restrict__ Ck, __half* __restrict__ Cv) {
    const int bx = blockIdx.x;
    const int bm = blockIdx.y * 128;
    if (bx < 16)      hgemm_rm<__half>(A, Wq, Cq, NQH * HD, HID, bm, bx * 256);
    else if (bx < 20) hgemm_rm<__half>(A, Wk, Ck, NKV * HD, HID, bm, (bx - 16) * 256);
    else              hgemm_rm<__half>(A, Wv, Cv, NKV * HD, HID, bm, (bx - 20) * 256);
}

__global__ __launch_bounds__(256, 1)
void hgemm_o(const __half* __restrict__ A, const __half* __restrict__ W,
             float* __restrict__ C) {
    hgemm_rm<float>(A, W, C, HID, NQH * HD, blockIdx.y * 128, blockIdx.x * 256);
}

// ---------------- RMSNorm + RoPE, in-place on fp16: one warp per row ----------------
__global__ __launch_bounds__(256)
void rmsnorm_rope_w(__half* __restrict__ buf, const float* __restrict__ w,
                    const float* __restrict__ cosT, const float* __restrict__ sinT,
                    const int* __restrict__ pos_ids, int n_heads, float oscale) {
    const int lane = threadIdx.x & 31;
    const int row  = blockIdx.x * 8 + (threadIdx.x >> 5);
    const int s    = row / n_heads;
    const int c0   = lane * 4;

    __half* rp = buf + (size_t)row * HD;
    uint2 raw = *(const uint2*)(rp + c0);
    __half2 h01 = *(__half2*)&raw.x;
    __half2 h23 = *(__half2*)&raw.y;
    float4 v = make_float4(__low2float(h01), __high2float(h01),
                           __low2float(h23), __high2float(h23));
    float4 wv = *(const float4*)(w + c0);

    float ss = v.x * v.x + v.y * v.y + v.z * v.z + v.w * v.w;
    #pragma unroll
    for (int off = 16; off > 0; off >>= 1)
        ss += __shfl_xor_sync(0xffffffffu, ss, off);
    const float inv = rsqrtf(ss * (1.0f / HD) + 1e-6f);

    float4 xn;
    xn.x = v.x * inv * wv.x; xn.y = v.y * inv * wv.y;
    xn.z = v.z * inv * wv.z; xn.w = v.w * inv * wv.w;

    float px = __shfl_xor_sync(0xffffffffu, xn.x, 16);
    float py = __shfl_xor_sync(0xffffffffu, xn.y, 16);
    float pz = __shfl_xor_sync(0xffffffffu, xn.z, 16);
    float pw = __shfl_xor_sync(0xffffffffu, xn.w, 16);
    const float sgn = (lane < 16) ? -1.0f : 1.0f;

    const int p = pos_ids[s];
    float4 c  = *(const float4*)(cosT + (size_t)p * HD + c0);
    float4 sn = *(const float4*)(sinT + (size_t)p * HD + c0);

    float ox = (xn.x * c.x + sgn * px * sn.x) * oscale;
    float oy = (xn.y * c.y + sgn * py * sn.y) * oscale;
    float oz = (xn.z * c.z + sgn * pz * sn.z) * oscale;
    float ow = (xn.w * c.w + sgn * pw * sn.w) * oscale;

    *(uint2*)(rp + c0) = make_uint2(pack_h2(ox, oy), pack_h2(oz, ow));
}

// ---------------- fp16 flash attention: GQA-shared K/V, exp2 softmax ----------------
// CTA = 32 q-rows x 4 heads (one kv head), M=128. grid (SEQ/32, NKV).
// Q pre-scaled by 128^-0.5 * log2(e) -> softmax in exp2 domain (identical result).
#define FSTR 136
#define FQ_HALVES (128 * FSTR)
#define FK_HALVES (64 * FSTR)
#define ATTN_SMEM ((FQ_HALVES + 4 * FK_HALVES) * 2)

__global__ __launch_bounds__(256, 1)
void flash_h(const __half* __restrict__ Qh, const __half* __restrict__ Kh,
             const __half* __restrict__ Vh, __half* __restrict__ Oh) {
    extern __shared__ __align__(16) __half fsm[];
    __half* Qs = fsm;
    __half* Ks = fsm + FQ_HALVES;
    __half* Vs = Ks + 2 * FK_HALVES;

    const int tid  = threadIdx.x;
    const int warp = tid >> 5;
    const int lane = tid & 31;
    const int g    = lane >> 2;
    const int t4   = lane & 3;
    const int wrow = warp * 16;

    const int qb    = gridDim.x - 1 - blockIdx.x;   // heavy blocks first
    const int kvh   = blockIdx.y;
    const int h0    = kvh * 4;
    const int qbase = qb * 32;                      // 32 seq rows per CTA

    const uint32_t qsb = smem_u32(Qs);
    const uint32_t ksb = smem_u32(Ks);
    const uint32_t vsb = smem_u32(Vs);
    const uint32_t KSTB = FK_HALVES * 2;

    // Q tile: 128 rows = 4 heads x 32 seq rows; row r -> (head h0 + r/32, seq qbase + r%32)
    {
        #pragma unroll
        for (int j = 0; j < 8; j++) {
            int c = tid + j * 256;
            int row = c >> 4, c8 = c & 15;
            CP_A16(qsb + (row * FSTR + c8 * 8) * 2,
                   Qh + (size_t)(qbase + (row & 31)) * (NQH * HD)
                      + (h0 + (row >> 5)) * HD + c8 * 8);
        }
        #pragma unroll
        for (int j = 0; j < 4; j++) {
            int c = tid + j * 256;
            int row = c >> 4, c8 = c & 15;
            size_t gi = (size_t)row * (NKV * HD) + kvh * HD + c8 * 8;
            CP_A16(ksb + (row * FSTR + c8 * 8) * 2, Kh + gi);
            CP_A16(vsb + (row * FSTR + c8 * 8) * 2, Vh + gi);
        }
        CP_COMMIT();
    }

    float o[16][4];
    #pragma unroll
    for (int ni = 0; ni < 16; ni++)
        #pragma unroll
        for (int r = 0; r < 4; r++) o[ni][r] = 0.0f;
    float m1 = -INFINITY, m2 = -INFINITY, l1 = 0.0f, l2 = 0.0f;

    const uint32_t qBase = qsb + ((wrow + (lane & 7) + ((lane >> 3) & 1) * 8) * FSTR
                                   + (lane >> 4) * 8) * 2;
    const uint32_t kBase = ksb + (((lane & 7) + (lane >> 4) * 8) * FSTR
                                   + ((lane >> 3) & 1) * 8) * 2;
    const uint32_t vBase = vsb + (((lane & 7) + ((lane >> 3) & 1) * 8) * FSTR
                                   + (lane >> 4) * 8) * 2;

    const int seqrel = wrow & 31;                   // this warp's seq offset within the 32
    const int nkb = (qbase >> 6) + 1;               // kv tiles needed (64-wide)
    for (int kb = 0; kb < nkb; kb++) {
        if (kb + 1 < nkb) {
            const int st = (kb + 1) & 1;
            const int kbase1 = (kb + 1) * 64;
            #pragma unroll
            for (int j = 0; j < 4; j++) {
                int c = tid + j * 256;
                int row = c >> 4, c8 = c & 15;
                size_t gi = (size_t)(kbase1 + row) * (NKV * HD) + kvh * HD + c8 * 8;
                CP_A16(ksb + st * KSTB + (row * FSTR + c8 * 8) * 2, Kh + gi);
                CP_A16(vsb + st * KSTB + (row * FSTR + c8 * 8) * 2, Vh + gi);
            }
            CP_COMMIT();
            CP_WAIT(1);
        } else {
            CP_WAIT(0);
        }
        __syncthreads();

        const uint32_t so = (kb & 1) * KSTB;
        const int kbase = kb * 64;

        float s[8][4];
        #pragma unroll
        for (int ni = 0; ni < 8; ni++)
            #pragma unroll
            for (int r = 0; r < 4; r++) s[ni][r] = 0.0f;

        #pragma unroll
        for (int k0 = 0; k0 < HD; k0 += 16) {
            uint32_t aq[4];
            ldsm_x4(aq, qBase + k0 * 2);
            #pragma unroll
            for (int nj = 0; nj < 4; nj++) {
                uint32_t bk[4];
                ldsm_x4(bk, kBase + so + nj * (16 * FSTR * 2) + k0 * 2);
                mma16816(s[2 * nj],     aq, bk[0], bk[1]);
                mma16816(s[2 * nj + 1], aq, bk[2], bk[3]);
            }
        }

        if (kbase + 63 > qbase + seqrel) {
            const int r1 = qbase + seqrel + g;
            const int r2 = r1 + 8;
            #pragma unroll
            for (int ni = 0; ni < 8; ni++) {
                int c0 = kbase + ni * 8 + t4 * 2;
                if (c0     > r1) s[ni][0] = -1e30f;
                if (c0 + 1 > r1) s[ni][1] = -1e30f;
                if (c0     > r2) s[ni][2] = -1e30f;
                if (c0 + 1 > r2) s[ni][3] = -1e30f;
            }
        }

        float mx1 = -INFINITY, mx2 = -INFINITY;
        #pragma unroll
        for (int ni = 0; ni < 8; ni++) {
            mx1 = fmaxf(mx1, fmaxf(s[ni][0], s[ni][1]));
            mx2 = fmaxf(mx2, fmaxf(s[ni][2], s[ni][3]));
        }
        mx1 = fmaxf(mx1, __shfl_xor_sync(0xffffffffu, mx1, 1));
        mx1 = fmaxf(mx1, __shfl_xor_sync(0xffffffffu, mx1, 2));
        mx2 = fmaxf(mx2, __shfl_xor_sync(0xffffffffu, mx2, 1));
        mx2 = fmaxf(mx2, __shfl_xor_sync(0xffffffffu, mx2, 2));

        float mn1 = fmaxf(m1, mx1), mn2 = fmaxf(m2, mx2);
        float sc1 = exp2f(m1 - mn1), sc2 = exp2f(m2 - mn2);
        m1 = mn1; m2 = mn2;

        float ps1 = 0.0f, ps2 = 0.0f;
        #pragma unroll
        for (int ni = 0; ni < 8; ni++) {
            s[ni][0] = exp2f(s[ni][0] - mn1);
            s[ni][1] = exp2f(s[ni][1] - mn1);
            s[ni][2] = exp2f(s[ni][2] - mn2);
            s[ni][3] = exp2f(s[ni][3] - mn2);
            ps1 += s[ni][0] + s[ni][1];
            ps2 += s[ni][2] + s[ni][3];
        }
        ps1 += __shfl_xor_sync(0xffffffffu, ps1, 1);
        ps1 += __shfl_xor_sync(0xffffffffu, ps1, 2);
        ps2 += __shfl_xor_sync(0xffffffffu, ps2, 1);
        ps2 += __shfl_xor_sync(0xffffffffu, ps2, 2);
        l1 = l1 * sc1 + ps1;
        l2 = l2 * sc2 + ps2;

        #pragma unroll
        for (int ni = 0; ni < 16; ni++) {
            o[ni][0] *= sc1; o[ni][1] *= sc1;
            o[ni][2] *= sc2; o[ni][3] *= sc2;
        }

        #pragma unroll
        for (int j = 0; j < 4; j++) {
            uint32_t ap[4];
            ap[0] = pack_h2(s[2 * j][0],     s[2 * j][1]);
            ap[1] = pack_h2(s[2 * j][2],     s[2 * j][3]);
            ap[2] = pack_h2(s[2 * j + 1][0], s[2 * j + 1][1]);
            ap[3] = pack_h2(s[2 * j + 1][2], s[2 * j + 1][3]);
            #pragma unroll
            for (int nj = 0; nj < 8; nj++) {
                uint32_t bv[4];
                ldsm_x4_t(bv, vBase + so + j * (16 * FSTR * 2) + nj * 32);
                mma16816(o[2 * nj],     ap, bv[0], bv[1]);
                mma16816(o[2 * nj + 1], ap, bv[2], bv[3]);
            }
        }
        __syncthreads();
    }

    // epilogue: warp w -> head h0 + (w>>1), seq rows qbase + (wrow&31) + {g, g+8}
    const float inv1 = 1.0f / l1;
    const float inv2 = 1.0f / l2;
    const int hOut = h0 + (warp >> 1);
    const int r1 = qbase + seqrel + g;
    #pragma unroll
    for (int ni = 0; ni < 16; ni++) {
        int c = ni * 8 + t4 * 2;
        *(uint32_t*)(Oh + (size_t)r1 * (NQH * HD) + hOut * HD + c) =
            pack_h2(o[ni][0] * inv1, o[ni][1] * inv1);
        *(uint32_t*)(Oh + (size_t)(r1 + 8) * (NQH * HD) + hOut * HD + c) =
            pack_h2(o[ni][2] * inv2, o[ni][3] * inv2);
    }
}

// ---------------- launch ----------------
extern "C" void kernel_launch(void* const* d_in, const int* in_sizes, int n_in,
                              void* d_out, int out_size) {
    const float* x    = (const float*)d_in[0];
    const int*   pos  = (const int*)  d_in[1];
    const float* cosT = (const float*)d_in[2];
    const float* sinT = (const float*)d_in[3];
    // d_in[4] = attn_mask — replicated exactly by causal skip
    const float* Wq   = (const float*)d_in[5];
    const float* Wk   = (const float*)d_in[6];
    const float* Wv   = (const float*)d_in[7];
    const float* Wo   = (const float*)d_in[8];
    const float* qw   = (const float*)d_in[9];
    const float* kw   = (const float*)d_in[10];
    float* out = (float*)d_out;

    __half *xh, *qh, *kh, *vh, *oh, *wqh, *wkh, *wvh, *woh;
    cudaGetSymbolAddress((void**)&xh, g_xh);
    cudaGetSymbolAddress((void**)&qh, g_qh);
    cudaGetSymbolAddress((void**)&kh, g_kh);
    cudaGetSymbolAddress((void**)&vh, g_vh);
    cudaGetSymbolAddress((void**)&oh, g_oh);
    cudaGetSymbolAddress((void**)&wqh, g_Wqh);
    cudaGetSymbolAddress((void**)&wkh, g_Wkh);
    cudaGetSymbolAddress((void**)&wvh, g_Wvh);
    cudaGetSymbolAddress((void**)&woh, g_Woh);

    cudaFuncSetAttribute(flash_h,   cudaFuncAttributeMaxDynamicSharedMemorySize, ATTN_SMEM);
    cudaFuncSetAttribute(hgemm_qkv, cudaFuncAttributeMaxDynamicSharedMemorySize, HG_SMEM);
    cudaFuncSetAttribute(hgemm_o,   cudaFuncAttributeMaxDynamicSharedMemorySize, HG_SMEM);

    // pre-pass: single fused fp32 -> fp16 conversion launch
    cvt_all<<<CVT_GRID, 256>>>(x, Wq, Wk, Wv, Wo, xh, wqh, wkh, wvh, woh);

    // fused QKV projection (all outputs fp16)
    hgemm_qkv<<<dim3(24, SEQ / 128), 256, HG_SMEM>>>(xh, wqh, wkh, wvh, qh, kh, vh);

    // RMSNorm + RoPE in-place on fp16 (q pre-scaled by 128^-0.5 * log2(e) for exp2 softmax)
    rmsnorm_rope_w<<<SEQ * NQH / 8, 256>>>(qh, qw, cosT, sinT, pos, NQH,
                                           0.08838834764831845f * 1.4426950408889634f);
    rmsnorm_rope_w<<<SEQ * NKV / 8, 256>>>(kh, kw, cosT, sinT, pos, NKV, 1.0f);

    // causal flash attention (GQA-shared K/V: 4 heads/CTA, heavy CTAs first)
    flash_h<<<dim3(SEQ / 32, NKV), 256, ATTN_SMEM>>>(qh, kh, vh, oh);

    // output projection
    hgemm_o<<<dim3(HID / 256, SEQ / 128), 256, HG_SMEM>>>(oh, woh, out);
}

// round 13
// speedup vs baseline: 9.5259x; 1.0281x over previous
#include <cuda_runtime.h>
#include <cuda_fp16.h>
#include <math.h>
#include <stdint.h>

#define SEQ 2048
#define HID 4096
#define NQH 32
#define NKV 8
#define HD  128

// ---------------- scratch (no cudaMalloc allowed) ----------------
__device__ __half g_xh[SEQ * HID];
__device__ __half g_qh[SEQ * NQH * HD];
__device__ __half g_kh[SEQ * NKV * HD];
__device__ __half g_vh[SEQ * NKV * HD];
__device__ __half g_oh[SEQ * NQH * HD];
__device__ __half g_Wqh[HID * (NQH * HD)];   // row-major [K, N] fp16
__device__ __half g_Wkh[HID * (NKV * HD)];
__device__ __half g_Wvh[HID * (NKV * HD)];
__device__ __half g_Woh[(NQH * HD) * HID];

// ---------------- asm helpers ----------------
__device__ __forceinline__ uint32_t smem_u32(const void* p) {
    uint32_t a;
    asm("{ .reg .u64 t; cvta.to.shared.u64 t, %1; cvt.u32.u64 %0, t; }" : "=r"(a) : "l"(p));
    return a;
}
#define CP_A16(dst, src) asm volatile("cp.async.cg.shared.global [%0], [%1], 16;" :: "r"(dst), "l"(src))
#define CP_COMMIT() asm volatile("cp.async.commit_group;")
#define CP_WAIT(n)  asm volatile("cp.async.wait_group %0;" :: "n"(n))

__device__ __forceinline__ void ldsm_x4(uint32_t* r, uint32_t a) {
    asm volatile("ldmatrix.sync.aligned.m8n8.x4.shared.b16 {%0,%1,%2,%3}, [%4];"
                 : "=r"(r[0]), "=r"(r[1]), "=r"(r[2]), "=r"(r[3]) : "r"(a));
}
__device__ __forceinline__ void ldsm_x4_t(uint32_t* r, uint32_t a) {
    asm volatile("ldmatrix.sync.aligned.m8n8.x4.trans.shared.b16 {%0,%1,%2,%3}, [%4];"
                 : "=r"(r[0]), "=r"(r[1]), "=r"(r[2]), "=r"(r[3]) : "r"(a));
}
__device__ __forceinline__ void mma16816(float (&d)[4], const uint32_t (&a)[4], uint32_t b0, uint32_t b1) {
    asm volatile(
        "mma.sync.aligned.m16n8k16.row.col.f32.f16.f16.f32 "
        "{%0,%1,%2,%3}, {%4,%5,%6,%7}, {%8,%9}, {%0,%1,%2,%3};"
        : "+f"(d[0]), "+f"(d[1]), "+f"(d[2]), "+f"(d[3])
        : "r"(a[0]), "r"(a[1]), "r"(a[2]), "r"(a[3]), "r"(b0), "r"(b1));
}
__device__ __forceinline__ uint32_t pack_h2(float lo, float hi) {
    __half2 h = __floats2half2_rn(lo, hi);
    return *(uint32_t*)&h;
}

// ---------------- pre-pass: ALL fp32 -> fp16 conversions in ONE launch ----------------
#define N_X  (SEQ * HID)
#define N_WQ (HID * NQH * HD)
#define N_WK (HID * NKV * HD)
#define N_WV (HID * NKV * HD)
#define N_WO (NQH * HD * HID)

__global__ __launch_bounds__(256)
void cvt_all(const float* __restrict__ x,  const float* __restrict__ wq,
             const float* __restrict__ wk, const float* __restrict__ wv,
             const float* __restrict__ wo,
             __half* __restrict__ xh,  __half* __restrict__ wqh,
             __half* __restrict__ wkh, __half* __restrict__ wvh,
             __half* __restrict__ woh) {
    int b = blockIdx.x;
    const float* in;
    __half* out;
    if (b < N_X / 4096)                          { in = x;  out = xh;  }
    else if ((b -= N_X / 4096)  < N_WQ / 4096)   { in = wq; out = wqh; }
    else if ((b -= N_WQ / 4096) < N_WK / 4096)   { in = wk; out = wkh; }
    else if ((b -= N_WK / 4096) < N_WV / 4096)   { in = wv; out = wvh; }
    else    { b -= N_WV / 4096;                    in = wo; out = woh; }

    const int base = b * 4096 + threadIdx.x * 4;
    float4 v0 = *(const float4*)(in + base);
    float4 v1 = *(const float4*)(in + base + 1024);
    float4 v2 = *(const float4*)(in + base + 2048);
    float4 v3 = *(const float4*)(in + base + 3072);
    *(uint2*)(out + base)        = make_uint2(pack_h2(v0.x, v0.y), pack_h2(v0.z, v0.w));
    *(uint2*)(out + base + 1024) = make_uint2(pack_h2(v1.x, v1.y), pack_h2(v1.z, v1.w));
    *(uint2*)(out + base + 2048) = make_uint2(pack_h2(v2.x, v2.y), pack_h2(v2.z, v2.w));
    *(uint2*)(out + base + 3072) = make_uint2(pack_h2(v3.x, v3.y), pack_h2(v3.z, v3.w));
}
#define CVT_GRID ((N_X + N_WQ + N_WK + N_WV + N_WO) / 4096)

// ---------------- fp16 GEMM (unchanged) ----------------
#define HA_STR 40
#define HB_STR 264
#define HA_ST  (128 * HA_STR * 2)
#define HB_ST  (32 * HB_STR * 2)
#define HG_SMEM (4 * (HA_ST + HB_ST))

template <typename OT>
__device__ __forceinline__
void hgemm_rm(const __half* __restrict__ A, const __half* __restrict__ W,
              OT* __restrict__ C, int Ncols, int K, int bm, int bn) {
    extern __shared__ __align__(16) __half hsm[];
    const uint32_t asb = smem_u32(hsm);
    const uint32_t bsb = asb + 4 * HA_ST;

    const int tid  = threadIdx.x;
    const int warp = tid >> 5;
    const int lane = tid & 31;
    const int g    = lane >> 2;
    const int t4   = lane & 3;
    const int wm   = warp >> 2;
    const int wn   = warp & 3;

    const __half* Asrc[2];
    uint32_t Adst[2];
    #pragma unroll
    for (int j = 0; j < 2; j++) {
        int ch = tid + j * 256;
        int row = ch >> 2, kc = (ch & 3) * 8;
        Asrc[j] = A + (size_t)(bm + row) * K + kc;
        Adst[j] = asb + (row * HA_STR + kc) * 2;
    }
    const __half* Bsrc[4];
    uint32_t Bdst[4];
    #pragma unroll
    for (int j = 0; j < 4; j++) {
        int ch = tid + j * 256;
        int row = ch >> 5, c8 = ch & 31;
        Bsrc[j] = W + (size_t)row * Ncols + bn + c8 * 8;
        Bdst[j] = bsb + (row * HB_STR + c8 * 8) * 2;
    }

    const uint32_t aBase = asb + ((wm * 64 + (lane & 7) + ((lane >> 3) & 1) * 8) * HA_STR
                                  + (lane >> 4) * 8) * 2;
    const uint32_t bBase = bsb + (((lane & 7) + ((lane >> 3) & 1) * 8) * HB_STR
                                  + wn * 64 + (lane >> 4) * 8) * 2;

    float acc[4][8][4];
    #pragma unroll
    for (int mi = 0; mi < 4; mi++)
        #pragma unroll
        for (int ni = 0; ni < 8; ni++)
            #pragma unroll
            for (int r = 0; r < 4; r++) acc[mi][ni][r] = 0.0f;

    const int iters = K >> 5;
    const size_t bAdv = (size_t)32 * Ncols;

    #pragma unroll
    for (int j = 0; j < 2; j++) CP_A16(Adst[j], Asrc[j]);
    #pragma unroll
    for (int j = 0; j < 4; j++) CP_A16(Bdst[j], Bsrc[j]);
    CP_COMMIT();
    {
        #pragma unroll
        for (int j = 0; j < 2; j++) CP_A16(Adst[j] + HA_ST, Asrc[j] + 32);
        #pragma unroll
        for (int j = 0; j < 4; j++) CP_A16(Bdst[j] + HB_ST, Bsrc[j] + bAdv);
        CP_COMMIT();
    }

    for (int i = 0; i < iters; i++) {
        if (i + 2 < iters) {
            const uint32_t ao = ((i + 2) & 3) * HA_ST;
            const uint32_t bo = ((i + 2) & 3) * HB_ST;
            const int ko = (i + 2) << 5;
            #pragma unroll
            for (int j = 0; j < 2; j++) CP_A16(Adst[j] + ao, Asrc[j] + ko);
            #pragma unroll
            for (int j = 0; j < 4; j++) CP_A16(Bdst[j] + bo, Bsrc[j] + (size_t)(i + 2) * bAdv);
            CP_COMMIT();
            CP_WAIT(2);
        } else if (i + 1 < iters) {
            CP_WAIT(1);
        } else {
            CP_WAIT(0);
        }
        __syncthreads();

        const uint32_t ao = (i & 3) * HA_ST;
        const uint32_t bo = (i & 3) * HB_ST;
        #pragma unroll
        for (int kb = 0; kb < 2; kb++) {
            uint32_t af[4][4];
            #pragma unroll
            for (int mi = 0; mi < 4; mi++)
                ldsm_x4(af[mi], aBase + ao + mi * (16 * HA_STR * 2) + kb * 32);
            uint32_t bf[4][4];
            #pragma unroll
            for (int nj = 0; nj < 4; nj++)
                ldsm_x4_t(bf[nj], bBase + bo + kb * (16 * HB_STR * 2) + nj * 32);
            #pragma unroll
            for (int mi = 0; mi < 4; mi++)
                #pragma unroll
                for (int nj = 0; nj < 4; nj++) {
                    mma16816(acc[mi][2 * nj],     af[mi], bf[nj][0], bf[nj][1]);
                    mma16816(acc[mi][2 * nj + 1], af[mi], bf[nj][2], bf[nj][3]);
                }
        }
    }

    #pragma unroll
    for (int mi = 0; mi < 4; mi++) {
        #pragma unroll
        for (int ni = 0; ni < 8; ni++) {
            int r1 = bm + wm * 64 + mi * 16 + g;
            int c  = bn + wn * 64 + ni * 8 + t4 * 2;
            if (sizeof(OT) == 2) {
                __half* Ch = (__half*)C;
                *(uint32_t*)(Ch + (size_t)r1 * Ncols + c)       = pack_h2(acc[mi][ni][0], acc[mi][ni][1]);
                *(uint32_t*)(Ch + (size_t)(r1 + 8) * Ncols + c) = pack_h2(acc[mi][ni][2], acc[mi][ni][3]);
            } else {
                float* Cf = (float*)C;
                *(float2*)(Cf + (size_t)r1 * Ncols + c)       = make_float2(acc[mi][ni][0], acc[mi][ni][1]);
                *(float2*)(Cf + (size_t)(r1 + 8) * Ncols + c) = make_float2(acc[mi][ni][2], acc[mi][ni][3]);
            }
        }
    }
}

__global__ __launch_bounds__(256, 1)
void hgemm_qkv(const __half* __restrict__ A,
               const __half* __restrict__ Wq, const __half* __restrict__ Wk,
               const __half* __restrict__ Wv,
               __half* __restrict__ Cq, __half* __restrict__ Ck, __half* __restrict__ Cv) {
    const int bx = blockIdx.x;
    const int bm = blockIdx.y * 128;
    if (bx < 16)      hgemm_rm<__half>(A, Wq, Cq, NQH * HD, HID, bm, bx * 256);
    else if (bx < 20) hgemm_rm<__half>(A, Wk, Ck, NKV * HD, HID, bm, (bx - 16) * 256);
    else              hgemm_rm<__half>(A, Wv, Cv, NKV * HD, HID, bm, (bx - 20) * 256);
}

__global__ __launch_bounds__(256, 1)
void hgemm_o(const __half* __restrict__ A, const __half* __restrict__ W,
             float* __restrict__ C) {
    hgemm_rm<float>(A, W, C, HID, NQH * HD, blockIdx.y * 128, blockIdx.x * 256);
}

// ---------------- RMSNorm + RoPE (q and k in ONE launch), in-place fp16 ----------------
// grid.x covers q rows (SEQ*NQH) then k rows (SEQ*NKV), 8 rows/CTA.
#define QROWS (SEQ * NQH)
#define KROWS (SEQ * NKV)

__global__ __launch_bounds__(256)
void rmsnorm_rope_qk(__half* __restrict__ qbuf, __half* __restrict__ kbuf,
                     const float* __restrict__ qw, const float* __restrict__ kw,
                     const float* __restrict__ cosT, const float* __restrict__ sinT,
                     const int* __restrict__ pos_ids, float qscale) {
    const int lane = threadIdx.x & 31;
    int row = blockIdx.x * 8 + (threadIdx.x >> 5);

    __half* buf;
    const float* w;
    float oscale;
    int s;
    if (row < QROWS) {
        buf = qbuf; w = qw; oscale = qscale; s = row / NQH;
    } else {
        row -= QROWS;
        buf = kbuf; w = kw; oscale = 1.0f; s = row / NKV;
    }
    const int c0 = lane * 4;

    __half* rp = buf + (size_t)row * HD;
    uint2 raw = *(const uint2*)(rp + c0);
    __half2 h01 = *(__half2*)&raw.x;
    __half2 h23 = *(__half2*)&raw.y;
    float4 v = make_float4(__low2float(h01), __high2float(h01),
                           __low2float(h23), __high2float(h23));
    float4 wv = *(const float4*)(w + c0);

    float ss = v.x * v.x + v.y * v.y + v.z * v.z + v.w * v.w;
    #pragma unroll
    for (int off = 16; off > 0; off >>= 1)
        ss += __shfl_xor_sync(0xffffffffu, ss, off);
    const float inv = rsqrtf(ss * (1.0f / HD) + 1e-6f);

    float4 xn;
    xn.x = v.x * inv * wv.x; xn.y = v.y * inv * wv.y;
    xn.z = v.z * inv * wv.z; xn.w = v.w * inv * wv.w;

    float px = __shfl_xor_sync(0xffffffffu, xn.x, 16);
    float py = __shfl_xor_sync(0xffffffffu, xn.y, 16);
    float pz = __shfl_xor_sync(0xffffffffu, xn.z, 16);
    float pw = __shfl_xor_sync(0xffffffffu, xn.w, 16);
    const float sgn = (lane < 16) ? -1.0f : 1.0f;

    const int p = pos_ids[s];
    float4 c  = *(const float4*)(cosT + (size_t)p * HD + c0);
    float4 sn = *(const float4*)(sinT + (size_t)p * HD + c0);

    float ox = (xn.x * c.x + sgn * px * sn.x) * oscale;
    float oy = (xn.y * c.y + sgn * py * sn.y) * oscale;
    float oz = (xn.z * c.z + sgn * pz * sn.z) * oscale;
    float ow = (xn.w * c.w + sgn * pw * sn.w) * oscale;

    *(uint2*)(rp + c0) = make_uint2(pack_h2(ox, oy), pack_h2(oz, ow));
}

// ---------------- fp16 flash attention: GQA-shared K/V, exp2 softmax ----------------
// CTA = 32 q-rows x 4 heads (one kv head), M=128. grid (SEQ/32, NKV).
// 4-stage KV ring, issue-ahead 2, ONE barrier/iter; Q fragments hoisted (loaded at kb==0).
#define FSTR 136
#define FQ_HALVES (128 * FSTR)
#define FK_HALVES (64 * FSTR)
#define ATTN_SMEM ((FQ_HALVES + 8 * FK_HALVES) * 2)   // Q + 4 stages x (K+V)

__global__ __launch_bounds__(256, 1)
void flash_h(const __half* __restrict__ Qh, const __half* __restrict__ Kh,
             const __half* __restrict__ Vh, __half* __restrict__ Oh) {
    extern __shared__ __align__(16) __half fsm[];
    __half* Qs = fsm;
    __half* Ks = fsm + FQ_HALVES;              // 4 stages
    __half* Vs = Ks + 4 * FK_HALVES;           // 4 stages

    const int tid  = threadIdx.x;
    const int warp = tid >> 5;
    const int lane = tid & 31;
    const int g    = lane >> 2;
    const int t4   = lane & 3;
    const int wrow = warp * 16;

    const int qb    = gridDim.x - 1 - blockIdx.x;   // heavy blocks first
    const int kvh   = blockIdx.y;
    const int h0    = kvh * 4;
    const int qbase = qb * 32;

    const uint32_t qsb = smem_u32(Qs);
    const uint32_t ksb = smem_u32(Ks);
    const uint32_t vsb = smem_u32(Vs);
    const uint32_t KSTB = FK_HALVES * 2;

    const int nkb = (qbase >> 6) + 1;

    // prologue: Q + KV0 (group 0); KV1 (group 1, if present)
    {
        #pragma unroll
        for (int j = 0; j < 8; j++) {
            int c = tid + j * 256;
            int row = c >> 4, c8 = c & 15;
            CP_A16(qsb + (row * FSTR + c8 * 8) * 2,
                   Qh + (size_t)(qbase + (row & 31)) * (NQH * HD)
                      + (h0 + (row >> 5)) * HD + c8 * 8);
        }
        #pragma unroll
        for (int j = 0; j < 4; j++) {
            int c = tid + j * 256;
            int row = c >> 4, c8 = c & 15;
            size_t gi = (size_t)row * (NKV * HD) + kvh * HD + c8 * 8;
            CP_A16(ksb + (row * FSTR + c8 * 8) * 2, Kh + gi);
            CP_A16(vsb + (row * FSTR + c8 * 8) * 2, Vh + gi);
        }
        CP_COMMIT();
        if (nkb > 1) {
            #pragma unroll
            for (int j = 0; j < 4; j++) {
                int c = tid + j * 256;
                int row = c >> 4, c8 = c & 15;
                size_t gi = (size_t)(64 + row) * (NKV * HD) + kvh * HD + c8 * 8;
                CP_A16(ksb + KSTB + (row * FSTR + c8 * 8) * 2, Kh + gi);
                CP_A16(vsb + KSTB + (row * FSTR + c8 * 8) * 2, Vh + gi);
            }
            CP_COMMIT();
        }
    }

    float o[16][4];
    #pragma unroll
    for (int ni = 0; ni < 16; ni++)
        #pragma unroll
        for (int r = 0; r < 4; r++) o[ni][r] = 0.0f;
    float m1 = -INFINITY, m2 = -INFINITY, l1 = 0.0f, l2 = 0.0f;

    const uint32_t qBase = qsb + ((wrow + (lane & 7) + ((lane >> 3) & 1) * 8) * FSTR
                                   + (lane >> 4) * 8) * 2;
    const uint32_t kBase = ksb + (((lane & 7) + (lane >> 4) * 8) * FSTR
                                   + ((lane >> 3) & 1) * 8) * 2;
    const uint32_t vBase = vsb + (((lane & 7) + ((lane >> 3) & 1) * 8) * FSTR
                                   + (lane >> 4) * 8) * 2;

    uint32_t aq[8][4];                               // hoisted Q fragments
    const int seqrel = wrow & 31;

    for (int kb = 0; kb < nkb; kb++) {
        if (kb + 2 < nkb) {
            const int st = (kb + 2) & 3;
            const int kbase2 = (kb + 2) * 64;
            #pragma unroll
            for (int j = 0; j < 4; j++) {
                int c = tid + j * 256;
                int row = c >> 4, c8 = c & 15;
                size_t gi = (size_t)(kbase2 + row) * (NKV * HD) + kvh * HD + c8 * 8;
                CP_A16(ksb + st * KSTB + (row * FSTR + c8 * 8) * 2, Kh + gi);
                CP_A16(vsb + st * KSTB + (row * FSTR + c8 * 8) * 2, Vh + gi);
            }
            CP_COMMIT();
            CP_WAIT(2);
        } else if (kb + 1 < nkb) {
            CP_WAIT(1);
        } else {
            CP_WAIT(0);
        }
        __syncthreads();   // single barrier per iter (4-stage ring)

        if (kb == 0) {
            #pragma unroll
            for (int k8 = 0; k8 < 8; k8++)
                ldsm_x4(aq[k8], qBase + k8 * 32);
        }

        const uint32_t so = (kb & 3) * KSTB;
        const int kbase = kb * 64;

        float s[8][4];
        #pragma unroll
        for (int ni = 0; ni < 8; ni++)
            #pragma unroll
            for (int r = 0; r < 4; r++) s[ni][r] = 0.0f;

        #pragma unroll
        for (int k8 = 0; k8 < 8; k8++) {
            #pragma unroll
            for (int nj = 0; nj < 4; nj++) {
                uint32_t bk[4];
                ldsm_x4(bk, kBase + so + nj * (16 * FSTR * 2) + k8 * 32);
                mma16816(s[2 * nj],     aq[k8], bk[0], bk[1]);
                mma16816(s[2 * nj + 1], aq[k8], bk[2], bk[3]);
            }
        }

        if (kbase + 63 > qbase + seqrel) {
            const int r1 = qbase + seqrel + g;
            const int r2 = r1 + 8;
            #pragma unroll
            for (int ni = 0; ni < 8; ni++) {
                int c0 = kbase + ni * 8 + t4 * 2;
                if (c0     > r1) s[ni][0] = -1e30f;
                if (c0 + 1 > r1) s[ni][1] = -1e30f;
                if (c0     > r2) s[ni][2] = -1e30f;
                if (c0 + 1 > r2) s[ni][3] = -1e30f;
            }
        }

        float mx1 = -INFINITY, mx2 = -INFINITY;
        #pragma unroll
        for (int ni = 0; ni < 8; ni++) {
            mx1 = fmaxf(mx1, fmaxf(s[ni][0], s[ni][1]));
            mx2 = fmaxf(mx2, fmaxf(s[ni][2], s[ni][3]));
        }
        mx1 = fmaxf(mx1, __shfl_xor_sync(0xffffffffu, mx1, 1));
        mx1 = fmaxf(mx1, __shfl_xor_sync(0xffffffffu, mx1, 2));
        mx2 = fmaxf(mx2, __shfl_xor_sync(0xffffffffu, mx2, 1));
        mx2 = fmaxf(mx2, __shfl_xor_sync(0xffffffffu, mx2, 2));

        float mn1 = fmaxf(m1, mx1), mn2 = fmaxf(m2, mx2);
        float sc1 = exp2f(m1 - mn1), sc2 = exp2f(m2 - mn2);
        m1 = mn1; m2 = mn2;

        float ps1 = 0.0f, ps2 = 0.0f;
        #pragma unroll
        for (int ni = 0; ni < 8; ni++) {
            s[ni][0] = exp2f(s[ni][0] - mn1);
            s[ni][1] = exp2f(s[ni][1] - mn1);
            s[ni][2] = exp2f(s[ni][2] - mn2);
            s[ni][3] = exp2f(s[ni][3] - mn2);
            ps1 += s[ni][0] + s[ni][1];
            ps2 += s[ni][2] + s[ni][3];
        }
        ps1 += __shfl_xor_sync(0xffffffffu, ps1, 1);
        ps1 += __shfl_xor_sync(0xffffffffu, ps1, 2);
        ps2 += __shfl_xor_sync(0xffffffffu, ps2, 1);
        ps2 += __shfl_xor_sync(0xffffffffu, ps2, 2);
        l1 = l1 * sc1 + ps1;
        l2 = l2 * sc2 + ps2;

        #pragma unroll
        for (int ni = 0; ni < 16; ni++) {
            o[ni][0] *= sc1; o[ni][1] *= sc1;
            o[ni][2] *= sc2; o[ni][3] *= sc2;
        }

        #pragma unroll
        for (int j = 0; j < 4; j++) {
            uint32_t ap[4];
            ap[0] = pack_h2(s[2 * j][0],     s[2 * j][1]);
            ap[1] = pack_h2(s[2 * j][2],     s[2 * j][3]);
            ap[2] = pack_h2(s[2 * j + 1][0], s[2 * j + 1][1]);
            ap[3] = pack_h2(s[2 * j + 1][2], s[2 * j + 1][3]);
            #pragma unroll
            for (int nj = 0; nj < 8; nj++) {
                uint32_t bv[4];
                ldsm_x4_t(bv, vBase + so + j * (16 * FSTR * 2) + nj * 32);
                mma16816(o[2 * nj],     ap, bv[0], bv[1]);
                mma16816(o[2 * nj + 1], ap, bv[2], bv[3]);
            }
        }
    }

    const float inv1 = 1.0f / l1;
    const float inv2 = 1.0f / l2;
    const int hOut = h0 + (warp >> 1);
    const int r1 = qbase + seqrel + g;
    #pragma unroll
    for (int ni = 0; ni < 16; ni++) {
        int c = ni * 8 + t4 * 2;
        *(uint32_t*)(Oh + (size_t)r1 * (NQH * HD) + hOut * HD + c) =
            pack_h2(o[ni][0] * inv1, o[ni][1] * inv1);
        *(uint32_t*)(Oh + (size_t)(r1 + 8) * (NQH * HD) + hOut * HD + c) =
            pack_h2(o[ni][2] * inv2, o[ni][3] * inv2);
    }
}

// ---------------- launch ----------------
extern "C" void kernel_launch(void* const* d_in, const int* in_sizes, int n_in,
                              void* d_out, int out_size) {
    const float* x    = (const float*)d_in[0];
    const int*   pos  = (const int*)  d_in[1];
    const float* cosT = (const float*)d_in[2];
    const float* sinT = (const float*)d_in[3];
    // d_in[4] = attn_mask — replicated exactly by causal skip
    const float* Wq   = (const float*)d_in[5];
    const float* Wk   = (const float*)d_in[6];
    const float* Wv   = (const float*)d_in[7];
    const float* Wo   = (const float*)d_in[8];
    const float* qw   = (const float*)d_in[9];
    const float* kw   = (const float*)d_in[10];
    float* out = (float*)d_out;

    __half *xh, *qh, *kh, *vh, *oh, *wqh, *wkh, *wvh, *woh;
    cudaGetSymbolAddress((void**)&xh, g_xh);
    cudaGetSymbolAddress((void**)&qh, g_qh);
    cudaGetSymbolAddress((void**)&kh, g_kh);
    cudaGetSymbolAddress((void**)&vh, g_vh);
    cudaGetSymbolAddress((void**)&oh, g_oh);
    cudaGetSymbolAddress((void**)&wqh, g_Wqh);
    cudaGetSymbolAddress((void**)&wkh, g_Wkh);
    cudaGetSymbolAddress((void**)&wvh, g_Wvh);
    cudaGetSymbolAddress((void**)&woh, g_Woh);

    cudaFuncSetAttribute(flash_h,   cudaFuncAttributeMaxDynamicSharedMemorySize, ATTN_SMEM);
    cudaFuncSetAttribute(hgemm_qkv, cudaFuncAttributeMaxDynamicSharedMemorySize, HG_SMEM);
    cudaFuncSetAttribute(hgemm_o,   cudaFuncAttributeMaxDynamicSharedMemorySize, HG_SMEM);

    // pre-pass: single fused fp32 -> fp16 conversion launch
    cvt_all<<<CVT_GRID, 256>>>(x, Wq, Wk, Wv, Wo, xh, wqh, wkh, wvh, woh);

    // fused QKV projection (all outputs fp16)
    hgemm_qkv<<<dim3(24, SEQ / 128), 256, HG_SMEM>>>(xh, wqh, wkh, wvh, qh, kh, vh);

    // RMSNorm + RoPE in-place on fp16 (q and k in one launch; q pre-scaled for exp2 softmax)
    rmsnorm_rope_qk<<<(QROWS + KROWS) / 8, 256>>>(qh, kh, qw, kw, cosT, sinT, pos,
                                                  0.08838834764831845f * 1.4426950408889634f);

    // causal flash attention (GQA-shared K/V, 4-stage ring, heavy CTAs first)
    flash_h<<<dim3(SEQ / 32, NKV), 256, ATTN_SMEM>>>(qh, kh, vh, oh);

    // output projection
    hgemm_o<<<dim3(HID / 256, SEQ / 128), 256, HG_SMEM>>>(oh, woh, out);
}